// round 8
// baseline (speedup 1.0000x reference)
#include <cuda_runtime.h>
#include <cuda_fp16.h>
#include <math.h>
#include <stdint.h>

// Problem dims
#define Tn 2048   // tokens = B*S
#define Hn 2048   // hidden
#define Fn 7168   // ffn
#define En 8      // experts
#define Rn 32     // lora rank
#define Kn 2      // top-k

// HMMA GEMM tiling: 128x256, 512 threads, 3 stages, B-dedup (A hi+lo share B)
#define GBM 128
#define GBN 256
#define KBE 64                       // fp16 K elems per stage = 128B rows (SW128)
#define STAGES 3
#define AH_TILE_B (GBM * 128)        // 16384 (A hi)
#define B_OFF     (2 * AH_TILE_B)    // 32768 (A lo at 16384, B at 32768)
#define STAGE_B   (B_OFF + GBN * 128)          // 65536
#define SMEM_TOTAL (STAGES * STAGE_B)          // 196608

#define SWZ(o) ((o) ^ (((o) >> 3) & 0x70))

// ---------------- scratch (device globals) ---------------------------------
__device__ __align__(256) float g_base1[Tn * Fn];
__device__ __align__(256) float g_base3[Tn * Fn];
__device__ __align__(256) float g_x2k0[Tn * Fn];
__device__ __align__(256) float g_x2k1[Tn * Fn];
__device__ __align__(256) float g_l2k0[Tn * Hn];
__device__ __align__(256) float g_l2k1[Tn * Hn];
__device__ __align__(256) __half g_xs [Tn * 2 * Hn];   // x split  [hi | lo] K-concat
__device__ __align__(256) __half g_w1s[Fn * Hn];       // W1 fp16 (single copy)
__device__ __align__(256) __half g_w3s[Fn * Hn];       // W3 fp16
__device__ __align__(256) __half g_w2s[Hn * Fn];       // W2 fp16
__device__ __align__(256) __half g_x2s[Tn * 2 * Fn];   // weighted x2 [hi | lo]
__device__ int   g_sel[Tn * Kn];
__device__ float g_rw [Tn * Kn];
__device__ float g_a1 [Tn * Kn * Rn];
__device__ float g_a3 [Tn * Kn * Rn];
__device__ float g_a2 [Tn * Kn * Rn];
// expert grouping
__device__ int g_off [En + 1];
__device__ int g_cur [En];
__device__ int g_list[Tn * Kn];

// ---------------- helpers ---------------------------------------------------
__device__ __forceinline__ uint32_t smem_u32(const void* p) {
    uint32_t a;
    asm("{ .reg .u64 t; cvta.to.shared.u64 t, %1; cvt.u32.u64 %0, t; }"
        : "=r"(a) : "l"(p));
    return a;
}

__device__ __forceinline__ float warp_sum(float v) {
#pragma unroll
    for (int o = 16; o; o >>= 1) v += __shfl_xor_sync(0xffffffffu, v, o);
    return v;
}

__device__ __forceinline__ bool find_chunk(int b, int CH, int& e, int& start,
                                           int& nent) {
    int acc = 0;
    for (int ee = 0; ee < En; ee++) {
        int o0 = g_off[ee], o1 = g_off[ee + 1];
        int cnt = o1 - o0;
        int nch = (cnt + CH - 1) / CH;
        if (b < acc + nch) {
            e = ee;
            start = o0 + (b - acc) * CH;
            nent = min(CH, o1 - start);
            return true;
        }
        acc += nch;
    }
    return false;
}

#define LDSM4(r0, r1, r2, r3, addr) \
    asm volatile("ldmatrix.sync.aligned.m8n8.x4.shared.b16 {%0,%1,%2,%3}, [%4];" \
                 : "=r"(r0), "=r"(r1), "=r"(r2), "=r"(r3) : "r"(addr))

#define MMA16816(c, a, b0, b1) \
    asm volatile("mma.sync.aligned.m16n8k16.row.col.f32.f16.f16.f32 " \
                 "{%0,%1,%2,%3}, {%4,%5,%6,%7}, {%8,%9}, {%0,%1,%2,%3};" \
                 : "+f"((c)[0]), "+f"((c)[1]), "+f"((c)[2]), "+f"((c)[3]) \
                 : "r"((a)[0]), "r"((a)[1]), "r"((a)[2]), "r"((a)[3]), \
                   "r"(b0), "r"(b1))

// ---------------- fp16 split kernels (row per block) -----------------------
// mode 0 (A side): dst row = [hi(cols) | lo(cols)]; mode 1 (B side): single fp16 copy
__global__ __launch_bounds__(256) void split_kernel(
    const float* __restrict__ src, __half* __restrict__ dst,
    int cols, int bmode)
{
    int r = blockIdx.x;
    const float* s = src + (size_t)r * cols;
    __half* d = dst + (size_t)r * (bmode ? cols : 2 * cols);
    for (int c = threadIdx.x * 4; c < cols; c += 256 * 4) {
        float4 v = *(const float4*)(s + c);
        __half h0 = __float2half_rn(v.x);
        __half h1 = __float2half_rn(v.y);
        __half h2 = __float2half_rn(v.z);
        __half h3 = __float2half_rn(v.w);
        *(__half2*)(d + c)     = __halves2half2(h0, h1);
        *(__half2*)(d + c + 2) = __halves2half2(h2, h3);
        if (!bmode) {
            __half l0 = __float2half_rn(v.x - __half2float(h0));
            __half l1 = __float2half_rn(v.y - __half2float(h1));
            __half l2 = __float2half_rn(v.z - __half2float(h2));
            __half l3 = __float2half_rn(v.w - __half2float(h3));
            *(__half2*)(d + cols + c)     = __halves2half2(l0, l1);
            *(__half2*)(d + cols + c + 2) = __halves2half2(l2, l3);
        }
    }
}

// ---------------- GEMM stage loader (cp.async, SW128, B-dedup) -------------
// A row length = 2*Kp  (hi at col 0, lo at col Kp); B row length = Kp
__device__ __forceinline__ void load_stage(
    uint32_t sb, const __half* Ab, const __half* Bb,
    int Kp, int it, int stage, int tid)
{
    uint32_t st = sb + stage * STAGE_B;
    int k0 = it * KBE;
#pragma unroll
    for (int i = 0; i < 8; i++) {
        int c = tid + i * 512;              // 0..4095
        uint32_t soff;
        const __half* g;
        if (c < 1024) {                     // A hi: 128 rows x 8 chunks
            int row = c >> 3, j = c & 7;
            soff = st + SWZ(row * 128 + j * 16);
            g = Ab + (size_t)row * (2 * Kp) + k0 + j * 8;
        } else if (c < 2048) {              // A lo
            int cc = c - 1024;
            int row = cc >> 3, j = cc & 7;
            soff = st + AH_TILE_B + SWZ(row * 128 + j * 16);
            g = Ab + (size_t)row * (2 * Kp) + Kp + k0 + j * 8;
        } else {                            // B: 256 rows x 8 chunks
            int cc = c - 2048;
            int row = cc >> 3, j = cc & 7;
            soff = st + B_OFF + SWZ(row * 128 + j * 16);
            g = Bb + (size_t)row * Kp + k0 + j * 8;
        }
        asm volatile("cp.async.cg.shared.global [%0], [%1], 16;"
                     :: "r"(soff), "l"(g) : "memory");
    }
}

// ---------------- HMMA fp16 GEMM: C = (Ahi+Alo)[M,Kp] @ B[N,Kp]^T ----------
__global__ __launch_bounds__(512, 1) void gemm_f16(
    const __half* __restrict__ A, const __half* __restrict__ B,
    float* __restrict__ C, int N, int Kp)
{
    extern __shared__ __align__(1024) char smem[];
    uint32_t sb = smem_u32(smem);
    int tid = threadIdx.x, wid = tid >> 5, lane = tid & 31;
    int wm = wid & 3, wn = wid >> 2;       // 4 warps in M, 4 in N
    int bx = blockIdx.x, by = blockIdx.y;
    const int niter = Kp / KBE;

    const __half* Ab = A + (size_t)(by * GBM) * (2 * Kp);
    const __half* Bb = B + (size_t)(bx * GBN) * Kp;

#pragma unroll
    for (int it = 0; it < STAGES - 1; it++) {
        load_stage(sb, Ab, Bb, Kp, it, it, tid);
        asm volatile("cp.async.commit_group;" ::: "memory");
    }

    float acc[2][8][4];
#pragma unroll
    for (int mi = 0; mi < 2; mi++)
#pragma unroll
        for (int nj = 0; nj < 8; nj++)
#pragma unroll
            for (int q = 0; q < 4; q++) acc[mi][nj][q] = 0.f;

    int gq = lane >> 3, rr = lane & 7;
    int kc = gq >> 1;
    uint32_t aRow[2]; int aXor[2];
#pragma unroll
    for (int mi = 0; mi < 2; mi++) {
        int m = wm * 32 + mi * 16 + (gq & 1) * 8 + rr;
        aRow[mi] = (uint32_t)(m * 128);
        aXor[mi] = m & 7;
    }
    uint32_t bRow[4]; int bXor[4];
#pragma unroll
    for (int ni = 0; ni < 4; ni++) {
        int n = wn * 64 + ni * 16 + (gq & 1) * 8 + rr;
        bRow[ni] = (uint32_t)(n * 128);
        bXor[ni] = n & 7;
    }

    int s = 0;
    for (int it = 0; it < niter; it++) {
        asm volatile("cp.async.wait_group %0;" :: "n"(STAGES - 2) : "memory");
        __syncthreads();
        int jt = it + STAGES - 1;
        if (jt < niter) {
            int sj = jt - (jt / STAGES) * STAGES;
            load_stage(sb, Ab, Bb, Kp, jt, sj, tid);
        }
        asm volatile("cp.async.commit_group;" ::: "memory");

        uint32_t stb = sb + s * STAGE_B;
        s++; if (s == STAGES) s = 0;
#pragma unroll
        for (int ph = 0; ph < 2; ph++) {       // hi then lo, same B tile
            uint32_t abase = stb + ph * AH_TILE_B;
            uint32_t bbase = stb + B_OFF;
#pragma unroll
            for (int ks = 0; ks < 4; ks++) {
                uint32_t a[2][4];
#pragma unroll
                for (int mi = 0; mi < 2; mi++) {
                    uint32_t ad = abase + aRow[mi]
                                + (uint32_t)((((ks << 1) + kc) ^ aXor[mi]) << 4);
                    LDSM4(a[mi][0], a[mi][1], a[mi][2], a[mi][3], ad);
                }
                uint32_t b[4][4];
#pragma unroll
                for (int ni = 0; ni < 4; ni++) {
                    uint32_t bd = bbase + bRow[ni]
                                + (uint32_t)((((ks << 1) + kc) ^ bXor[ni]) << 4);
                    LDSM4(b[ni][0], b[ni][1], b[ni][2], b[ni][3], bd);
                }
#pragma unroll
                for (int mi = 0; mi < 2; mi++)
#pragma unroll
                    for (int ni = 0; ni < 4; ni++) {
                        MMA16816(acc[mi][ni * 2],     a[mi], b[ni][0], b[ni][2]);
                        MMA16816(acc[mi][ni * 2 + 1], a[mi], b[ni][1], b[ni][3]);
                    }
            }
        }
        __syncthreads();
    }

    int gid = lane >> 2, tig = lane & 3;
#pragma unroll
    for (int mi = 0; mi < 2; mi++) {
        int row = by * GBM + wm * 32 + mi * 16 + gid;
#pragma unroll
        for (int nj = 0; nj < 8; nj++) {
            float* p = C + (size_t)row * N + bx * GBN + wn * 64 + nj * 8 + tig * 2;
            *(float2*)p = make_float2(acc[mi][nj][0], acc[mi][nj][1]);
            *(float2*)(p + (size_t)8 * N) = make_float2(acc[mi][nj][2], acc[mi][nj][3]);
        }
    }
}

// ---------------- K1: gate -------------------------------------------------
__global__ __launch_bounds__(256) void gate_kernel(
    const float* __restrict__ x, const float* __restrict__ Wg)
{
    int t = blockIdx.x;
    int tid = threadIdx.x;
    int w = tid >> 5, lane = tid & 31;
    const float* xr = x + (size_t)t * Hn;
    const float* wr = Wg + (size_t)w * Hn;
    float s = 0.f;
    for (int h = lane * 4; h < Hn; h += 32 * 4) {
        float4 xv = *(const float4*)(xr + h);
        float4 wv = *(const float4*)(wr + h);
        s += xv.x * wv.x + xv.y * wv.y + xv.z * wv.z + xv.w * wv.w;
    }
    s = warp_sum(s);
    __shared__ float logits[En];
    if (lane == 0) logits[w] = s;
    __syncthreads();
    if (tid == 0) {
        int i0 = 0; float l0 = logits[0];
#pragma unroll
        for (int e = 1; e < En; e++) if (logits[e] > l0) { l0 = logits[e]; i0 = e; }
        int i1 = -1; float l1 = -3.0e38f;
#pragma unroll
        for (int e = 0; e < En; e++) if (e != i0 && logits[e] > l1) { l1 = logits[e]; i1 = e; }
        float r0 = 1.f / (1.f + expf(l1 - l0));
        g_sel[t * 2 + 0] = i0;
        g_sel[t * 2 + 1] = i1;
        g_rw [t * 2 + 0] = r0;
        g_rw [t * 2 + 1] = 1.f - r0;
    }
}

// ---------------- expert grouping ------------------------------------------
__global__ __launch_bounds__(256) void hist_kernel()
{
    __shared__ int hc[En];
    int tid = threadIdx.x;
    if (tid < En) hc[tid] = 0;
    __syncthreads();
    for (int i = tid; i < Tn * Kn; i += 256)
        atomicAdd(&hc[g_sel[i]], 1);
    __syncthreads();
    if (tid == 0) {
        int off = 0;
        for (int e = 0; e < En; e++) {
            g_off[e] = off;
            g_cur[e] = off;
            off += hc[e];
        }
        g_off[En] = off;
    }
}

__global__ __launch_bounds__(256) void scatter_kernel()
{
    int i = blockIdx.x * 256 + threadIdx.x;
    if (i < Tn * Kn) {
        int e = g_sel[i];
        int pos = atomicAdd(&g_cur[e], 1);
        g_list[pos] = i;
    }
}

// -------- grouped a1/a3 (CH=8 entries; float4 inner loop) ------------------
#define CHA 8
#define PAD 132
__global__ __launch_bounds__(256) void a13_grouped(
    const float* __restrict__ x, const float* __restrict__ A1,
    const float* __restrict__ A3)
{
    int e, start, nent;
    if (!find_chunk(blockIdx.x, CHA, e, start, nent)) return;
    __shared__ float xs[CHA][PAD];
    __shared__ float as[64][PAD];
    __shared__ int ids[CHA];
    int tid = threadIdx.x;
    if (tid < CHA)
        ids[tid] = (tid < nent) ? g_list[start + tid] : g_list[start];
    __syncthreads();

    int entry = tid >> 5, rg = tid & 31;
    float acc0 = 0.f, acc1 = 0.f;
    int myid = ids[entry];

    for (int h0 = 0; h0 < Hn; h0 += 128) {
#pragma unroll
        for (int i = 0; i < 4; i++) {
            int q = tid + i * 256;
            int row = q >> 7, col = q & 127;
            xs[row][col] = x[(size_t)(ids[row] >> 1) * Hn + h0 + col];
        }
#pragma unroll
        for (int i = 0; i < 32; i++) {
            int q = tid + i * 256;
            int row = q >> 7, col = q & 127;
            const float* src = (row < 32)
                ? A1 + ((size_t)(e * Rn + row) * Hn + h0 + col)
                : A3 + ((size_t)(e * Rn + row - 32) * Hn + h0 + col);
            as[row][col] = *src;
        }
        __syncthreads();
#pragma unroll
        for (int h = 0; h < 128; h += 4) {
            float4 xv = *(const float4*)&xs[entry][h];
            float4 a0 = *(const float4*)&as[rg][h];
            float4 a1 = *(const float4*)&as[rg + 32][h];
            acc0 += xv.x * a0.x + xv.y * a0.y + xv.z * a0.z + xv.w * a0.w;
            acc1 += xv.x * a1.x + xv.y * a1.y + xv.z * a1.z + xv.w * a1.w;
        }
        __syncthreads();
    }
    if (entry < nent) {
        g_a1[(size_t)myid * Rn + rg] = acc0;
        g_a3[(size_t)myid * Rn + rg] = acc1;
    }
}

// -------- grouped fuse (CH=32) ---------------------------------------------
#define CHF 32
__global__ __launch_bounds__(256) void fuse_grouped(
    const float* __restrict__ B1, const float* __restrict__ B3)
{
    int e, start, nent;
    if (!find_chunk(blockIdx.x, CHF, e, start, nent)) return;
    __shared__ float a1s[CHF][Rn];
    __shared__ float a3s[CHF][Rn];
    __shared__ int ids[CHF];
    int tid = threadIdx.x;
    if (tid < CHF)
        ids[tid] = (tid < nent) ? g_list[start + tid] : g_list[start];
    __syncthreads();
#pragma unroll
    for (int i = 0; i < 4; i++) {
        int q = tid + i * 256;
        int en = q >> 5, r = q & 31;
        int id = ids[en];
        a1s[en][r] = g_a1[(size_t)id * Rn + r];
        a3s[en][r] = g_a3[(size_t)id * Rn + r];
    }
    __syncthreads();

    for (int f0 = 0; f0 < Fn; f0 += 256) {
        int f = f0 + tid;
        float b1r[Rn], b3r[Rn];
        const float4* p1 = (const float4*)(B1 + ((size_t)e * Fn + f) * Rn);
        const float4* p3 = (const float4*)(B3 + ((size_t)e * Fn + f) * Rn);
#pragma unroll
        for (int q = 0; q < 8; q++) {
            float4 v1 = p1[q], v3 = p3[q];
            b1r[q * 4 + 0] = v1.x; b1r[q * 4 + 1] = v1.y;
            b1r[q * 4 + 2] = v1.z; b1r[q * 4 + 3] = v1.w;
            b3r[q * 4 + 0] = v3.x; b3r[q * 4 + 1] = v3.y;
            b3r[q * 4 + 2] = v3.z; b3r[q * 4 + 3] = v3.w;
        }
        for (int en = 0; en < nent; en++) {
            int id = ids[en];
            int t = id >> 1, kk = id & 1;
            float l1 = 0.f, l3 = 0.f;
#pragma unroll
            for (int r = 0; r < Rn; r++) {
                l1 += b1r[r] * a1s[en][r];
                l3 += b3r[r] * a3s[en][r];
            }
            float x1 = g_base1[(size_t)t * Fn + f] + l1;
            float x3 = g_base3[(size_t)t * Fn + f] + l3;
            float sig = 1.f / (1.f + expf(-x1));
            float x2 = x1 * sig * x3;
            (kk ? g_x2k1 : g_x2k0)[(size_t)t * Fn + f] = x2;
        }
    }
}

// -------- combine + split weighted x2 (fp16 [hi|lo]) -----------------------
__global__ __launch_bounds__(256) void combine_split_x2()
{
    int t = blockIdx.x;
    float w0 = g_rw[t * 2], w1 = g_rw[t * 2 + 1];
    __half* d = g_x2s + (size_t)t * 2 * Fn;
    const float* s0 = g_x2k0 + (size_t)t * Fn;
    const float* s1 = g_x2k1 + (size_t)t * Fn;
    for (int f = threadIdx.x; f < Fn; f += 256) {
        float v = w0 * s0[f] + w1 * s1[f];
        __half hi = __float2half_rn(v);
        __half lo = __float2half_rn(v - __half2float(hi));
        d[f] = hi;
        d[Fn + f] = lo;
    }
}

// -------- grouped a2 (CH=32; float4 inner loop) ----------------------------
#define CH2 32
__global__ __launch_bounds__(256) void a2_grouped(const float* __restrict__ A2)
{
    int e, start, nent;
    if (!find_chunk(blockIdx.x, CH2, e, start, nent)) return;
    __shared__ float xs[CH2][PAD];
    __shared__ float as[Rn][PAD];
    __shared__ int ids[CH2];
    int tid = threadIdx.x;
    if (tid < CH2)
        ids[tid] = (tid < nent) ? g_list[start + tid] : g_list[start];
    __syncthreads();

    int entry = tid >> 3, rg = tid & 7;
    float acc[4] = {0.f, 0.f, 0.f, 0.f};
    int myid = ids[entry];

    for (int f0 = 0; f0 < Fn; f0 += 128) {
#pragma unroll
        for (int i = 0; i < 16; i++) {
            int q = tid + i * 256;
            int row = q >> 7, col = q & 127;
            int id = ids[row];
            const float* src = (id & 1) ? g_x2k1 : g_x2k0;
            xs[row][col] = src[(size_t)(id >> 1) * Fn + f0 + col];
        }
#pragma unroll
        for (int i = 0; i < 16; i++) {
            int q = tid + i * 256;
            int row = q >> 7, col = q & 127;
            as[row][col] = A2[(size_t)(e * Rn + row) * Fn + f0 + col];
        }
        __syncthreads();
#pragma unroll
        for (int h = 0; h < 128; h += 4) {
            float4 xv = *(const float4*)&xs[entry][h];
#pragma unroll
            for (int j = 0; j < 4; j++) {
                float4 av = *(const float4*)&as[rg + 8 * j][h];
                acc[j] += xv.x * av.x + xv.y * av.y + xv.z * av.z + xv.w * av.w;
            }
        }
        __syncthreads();
    }
    if (entry < nent) {
#pragma unroll
        for (int j = 0; j < 4; j++)
            g_a2[(size_t)myid * Rn + rg + 8 * j] = acc[j];
    }
}

// -------- grouped final (CH=64) --------------------------------------------
#define CHL 64
__global__ __launch_bounds__(256) void final_grouped(const float* __restrict__ B2)
{
    int e, start, nent;
    if (!find_chunk(blockIdx.x, CHL, e, start, nent)) return;
    __shared__ float a2s[CHL][Rn];
    __shared__ float ws[CHL];
    __shared__ int ids[CHL];
    int tid = threadIdx.x;
    if (tid < CHL) {
        int id = (tid < nent) ? g_list[start + tid] : g_list[start];
        ids[tid] = id;
        ws[tid] = g_rw[id];
    }
    __syncthreads();
#pragma unroll
    for (int i = 0; i < 8; i++) {
        int q = tid + i * 256;
        int en = q >> 5, r = q & 31;
        a2s[en][r] = g_a2[(size_t)ids[en] * Rn + r];
    }
    __syncthreads();

    for (int h0 = 0; h0 < Hn; h0 += 256) {
        int h = h0 + tid;
        float b2r[Rn];
        const float4* p2 = (const float4*)(B2 + ((size_t)e * Hn + h) * Rn);
#pragma unroll
        for (int q = 0; q < 8; q++) {
            float4 v = p2[q];
            b2r[q * 4 + 0] = v.x; b2r[q * 4 + 1] = v.y;
            b2r[q * 4 + 2] = v.z; b2r[q * 4 + 3] = v.w;
        }
        for (int en = 0; en < nent; en++) {
            int id = ids[en];
            int t = id >> 1, kk = id & 1;
            float l2 = 0.f;
#pragma unroll
            for (int r = 0; r < Rn; r++) l2 += b2r[r] * a2s[en][r];
            (kk ? g_l2k1 : g_l2k0)[(size_t)t * Hn + h] = ws[en] * l2;
        }
    }
}

// -------- add lora2 contributions into out ---------------------------------
__global__ __launch_bounds__(256) void add_out(float* __restrict__ out)
{
    int i = (blockIdx.x * 256 + threadIdx.x) * 4;
    float4 o = *(float4*)(out + i);
    float4 a = *(const float4*)(g_l2k0 + i);
    float4 b = *(const float4*)(g_l2k1 + i);
    o.x += a.x + b.x; o.y += a.y + b.y;
    o.z += a.z + b.z; o.w += a.w + b.w;
    *(float4*)(out + i) = o;
}

// ---------------------------------------------------------------------------
extern "C" void kernel_launch(void* const* d_in, const int* in_sizes, int n_in,
                              void* d_out, int out_size)
{
    (void)in_sizes; (void)n_in; (void)out_size;
    const float* x  = (const float*)d_in[0];
    const float* Wg = (const float*)d_in[1];
    const float* W1 = (const float*)d_in[2];
    const float* W2 = (const float*)d_in[3];
    const float* W3 = (const float*)d_in[4];
    const float* A1 = (const float*)d_in[5];
    const float* B1 = (const float*)d_in[6];
    const float* A2 = (const float*)d_in[7];
    const float* B2 = (const float*)d_in[8];
    const float* A3 = (const float*)d_in[9];
    const float* B3 = (const float*)d_in[10];
    float* out = (float*)d_out;

    float *base1, *base3;
    __half *xs, *w1s, *w3s, *w2s, *x2s;
    cudaGetSymbolAddress((void**)&base1, g_base1);
    cudaGetSymbolAddress((void**)&base3, g_base3);
    cudaGetSymbolAddress((void**)&xs,  g_xs);
    cudaGetSymbolAddress((void**)&w1s, g_w1s);
    cudaGetSymbolAddress((void**)&w3s, g_w3s);
    cudaGetSymbolAddress((void**)&w2s, g_w2s);
    cudaGetSymbolAddress((void**)&x2s, g_x2s);

    cudaFuncSetAttribute(gemm_f16, cudaFuncAttributeMaxDynamicSharedMemorySize,
                         SMEM_TOTAL);

    gate_kernel<<<Tn, 256>>>(x, Wg);
    hist_kernel<<<1, 256>>>();
    scatter_kernel<<<(Tn * Kn + 255) / 256, 256>>>();

    a13_grouped<<<Tn * Kn / CHA + En, 256>>>(x, A1, A3);

    split_kernel<<<Tn, 256>>>(x,  xs,  Hn, 0);   // A side [hi|lo]
    split_kernel<<<Fn, 256>>>(W1, w1s, Hn, 1);   // B side single fp16
    split_kernel<<<Fn, 256>>>(W3, w3s, Hn, 1);
    split_kernel<<<Hn, 256>>>(W2, w2s, Fn, 1);

    // base1 = x @ W1^T, base3 = x @ W3^T   (fp16 2-term, B-dedup)
    gemm_f16<<<dim3(Fn / GBN, Tn / GBM), 512, SMEM_TOTAL>>>(xs, w1s, base1, Fn, Hn);
    gemm_f16<<<dim3(Fn / GBN, Tn / GBM), 512, SMEM_TOTAL>>>(xs, w3s, base3, Fn, Hn);

    fuse_grouped<<<Tn * Kn / CHF + En, 256>>>(B1, B3);
    combine_split_x2<<<Tn, 256>>>();
    a2_grouped<<<Tn * Kn / CH2 + En, 256>>>(A2);

    // down GEMM into d_out: out = (rw0*x2_0 + rw1*x2_1) @ W2^T
    gemm_f16<<<dim3(Hn / GBN, Tn / GBM), 512, SMEM_TOTAL>>>(x2s, w2s, out, Hn, Fn);

    final_grouped<<<Tn * Kn / CHL + En, 256>>>(B2);
    add_out<<<Tn * Hn / 1024, 256>>>(out);
}

// round 9
// speedup vs baseline: 1.0620x; 1.0620x over previous
#include <cuda_runtime.h>
#include <cuda_fp16.h>
#include <math.h>
#include <stdint.h>

// Problem dims
#define Tn 2048   // tokens = B*S
#define Hn 2048   // hidden
#define Fn 7168   // ffn
#define En 8      // experts
#define Rn 32     // lora rank
#define Kn 2      // top-k

// HMMA GEMM tiling: 128x256, 512 threads, 3 stages (R7 known-good config)
#define GBM 128
#define GBN 256
#define KBE 64                     // fp16 K elems per stage = 128B rows (SW128)
#define STAGES 3
#define A_TILE_B (GBM * 128)       // 16384
#define B_TILE_B (GBN * 128)       // 32768
#define STAGE_B  (A_TILE_B + B_TILE_B)       // 49152
#define SMEM_TOTAL (STAGES * STAGE_B)        // 147456

#define SWZ(o) ((o) ^ (((o) >> 3) & 0x70))

// ---------------- scratch (device globals) ---------------------------------
__device__ __align__(256) float g_base1[Tn * Fn];
__device__ __align__(256) float g_base3[Tn * Fn];
__device__ __align__(256) float g_x2k0[Tn * Fn];
__device__ __align__(256) float g_x2k1[Tn * Fn];
__device__ __align__(256) float g_l2k0[Tn * Hn];
__device__ __align__(256) float g_l2k1[Tn * Hn];
__device__ __align__(256) __half g_xs [Tn * 2 * Hn];   // x split  [hi,lo]
__device__ __align__(256) __half g_w1s[Fn * 2 * Hn];   // W1 dup  [wh,wh]
__device__ __align__(256) __half g_w3s[Fn * 2 * Hn];   // W3 dup  [wh,wh]
__device__ __align__(256) __half g_w2s[Hn * 2 * Fn];   // W2 dup  [wh,wh]
__device__ __align__(256) __half g_x2s[Tn * 2 * Fn];   // weighted x2 [hi,lo]
__device__ int   g_sel[Tn * Kn];
__device__ float g_rw [Tn * Kn];
__device__ float g_a1 [Tn * Kn * Rn];
__device__ float g_a3 [Tn * Kn * Rn];
__device__ float g_a2 [Tn * Kn * Rn];
// expert grouping
__device__ int g_off [En + 1];
__device__ int g_cur [En];
__device__ int g_list[Tn * Kn];

// ---------------- helpers ---------------------------------------------------
__device__ __forceinline__ uint32_t smem_u32(const void* p) {
    uint32_t a;
    asm("{ .reg .u64 t; cvta.to.shared.u64 t, %1; cvt.u32.u64 %0, t; }"
        : "=r"(a) : "l"(p));
    return a;
}

__device__ __forceinline__ float warp_sum(float v) {
#pragma unroll
    for (int o = 16; o; o >>= 1) v += __shfl_xor_sync(0xffffffffu, v, o);
    return v;
}

__device__ __forceinline__ bool find_chunk(int b, int CH, int& e, int& start,
                                           int& nent) {
    int acc = 0;
    for (int ee = 0; ee < En; ee++) {
        int o0 = g_off[ee], o1 = g_off[ee + 1];
        int cnt = o1 - o0;
        int nch = (cnt + CH - 1) / CH;
        if (b < acc + nch) {
            e = ee;
            start = o0 + (b - acc) * CH;
            nent = min(CH, o1 - start);
            return true;
        }
        acc += nch;
    }
    return false;
}

#define LDSM4(r0, r1, r2, r3, addr) \
    asm volatile("ldmatrix.sync.aligned.m8n8.x4.shared.b16 {%0,%1,%2,%3}, [%4];" \
                 : "=r"(r0), "=r"(r1), "=r"(r2), "=r"(r3) : "r"(addr))

#define MMA16816(c, a, b0, b1) \
    asm volatile("mma.sync.aligned.m16n8k16.row.col.f32.f16.f16.f32 " \
                 "{%0,%1,%2,%3}, {%4,%5,%6,%7}, {%8,%9}, {%0,%1,%2,%3};" \
                 : "+f"((c)[0]), "+f"((c)[1]), "+f"((c)[2]), "+f"((c)[3]) \
                 : "r"((a)[0]), "r"((a)[1]), "r"((a)[2]), "r"((a)[3]), \
                   "r"(b0), "r"(b1))

// ---------------- fp16 split kernels (row per block) -----------------------
// mode 0 (A side): [hi, lo]; mode 1 (B side): [wh, wh]
__global__ __launch_bounds__(256) void split_kernel(
    const float* __restrict__ src, __half* __restrict__ dst,
    int cols, int bmode)
{
    int r = blockIdx.x;
    const float* s = src + (size_t)r * cols;
    __half* d = dst + (size_t)r * (2 * cols);
    for (int c = threadIdx.x * 4; c < cols; c += 256 * 4) {
        float4 v = *(const float4*)(s + c);
        __half h0 = __float2half_rn(v.x);
        __half h1 = __float2half_rn(v.y);
        __half h2 = __float2half_rn(v.z);
        __half h3 = __float2half_rn(v.w);
        __half2 hA = __halves2half2(h0, h1);
        __half2 hB = __halves2half2(h2, h3);
        *(__half2*)(d + c)     = hA;
        *(__half2*)(d + c + 2) = hB;
        if (bmode) {
            *(__half2*)(d + cols + c)     = hA;
            *(__half2*)(d + cols + c + 2) = hB;
        } else {
            __half l0 = __float2half_rn(v.x - __half2float(h0));
            __half l1 = __float2half_rn(v.y - __half2float(h1));
            __half l2 = __float2half_rn(v.z - __half2float(h2));
            __half l3 = __float2half_rn(v.w - __half2float(h3));
            *(__half2*)(d + cols + c)     = __halves2half2(l0, l1);
            *(__half2*)(d + cols + c + 2) = __halves2half2(l2, l3);
        }
    }
}

// ---------------- GEMM stage loader (cp.async, SW128) ----------------------
__device__ __forceinline__ void load_stage(
    uint32_t sb, const __half* Ab, const __half* Bb,
    int Kp, int it, int stage, int tid)
{
    uint32_t st = sb + stage * STAGE_B;
    int k0 = it * KBE;
#pragma unroll
    for (int i = 0; i < 6; i++) {
        int c = tid + i * 512;          // 0..3071
        uint32_t soff;
        const __half* g;
        if (c < 1024) {                 // A: 128 rows x 8 chunks
            int row = c >> 3, j = c & 7;
            soff = st + SWZ(row * 128 + j * 16);
            g = Ab + (size_t)row * Kp + k0 + j * 8;
        } else {                        // B: 256 rows x 8 chunks
            int cc = c - 1024;
            int row = cc >> 3, j = cc & 7;
            soff = st + A_TILE_B + SWZ(row * 128 + j * 16);
            g = Bb + (size_t)row * Kp + k0 + j * 8;
        }
        asm volatile("cp.async.cg.shared.global [%0], [%1], 16;"
                     :: "r"(soff), "l"(g) : "memory");
    }
}

// ---------------- HMMA fp16 GEMM: C[M,N] = A[M,Kp] @ B[N,Kp]^T -------------
__global__ __launch_bounds__(512, 1) void gemm_f16(
    const __half* __restrict__ A, const __half* __restrict__ B,
    float* __restrict__ C, int N, int Kp)
{
    extern __shared__ __align__(1024) char smem[];
    uint32_t sb = smem_u32(smem);
    int tid = threadIdx.x, wid = tid >> 5, lane = tid & 31;
    int wm = wid & 3, wn = wid >> 2;       // 4 warps in M, 4 in N
    int bx = blockIdx.x, by = blockIdx.y;
    const int niter = Kp / KBE;

    const __half* Ab = A + (size_t)(by * GBM) * Kp;
    const __half* Bb = B + (size_t)(bx * GBN) * Kp;

#pragma unroll
    for (int it = 0; it < STAGES - 1; it++) {
        load_stage(sb, Ab, Bb, Kp, it, it, tid);
        asm volatile("cp.async.commit_group;" ::: "memory");
    }

    float acc[2][8][4];
#pragma unroll
    for (int mi = 0; mi < 2; mi++)
#pragma unroll
        for (int nj = 0; nj < 8; nj++)
#pragma unroll
            for (int q = 0; q < 4; q++) acc[mi][nj][q] = 0.f;

    int gq = lane >> 3, rr = lane & 7;
    int kc = gq >> 1;
    uint32_t aRow[2]; int aXor[2];
#pragma unroll
    for (int mi = 0; mi < 2; mi++) {
        int m = wm * 32 + mi * 16 + (gq & 1) * 8 + rr;
        aRow[mi] = (uint32_t)(m * 128);
        aXor[mi] = m & 7;
    }
    uint32_t bRow[4]; int bXor[4];
#pragma unroll
    for (int ni = 0; ni < 4; ni++) {
        int n = wn * 64 + ni * 16 + (gq & 1) * 8 + rr;
        bRow[ni] = (uint32_t)(A_TILE_B + n * 128);
        bXor[ni] = n & 7;
    }

    int s = 0;
    for (int it = 0; it < niter; it++) {
        asm volatile("cp.async.wait_group %0;" :: "n"(STAGES - 2) : "memory");
        __syncthreads();
        int jt = it + STAGES - 1;
        if (jt < niter) {
            int sj = jt - (jt / STAGES) * STAGES;
            load_stage(sb, Ab, Bb, Kp, jt, sj, tid);
        }
        asm volatile("cp.async.commit_group;" ::: "memory");

        uint32_t stb = sb + s * STAGE_B;
        s++; if (s == STAGES) s = 0;
#pragma unroll
        for (int ks = 0; ks < 4; ks++) {
            uint32_t a[2][4];
#pragma unroll
            for (int mi = 0; mi < 2; mi++) {
                uint32_t ad = stb + aRow[mi]
                            + (uint32_t)((((ks << 1) + kc) ^ aXor[mi]) << 4);
                LDSM4(a[mi][0], a[mi][1], a[mi][2], a[mi][3], ad);
            }
            uint32_t b[4][4];
#pragma unroll
            for (int ni = 0; ni < 4; ni++) {
                uint32_t bd = stb + bRow[ni]
                            + (uint32_t)((((ks << 1) + kc) ^ bXor[ni]) << 4);
                LDSM4(b[ni][0], b[ni][1], b[ni][2], b[ni][3], bd);
            }
#pragma unroll
            for (int mi = 0; mi < 2; mi++)
#pragma unroll
                for (int ni = 0; ni < 4; ni++) {
                    MMA16816(acc[mi][ni * 2],     a[mi], b[ni][0], b[ni][2]);
                    MMA16816(acc[mi][ni * 2 + 1], a[mi], b[ni][1], b[ni][3]);
                }
        }
        __syncthreads();
    }

    int gid = lane >> 2, tig = lane & 3;
#pragma unroll
    for (int mi = 0; mi < 2; mi++) {
        int row = by * GBM + wm * 32 + mi * 16 + gid;
#pragma unroll
        for (int nj = 0; nj < 8; nj++) {
            float* p = C + (size_t)row * N + bx * GBN + wn * 64 + nj * 8 + tig * 2;
            *(float2*)p = make_float2(acc[mi][nj][0], acc[mi][nj][1]);
            *(float2*)(p + (size_t)8 * N) = make_float2(acc[mi][nj][2], acc[mi][nj][3]);
        }
    }
}

// ---------------- K1: gate -------------------------------------------------
__global__ __launch_bounds__(256) void gate_kernel(
    const float* __restrict__ x, const float* __restrict__ Wg)
{
    int t = blockIdx.x;
    int tid = threadIdx.x;
    int w = tid >> 5, lane = tid & 31;
    const float* xr = x + (size_t)t * Hn;
    const float* wr = Wg + (size_t)w * Hn;
    float s = 0.f;
    for (int h = lane * 4; h < Hn; h += 32 * 4) {
        float4 xv = *(const float4*)(xr + h);
        float4 wv = *(const float4*)(wr + h);
        s += xv.x * wv.x + xv.y * wv.y + xv.z * wv.z + xv.w * wv.w;
    }
    s = warp_sum(s);
    __shared__ float logits[En];
    if (lane == 0) logits[w] = s;
    __syncthreads();
    if (tid == 0) {
        int i0 = 0; float l0 = logits[0];
#pragma unroll
        for (int e = 1; e < En; e++) if (logits[e] > l0) { l0 = logits[e]; i0 = e; }
        int i1 = -1; float l1 = -3.0e38f;
#pragma unroll
        for (int e = 0; e < En; e++) if (e != i0 && logits[e] > l1) { l1 = logits[e]; i1 = e; }
        float r0 = 1.f / (1.f + expf(l1 - l0));
        g_sel[t * 2 + 0] = i0;
        g_sel[t * 2 + 1] = i1;
        g_rw [t * 2 + 0] = r0;
        g_rw [t * 2 + 1] = 1.f - r0;
    }
}

// ---------------- expert grouping ------------------------------------------
__global__ __launch_bounds__(256) void hist_kernel()
{
    __shared__ int hc[En];
    int tid = threadIdx.x;
    if (tid < En) hc[tid] = 0;
    __syncthreads();
    for (int i = tid; i < Tn * Kn; i += 256)
        atomicAdd(&hc[g_sel[i]], 1);
    __syncthreads();
    if (tid == 0) {
        int off = 0;
        for (int e = 0; e < En; e++) {
            g_off[e] = off;
            g_cur[e] = off;
            off += hc[e];
        }
        g_off[En] = off;
    }
}

__global__ __launch_bounds__(256) void scatter_kernel()
{
    int i = blockIdx.x * 256 + threadIdx.x;
    if (i < Tn * Kn) {
        int e = g_sel[i];
        int pos = atomicAdd(&g_cur[e], 1);
        g_list[pos] = i;
    }
}

// -------- grouped a1/a3 (CH=8 entries; float4 inner loop) ------------------
#define CHA 8
#define PAD 132
__global__ __launch_bounds__(256) void a13_grouped(
    const float* __restrict__ x, const float* __restrict__ A1,
    const float* __restrict__ A3)
{
    int e, start, nent;
    if (!find_chunk(blockIdx.x, CHA, e, start, nent)) return;
    __shared__ float xs[CHA][PAD];
    __shared__ float as[64][PAD];
    __shared__ int ids[CHA];
    int tid = threadIdx.x;
    if (tid < CHA)
        ids[tid] = (tid < nent) ? g_list[start + tid] : g_list[start];
    __syncthreads();

    int entry = tid >> 5, rg = tid & 31;
    float acc0 = 0.f, acc1 = 0.f;
    int myid = ids[entry];

    for (int h0 = 0; h0 < Hn; h0 += 128) {
#pragma unroll
        for (int i = 0; i < 4; i++) {
            int q = tid + i * 256;
            int row = q >> 7, col = q & 127;
            xs[row][col] = x[(size_t)(ids[row] >> 1) * Hn + h0 + col];
        }
#pragma unroll
        for (int i = 0; i < 32; i++) {
            int q = tid + i * 256;
            int row = q >> 7, col = q & 127;
            const float* src = (row < 32)
                ? A1 + ((size_t)(e * Rn + row) * Hn + h0 + col)
                : A3 + ((size_t)(e * Rn + row - 32) * Hn + h0 + col);
            as[row][col] = *src;
        }
        __syncthreads();
#pragma unroll
        for (int h = 0; h < 128; h += 4) {
            float4 xv = *(const float4*)&xs[entry][h];
            float4 a0 = *(const float4*)&as[rg][h];
            float4 a1 = *(const float4*)&as[rg + 32][h];
            acc0 += xv.x * a0.x + xv.y * a0.y + xv.z * a0.z + xv.w * a0.w;
            acc1 += xv.x * a1.x + xv.y * a1.y + xv.z * a1.z + xv.w * a1.w;
        }
        __syncthreads();
    }
    if (entry < nent) {
        g_a1[(size_t)myid * Rn + rg] = acc0;
        g_a3[(size_t)myid * Rn + rg] = acc1;
    }
}

// -------- grouped fuse (CH=32) ---------------------------------------------
#define CHF 32
__global__ __launch_bounds__(256) void fuse_grouped(
    const float* __restrict__ B1, const float* __restrict__ B3)
{
    int e, start, nent;
    if (!find_chunk(blockIdx.x, CHF, e, start, nent)) return;
    __shared__ float a1s[CHF][Rn];
    __shared__ float a3s[CHF][Rn];
    __shared__ int ids[CHF];
    int tid = threadIdx.x;
    if (tid < CHF)
        ids[tid] = (tid < nent) ? g_list[start + tid] : g_list[start];
    __syncthreads();
#pragma unroll
    for (int i = 0; i < 4; i++) {
        int q = tid + i * 256;
        int en = q >> 5, r = q & 31;
        int id = ids[en];
        a1s[en][r] = g_a1[(size_t)id * Rn + r];
        a3s[en][r] = g_a3[(size_t)id * Rn + r];
    }
    __syncthreads();

    for (int f0 = 0; f0 < Fn; f0 += 256) {
        int f = f0 + tid;
        float b1r[Rn], b3r[Rn];
        const float4* p1 = (const float4*)(B1 + ((size_t)e * Fn + f) * Rn);
        const float4* p3 = (const float4*)(B3 + ((size_t)e * Fn + f) * Rn);
#pragma unroll
        for (int q = 0; q < 8; q++) {
            float4 v1 = p1[q], v3 = p3[q];
            b1r[q * 4 + 0] = v1.x; b1r[q * 4 + 1] = v1.y;
            b1r[q * 4 + 2] = v1.z; b1r[q * 4 + 3] = v1.w;
            b3r[q * 4 + 0] = v3.x; b3r[q * 4 + 1] = v3.y;
            b3r[q * 4 + 2] = v3.z; b3r[q * 4 + 3] = v3.w;
        }
        for (int en = 0; en < nent; en++) {
            int id = ids[en];
            int t = id >> 1, kk = id & 1;
            float l1 = 0.f, l3 = 0.f;
#pragma unroll
            for (int r = 0; r < Rn; r++) {
                l1 += b1r[r] * a1s[en][r];
                l3 += b3r[r] * a3s[en][r];
            }
            float x1 = g_base1[(size_t)t * Fn + f] + l1;
            float x3 = g_base3[(size_t)t * Fn + f] + l3;
            float sig = 1.f / (1.f + expf(-x1));
            float x2 = x1 * sig * x3;
            (kk ? g_x2k1 : g_x2k0)[(size_t)t * Fn + f] = x2;
        }
    }
}

// -------- combine + split weighted x2 (fp16 [hi,lo]) -----------------------
__global__ __launch_bounds__(256) void combine_split_x2()
{
    int t = blockIdx.x;
    float w0 = g_rw[t * 2], w1 = g_rw[t * 2 + 1];
    __half* d = g_x2s + (size_t)t * 2 * Fn;
    const float* s0 = g_x2k0 + (size_t)t * Fn;
    const float* s1 = g_x2k1 + (size_t)t * Fn;
    for (int f = threadIdx.x; f < Fn; f += 256) {
        float v = w0 * s0[f] + w1 * s1[f];
        __half hi = __float2half_rn(v);
        __half lo = __float2half_rn(v - __half2float(hi));
        d[f] = hi;
        d[Fn + f] = lo;
    }
}

// -------- grouped a2 (CH=32; float4 inner loop) ----------------------------
#define CH2 32
__global__ __launch_bounds__(256) void a2_grouped(const float* __restrict__ A2)
{
    int e, start, nent;
    if (!find_chunk(blockIdx.x, CH2, e, start, nent)) return;
    __shared__ float xs[CH2][PAD];
    __shared__ float as[Rn][PAD];
    __shared__ int ids[CH2];
    int tid = threadIdx.x;
    if (tid < CH2)
        ids[tid] = (tid < nent) ? g_list[start + tid] : g_list[start];
    __syncthreads();

    int entry = tid >> 3, rg = tid & 7;
    float acc[4] = {0.f, 0.f, 0.f, 0.f};
    int myid = ids[entry];

    for (int f0 = 0; f0 < Fn; f0 += 128) {
#pragma unroll
        for (int i = 0; i < 16; i++) {
            int q = tid + i * 256;
            int row = q >> 7, col = q & 127;
            int id = ids[row];
            const float* src = (id & 1) ? g_x2k1 : g_x2k0;
            xs[row][col] = src[(size_t)(id >> 1) * Fn + f0 + col];
        }
#pragma unroll
        for (int i = 0; i < 16; i++) {
            int q = tid + i * 256;
            int row = q >> 7, col = q & 127;
            as[row][col] = A2[(size_t)(e * Rn + row) * Fn + f0 + col];
        }
        __syncthreads();
#pragma unroll
        for (int h = 0; h < 128; h += 4) {
            float4 xv = *(const float4*)&xs[entry][h];
#pragma unroll
            for (int j = 0; j < 4; j++) {
                float4 av = *(const float4*)&as[rg + 8 * j][h];
                acc[j] += xv.x * av.x + xv.y * av.y + xv.z * av.z + xv.w * av.w;
            }
        }
        __syncthreads();
    }
    if (entry < nent) {
#pragma unroll
        for (int j = 0; j < 4; j++)
            g_a2[(size_t)myid * Rn + rg + 8 * j] = acc[j];
    }
}

// -------- grouped final (CH=64) --------------------------------------------
#define CHL 64
__global__ __launch_bounds__(256) void final_grouped(const float* __restrict__ B2)
{
    int e, start, nent;
    if (!find_chunk(blockIdx.x, CHL, e, start, nent)) return;
    __shared__ float a2s[CHL][Rn];
    __shared__ float ws[CHL];
    __shared__ int ids[CHL];
    int tid = threadIdx.x;
    if (tid < CHL) {
        int id = (tid < nent) ? g_list[start + tid] : g_list[start];
        ids[tid] = id;
        ws[tid] = g_rw[id];
    }
    __syncthreads();
#pragma unroll
    for (int i = 0; i < 8; i++) {
        int q = tid + i * 256;
        int en = q >> 5, r = q & 31;
        a2s[en][r] = g_a2[(size_t)ids[en] * Rn + r];
    }
    __syncthreads();

    for (int h0 = 0; h0 < Hn; h0 += 256) {
        int h = h0 + tid;
        float b2r[Rn];
        const float4* p2 = (const float4*)(B2 + ((size_t)e * Hn + h) * Rn);
#pragma unroll
        for (int q = 0; q < 8; q++) {
            float4 v = p2[q];
            b2r[q * 4 + 0] = v.x; b2r[q * 4 + 1] = v.y;
            b2r[q * 4 + 2] = v.z; b2r[q * 4 + 3] = v.w;
        }
        for (int en = 0; en < nent; en++) {
            int id = ids[en];
            int t = id >> 1, kk = id & 1;
            float l2 = 0.f;
#pragma unroll
            for (int r = 0; r < Rn; r++) l2 += b2r[r] * a2s[en][r];
            (kk ? g_l2k1 : g_l2k0)[(size_t)t * Hn + h] = ws[en] * l2;
        }
    }
}

// -------- add lora2 contributions into out ---------------------------------
__global__ __launch_bounds__(256) void add_out(float* __restrict__ out)
{
    int i = (blockIdx.x * 256 + threadIdx.x) * 4;
    float4 o = *(float4*)(out + i);
    float4 a = *(const float4*)(g_l2k0 + i);
    float4 b = *(const float4*)(g_l2k1 + i);
    o.x += a.x + b.x; o.y += a.y + b.y;
    o.z += a.z + b.z; o.w += a.w + b.w;
    *(float4*)(out + i) = o;
}

// ---------------------------------------------------------------------------
extern "C" void kernel_launch(void* const* d_in, const int* in_sizes, int n_in,
                              void* d_out, int out_size)
{
    (void)in_sizes; (void)n_in; (void)out_size;
    const float* x  = (const float*)d_in[0];
    const float* Wg = (const float*)d_in[1];
    const float* W1 = (const float*)d_in[2];
    const float* W2 = (const float*)d_in[3];
    const float* W3 = (const float*)d_in[4];
    const float* A1 = (const float*)d_in[5];
    const float* B1 = (const float*)d_in[6];
    const float* A2 = (const float*)d_in[7];
    const float* B2 = (const float*)d_in[8];
    const float* A3 = (const float*)d_in[9];
    const float* B3 = (const float*)d_in[10];
    float* out = (float*)d_out;

    float *base1, *base3;
    __half *xs, *w1s, *w3s, *w2s, *x2s;
    cudaGetSymbolAddress((void**)&base1, g_base1);
    cudaGetSymbolAddress((void**)&base3, g_base3);
    cudaGetSymbolAddress((void**)&xs,  g_xs);
    cudaGetSymbolAddress((void**)&w1s, g_w1s);
    cudaGetSymbolAddress((void**)&w3s, g_w3s);
    cudaGetSymbolAddress((void**)&w2s, g_w2s);
    cudaGetSymbolAddress((void**)&x2s, g_x2s);

    cudaFuncSetAttribute(gemm_f16, cudaFuncAttributeMaxDynamicSharedMemorySize,
                         SMEM_TOTAL);

    // side streams + events for graph-captured fork/join (created once;
    // identical launch graph every call)
    static cudaStream_t s1 = nullptr, s2 = nullptr;
    static cudaEvent_t ev0 = nullptr, ev1 = nullptr, ev2 = nullptr, ev3 = nullptr;
    if (s1 == nullptr) {
        cudaStreamCreateWithFlags(&s1, cudaStreamNonBlocking);
        cudaStreamCreateWithFlags(&s2, cudaStreamNonBlocking);
        cudaEventCreateWithFlags(&ev0, cudaEventDisableTiming);
        cudaEventCreateWithFlags(&ev1, cudaEventDisableTiming);
        cudaEventCreateWithFlags(&ev2, cudaEventDisableTiming);
        cudaEventCreateWithFlags(&ev3, cudaEventDisableTiming);
    }

    // main chain: gate -> grouping
    gate_kernel<<<Tn, 256>>>(x, Wg);
    hist_kernel<<<1, 256>>>();
    scatter_kernel<<<(Tn * Kn + 255) / 256, 256>>>();

    // fork: a13_grouped runs concurrent with splits + base GEMMs
    cudaEventRecord(ev0, 0);
    cudaStreamWaitEvent(s1, ev0, 0);
    a13_grouped<<<Tn * Kn / CHA + En, 256, 0, s1>>>(x, A1, A3);
    cudaEventRecord(ev1, s1);

    split_kernel<<<Tn, 256>>>(x,  xs,  Hn, 0);   // A side [hi,lo]
    split_kernel<<<Fn, 256>>>(W1, w1s, Hn, 1);   // B side [wh,wh]
    split_kernel<<<Fn, 256>>>(W3, w3s, Hn, 1);
    split_kernel<<<Hn, 256>>>(W2, w2s, Fn, 1);

    gemm_f16<<<dim3(Fn / GBN, Tn / GBM), 512, SMEM_TOTAL>>>(xs, w1s, base1, Fn, 2 * Hn);
    gemm_f16<<<dim3(Fn / GBN, Tn / GBM), 512, SMEM_TOTAL>>>(xs, w3s, base3, Fn, 2 * Hn);

    // join a13 before fuse
    cudaStreamWaitEvent(0, ev1, 0);
    fuse_grouped<<<Tn * Kn / CHF + En, 256>>>(B1, B3);
    combine_split_x2<<<Tn, 256>>>();
    a2_grouped<<<Tn * Kn / CH2 + En, 256>>>(A2);

    // fork: final_grouped (needs a2 only) runs concurrent with down GEMM
    cudaEventRecord(ev2, 0);
    cudaStreamWaitEvent(s2, ev2, 0);
    final_grouped<<<Tn * Kn / CHL + En, 256, 0, s2>>>(B2);
    cudaEventRecord(ev3, s2);

    gemm_f16<<<dim3(Hn / GBN, Tn / GBM), 512, SMEM_TOTAL>>>(x2s, w2s, out, Hn, 2 * Fn);

    // join final before add
    cudaStreamWaitEvent(0, ev3, 0);
    add_out<<<Tn * Hn / 1024, 256>>>(out);
}

// round 10
// speedup vs baseline: 1.3330x; 1.2552x over previous
#include <cuda_runtime.h>
#include <cuda_fp16.h>
#include <math.h>
#include <stdint.h>

// Problem dims
#define Tn 2048   // tokens = B*S
#define Hn 2048   // hidden
#define Fn 7168   // ffn
#define En 8      // experts
#define Rn 32     // lora rank
#define Kn 2      // top-k

// HMMA GEMM tiling: 128x256, 512 threads, 3 stages (known-good config)
#define GBM 128
#define GBN 256
#define KBE 64                     // fp16 K elems per stage = 128B rows (SW128)
#define STAGES 3
#define A_TILE_B (GBM * 128)       // 16384
#define B_TILE_B (GBN * 128)       // 32768
#define STAGE_B  (A_TILE_B + B_TILE_B)       // 49152
#define SMEM_TOTAL (STAGES * STAGE_B)        // 147456

#define SWZ(o) ((o) ^ (((o) >> 3) & 0x70))

// ---------------- scratch (device globals) ---------------------------------
__device__ __align__(256) float g_base1[Tn * Fn];
__device__ __align__(256) float g_base3[Tn * Fn];
__device__ __align__(256) float g_x2k0[Tn * Fn];
__device__ __align__(256) float g_x2k1[Tn * Fn];
__device__ __align__(256) float g_l2k0[Tn * Hn];
__device__ __align__(256) float g_l2k1[Tn * Hn];
__device__ __align__(256) __half g_xs [Tn * Hn];   // x fp16
__device__ __align__(256) __half g_w1s[Fn * Hn];   // W1 fp16
__device__ __align__(256) __half g_w3s[Fn * Hn];   // W3 fp16
__device__ __align__(256) __half g_w2s[Hn * Fn];   // W2 fp16
__device__ __align__(256) __half g_x2s[Tn * Fn];   // weighted x2 fp16
__device__ int   g_sel[Tn * Kn];
__device__ float g_rw [Tn * Kn];
__device__ float g_a1 [Tn * Kn * Rn];
__device__ float g_a3 [Tn * Kn * Rn];
__device__ float g_a2 [Tn * Kn * Rn];
// expert grouping
__device__ int g_off [En + 1];
__device__ int g_cur [En];
__device__ int g_list[Tn * Kn];

// ---------------- helpers ---------------------------------------------------
__device__ __forceinline__ uint32_t smem_u32(const void* p) {
    uint32_t a;
    asm("{ .reg .u64 t; cvta.to.shared.u64 t, %1; cvt.u32.u64 %0, t; }"
        : "=r"(a) : "l"(p));
    return a;
}

__device__ __forceinline__ float warp_sum(float v) {
#pragma unroll
    for (int o = 16; o; o >>= 1) v += __shfl_xor_sync(0xffffffffu, v, o);
    return v;
}

__device__ __forceinline__ bool find_chunk(int b, int CH, int& e, int& start,
                                           int& nent) {
    int acc = 0;
    for (int ee = 0; ee < En; ee++) {
        int o0 = g_off[ee], o1 = g_off[ee + 1];
        int cnt = o1 - o0;
        int nch = (cnt + CH - 1) / CH;
        if (b < acc + nch) {
            e = ee;
            start = o0 + (b - acc) * CH;
            nent = min(CH, o1 - start);
            return true;
        }
        acc += nch;
    }
    return false;
}

#define LDSM4(r0, r1, r2, r3, addr) \
    asm volatile("ldmatrix.sync.aligned.m8n8.x4.shared.b16 {%0,%1,%2,%3}, [%4];" \
                 : "=r"(r0), "=r"(r1), "=r"(r2), "=r"(r3) : "r"(addr))

#define MMA16816(c, a, b0, b1) \
    asm volatile("mma.sync.aligned.m16n8k16.row.col.f32.f16.f16.f32 " \
                 "{%0,%1,%2,%3}, {%4,%5,%6,%7}, {%8,%9}, {%0,%1,%2,%3};" \
                 : "+f"((c)[0]), "+f"((c)[1]), "+f"((c)[2]), "+f"((c)[3]) \
                 : "r"((a)[0]), "r"((a)[1]), "r"((a)[2]), "r"((a)[3]), \
                   "r"(b0), "r"(b1))

// ---------------- fp32 -> fp16 convert (row per block) ---------------------
__global__ __launch_bounds__(256) void convert_kernel(
    const float* __restrict__ src, __half* __restrict__ dst, int cols)
{
    int r = blockIdx.x;
    const float* s = src + (size_t)r * cols;
    __half* d = dst + (size_t)r * cols;
    for (int c = threadIdx.x * 4; c < cols; c += 256 * 4) {
        float4 v = *(const float4*)(s + c);
        __half2 hA = __halves2half2(__float2half_rn(v.x), __float2half_rn(v.y));
        __half2 hB = __halves2half2(__float2half_rn(v.z), __float2half_rn(v.w));
        *(__half2*)(d + c)     = hA;
        *(__half2*)(d + c + 2) = hB;
    }
}

// ---------------- GEMM stage loader (cp.async, SW128) ----------------------
__device__ __forceinline__ void load_stage(
    uint32_t sb, const __half* Ab, const __half* Bb,
    int Kp, int it, int stage, int tid)
{
    uint32_t st = sb + stage * STAGE_B;
    int k0 = it * KBE;
#pragma unroll
    for (int i = 0; i < 6; i++) {
        int c = tid + i * 512;          // 0..3071
        uint32_t soff;
        const __half* g;
        if (c < 1024) {                 // A: 128 rows x 8 chunks
            int row = c >> 3, j = c & 7;
            soff = st + SWZ(row * 128 + j * 16);
            g = Ab + (size_t)row * Kp + k0 + j * 8;
        } else {                        // B: 256 rows x 8 chunks
            int cc = c - 1024;
            int row = cc >> 3, j = cc & 7;
            soff = st + A_TILE_B + SWZ(row * 128 + j * 16);
            g = Bb + (size_t)row * Kp + k0 + j * 8;
        }
        asm volatile("cp.async.cg.shared.global [%0], [%1], 16;"
                     :: "r"(soff), "l"(g) : "memory");
    }
}

// ---------------- HMMA fp16 GEMM: C[M,N] = A[M,Kp] @ B[N,Kp]^T -------------
__global__ __launch_bounds__(512, 1) void gemm_f16(
    const __half* __restrict__ A, const __half* __restrict__ B,
    float* __restrict__ C, int N, int Kp)
{
    extern __shared__ __align__(1024) char smem[];
    uint32_t sb = smem_u32(smem);
    int tid = threadIdx.x, wid = tid >> 5, lane = tid & 31;
    int wm = wid & 3, wn = wid >> 2;       // 4 warps in M, 4 in N
    int bx = blockIdx.x, by = blockIdx.y;
    const int niter = Kp / KBE;

    const __half* Ab = A + (size_t)(by * GBM) * Kp;
    const __half* Bb = B + (size_t)(bx * GBN) * Kp;

#pragma unroll
    for (int it = 0; it < STAGES - 1; it++) {
        load_stage(sb, Ab, Bb, Kp, it, it, tid);
        asm volatile("cp.async.commit_group;" ::: "memory");
    }

    float acc[2][8][4];
#pragma unroll
    for (int mi = 0; mi < 2; mi++)
#pragma unroll
        for (int nj = 0; nj < 8; nj++)
#pragma unroll
            for (int q = 0; q < 4; q++) acc[mi][nj][q] = 0.f;

    int gq = lane >> 3, rr = lane & 7;
    int kc = gq >> 1;
    uint32_t aRow[2]; int aXor[2];
#pragma unroll
    for (int mi = 0; mi < 2; mi++) {
        int m = wm * 32 + mi * 16 + (gq & 1) * 8 + rr;
        aRow[mi] = (uint32_t)(m * 128);
        aXor[mi] = m & 7;
    }
    uint32_t bRow[4]; int bXor[4];
#pragma unroll
    for (int ni = 0; ni < 4; ni++) {
        int n = wn * 64 + ni * 16 + (gq & 1) * 8 + rr;
        bRow[ni] = (uint32_t)(A_TILE_B + n * 128);
        bXor[ni] = n & 7;
    }

    int s = 0;
    for (int it = 0; it < niter; it++) {
        asm volatile("cp.async.wait_group %0;" :: "n"(STAGES - 2) : "memory");
        __syncthreads();
        int jt = it + STAGES - 1;
        if (jt < niter) {
            int sj = jt - (jt / STAGES) * STAGES;
            load_stage(sb, Ab, Bb, Kp, jt, sj, tid);
        }
        asm volatile("cp.async.commit_group;" ::: "memory");

        uint32_t stb = sb + s * STAGE_B;
        s++; if (s == STAGES) s = 0;
#pragma unroll
        for (int ks = 0; ks < 4; ks++) {
            uint32_t a[2][4];
#pragma unroll
            for (int mi = 0; mi < 2; mi++) {
                uint32_t ad = stb + aRow[mi]
                            + (uint32_t)((((ks << 1) + kc) ^ aXor[mi]) << 4);
                LDSM4(a[mi][0], a[mi][1], a[mi][2], a[mi][3], ad);
            }
            uint32_t b[4][4];
#pragma unroll
            for (int ni = 0; ni < 4; ni++) {
                uint32_t bd = stb + bRow[ni]
                            + (uint32_t)((((ks << 1) + kc) ^ bXor[ni]) << 4);
                LDSM4(b[ni][0], b[ni][1], b[ni][2], b[ni][3], bd);
            }
#pragma unroll
            for (int mi = 0; mi < 2; mi++)
#pragma unroll
                for (int ni = 0; ni < 4; ni++) {
                    MMA16816(acc[mi][ni * 2],     a[mi], b[ni][0], b[ni][2]);
                    MMA16816(acc[mi][ni * 2 + 1], a[mi], b[ni][1], b[ni][3]);
                }
        }
        __syncthreads();
    }

    int gid = lane >> 2, tig = lane & 3;
#pragma unroll
    for (int mi = 0; mi < 2; mi++) {
        int row = by * GBM + wm * 32 + mi * 16 + gid;
#pragma unroll
        for (int nj = 0; nj < 8; nj++) {
            float* p = C + (size_t)row * N + bx * GBN + wn * 64 + nj * 8 + tig * 2;
            *(float2*)p = make_float2(acc[mi][nj][0], acc[mi][nj][1]);
            *(float2*)(p + (size_t)8 * N) = make_float2(acc[mi][nj][2], acc[mi][nj][3]);
        }
    }
}

// ---------------- K1: gate -------------------------------------------------
__global__ __launch_bounds__(256) void gate_kernel(
    const float* __restrict__ x, const float* __restrict__ Wg)
{
    int t = blockIdx.x;
    int tid = threadIdx.x;
    int w = tid >> 5, lane = tid & 31;
    const float* xr = x + (size_t)t * Hn;
    const float* wr = Wg + (size_t)w * Hn;
    float s = 0.f;
    for (int h = lane * 4; h < Hn; h += 32 * 4) {
        float4 xv = *(const float4*)(xr + h);
        float4 wv = *(const float4*)(wr + h);
        s += xv.x * wv.x + xv.y * wv.y + xv.z * wv.z + xv.w * wv.w;
    }
    s = warp_sum(s);
    __shared__ float logits[En];
    if (lane == 0) logits[w] = s;
    __syncthreads();
    if (tid == 0) {
        int i0 = 0; float l0 = logits[0];
#pragma unroll
        for (int e = 1; e < En; e++) if (logits[e] > l0) { l0 = logits[e]; i0 = e; }
        int i1 = -1; float l1 = -3.0e38f;
#pragma unroll
        for (int e = 0; e < En; e++) if (e != i0 && logits[e] > l1) { l1 = logits[e]; i1 = e; }
        float r0 = 1.f / (1.f + expf(l1 - l0));
        g_sel[t * 2 + 0] = i0;
        g_sel[t * 2 + 1] = i1;
        g_rw [t * 2 + 0] = r0;
        g_rw [t * 2 + 1] = 1.f - r0;
    }
}

// ---------------- expert grouping ------------------------------------------
__global__ __launch_bounds__(256) void hist_kernel()
{
    __shared__ int hc[En];
    int tid = threadIdx.x;
    if (tid < En) hc[tid] = 0;
    __syncthreads();
    for (int i = tid; i < Tn * Kn; i += 256)
        atomicAdd(&hc[g_sel[i]], 1);
    __syncthreads();
    if (tid == 0) {
        int off = 0;
        for (int e = 0; e < En; e++) {
            g_off[e] = off;
            g_cur[e] = off;
            off += hc[e];
        }
        g_off[En] = off;
    }
}

__global__ __launch_bounds__(256) void scatter_kernel()
{
    int i = blockIdx.x * 256 + threadIdx.x;
    if (i < Tn * Kn) {
        int e = g_sel[i];
        int pos = atomicAdd(&g_cur[e], 1);
        g_list[pos] = i;
    }
}

// -------- grouped a1/a3 (CH=8 entries; float4 inner loop) ------------------
#define CHA 8
#define PAD 132
__global__ __launch_bounds__(256) void a13_grouped(
    const float* __restrict__ x, const float* __restrict__ A1,
    const float* __restrict__ A3)
{
    int e, start, nent;
    if (!find_chunk(blockIdx.x, CHA, e, start, nent)) return;
    __shared__ float xs[CHA][PAD];
    __shared__ float as[64][PAD];
    __shared__ int ids[CHA];
    int tid = threadIdx.x;
    if (tid < CHA)
        ids[tid] = (tid < nent) ? g_list[start + tid] : g_list[start];
    __syncthreads();

    int entry = tid >> 5, rg = tid & 31;
    float acc0 = 0.f, acc1 = 0.f;
    int myid = ids[entry];

    for (int h0 = 0; h0 < Hn; h0 += 128) {
#pragma unroll
        for (int i = 0; i < 4; i++) {
            int q = tid + i * 256;
            int row = q >> 7, col = q & 127;
            xs[row][col] = x[(size_t)(ids[row] >> 1) * Hn + h0 + col];
        }
#pragma unroll
        for (int i = 0; i < 32; i++) {
            int q = tid + i * 256;
            int row = q >> 7, col = q & 127;
            const float* src = (row < 32)
                ? A1 + ((size_t)(e * Rn + row) * Hn + h0 + col)
                : A3 + ((size_t)(e * Rn + row - 32) * Hn + h0 + col);
            as[row][col] = *src;
        }
        __syncthreads();
#pragma unroll
        for (int h = 0; h < 128; h += 4) {
            float4 xv = *(const float4*)&xs[entry][h];
            float4 a0 = *(const float4*)&as[rg][h];
            float4 a1 = *(const float4*)&as[rg + 32][h];
            acc0 += xv.x * a0.x + xv.y * a0.y + xv.z * a0.z + xv.w * a0.w;
            acc1 += xv.x * a1.x + xv.y * a1.y + xv.z * a1.z + xv.w * a1.w;
        }
        __syncthreads();
    }
    if (entry < nent) {
        g_a1[(size_t)myid * Rn + rg] = acc0;
        g_a3[(size_t)myid * Rn + rg] = acc1;
    }
}

// -------- grouped fuse (CH=32) ---------------------------------------------
#define CHF 32
__global__ __launch_bounds__(256) void fuse_grouped(
    const float* __restrict__ B1, const float* __restrict__ B3)
{
    int e, start, nent;
    if (!find_chunk(blockIdx.x, CHF, e, start, nent)) return;
    __shared__ float a1s[CHF][Rn];
    __shared__ float a3s[CHF][Rn];
    __shared__ int ids[CHF];
    int tid = threadIdx.x;
    if (tid < CHF)
        ids[tid] = (tid < nent) ? g_list[start + tid] : g_list[start];
    __syncthreads();
#pragma unroll
    for (int i = 0; i < 4; i++) {
        int q = tid + i * 256;
        int en = q >> 5, r = q & 31;
        int id = ids[en];
        a1s[en][r] = g_a1[(size_t)id * Rn + r];
        a3s[en][r] = g_a3[(size_t)id * Rn + r];
    }
    __syncthreads();

    for (int f0 = 0; f0 < Fn; f0 += 256) {
        int f = f0 + tid;
        float b1r[Rn], b3r[Rn];
        const float4* p1 = (const float4*)(B1 + ((size_t)e * Fn + f) * Rn);
        const float4* p3 = (const float4*)(B3 + ((size_t)e * Fn + f) * Rn);
#pragma unroll
        for (int q = 0; q < 8; q++) {
            float4 v1 = p1[q], v3 = p3[q];
            b1r[q * 4 + 0] = v1.x; b1r[q * 4 + 1] = v1.y;
            b1r[q * 4 + 2] = v1.z; b1r[q * 4 + 3] = v1.w;
            b3r[q * 4 + 0] = v3.x; b3r[q * 4 + 1] = v3.y;
            b3r[q * 4 + 2] = v3.z; b3r[q * 4 + 3] = v3.w;
        }
        for (int en = 0; en < nent; en++) {
            int id = ids[en];
            int t = id >> 1, kk = id & 1;
            float l1 = 0.f, l3 = 0.f;
#pragma unroll
            for (int r = 0; r < Rn; r++) {
                l1 += b1r[r] * a1s[en][r];
                l3 += b3r[r] * a3s[en][r];
            }
            float x1 = g_base1[(size_t)t * Fn + f] + l1;
            float x3 = g_base3[(size_t)t * Fn + f] + l3;
            float sig = 1.f / (1.f + expf(-x1));
            float x2 = x1 * sig * x3;
            (kk ? g_x2k1 : g_x2k0)[(size_t)t * Fn + f] = x2;
        }
    }
}

// -------- combine weighted x2 -> fp16 --------------------------------------
__global__ __launch_bounds__(256) void combine_x2()
{
    int t = blockIdx.x;
    float w0 = g_rw[t * 2], w1 = g_rw[t * 2 + 1];
    __half* d = g_x2s + (size_t)t * Fn;
    const float* s0 = g_x2k0 + (size_t)t * Fn;
    const float* s1 = g_x2k1 + (size_t)t * Fn;
    for (int f = threadIdx.x * 2; f < Fn; f += 256 * 2) {
        float2 v0 = *(const float2*)(s0 + f);
        float2 v1 = *(const float2*)(s1 + f);
        *(__half2*)(d + f) = __halves2half2(
            __float2half_rn(w0 * v0.x + w1 * v1.x),
            __float2half_rn(w0 * v0.y + w1 * v1.y));
    }
}

// -------- grouped a2 (CH=32; float4 inner loop) ----------------------------
#define CH2 32
__global__ __launch_bounds__(256) void a2_grouped(const float* __restrict__ A2)
{
    int e, start, nent;
    if (!find_chunk(blockIdx.x, CH2, e, start, nent)) return;
    __shared__ float xs[CH2][PAD];
    __shared__ float as[Rn][PAD];
    __shared__ int ids[CH2];
    int tid = threadIdx.x;
    if (tid < CH2)
        ids[tid] = (tid < nent) ? g_list[start + tid] : g_list[start];
    __syncthreads();

    int entry = tid >> 3, rg = tid & 7;
    float acc[4] = {0.f, 0.f, 0.f, 0.f};
    int myid = ids[entry];

    for (int f0 = 0; f0 < Fn; f0 += 128) {
#pragma unroll
        for (int i = 0; i < 16; i++) {
            int q = tid + i * 256;
            int row = q >> 7, col = q & 127;
            int id = ids[row];
            const float* src = (id & 1) ? g_x2k1 : g_x2k0;
            xs[row][col] = src[(size_t)(id >> 1) * Fn + f0 + col];
        }
#pragma unroll
        for (int i = 0; i < 16; i++) {
            int q = tid + i * 256;
            int row = q >> 7, col = q & 127;
            as[row][col] = A2[(size_t)(e * Rn + row) * Fn + f0 + col];
        }
        __syncthreads();
#pragma unroll
        for (int h = 0; h < 128; h += 4) {
            float4 xv = *(const float4*)&xs[entry][h];
#pragma unroll
            for (int j = 0; j < 4; j++) {
                float4 av = *(const float4*)&as[rg + 8 * j][h];
                acc[j] += xv.x * av.x + xv.y * av.y + xv.z * av.z + xv.w * av.w;
            }
        }
        __syncthreads();
    }
    if (entry < nent) {
#pragma unroll
        for (int j = 0; j < 4; j++)
            g_a2[(size_t)myid * Rn + rg + 8 * j] = acc[j];
    }
}

// -------- grouped final (CH=64) --------------------------------------------
#define CHL 64
__global__ __launch_bounds__(256) void final_grouped(const float* __restrict__ B2)
{
    int e, start, nent;
    if (!find_chunk(blockIdx.x, CHL, e, start, nent)) return;
    __shared__ float a2s[CHL][Rn];
    __shared__ float ws[CHL];
    __shared__ int ids[CHL];
    int tid = threadIdx.x;
    if (tid < CHL) {
        int id = (tid < nent) ? g_list[start + tid] : g_list[start];
        ids[tid] = id;
        ws[tid] = g_rw[id];
    }
    __syncthreads();
#pragma unroll
    for (int i = 0; i < 8; i++) {
        int q = tid + i * 256;
        int en = q >> 5, r = q & 31;
        a2s[en][r] = g_a2[(size_t)ids[en] * Rn + r];
    }
    __syncthreads();

    for (int h0 = 0; h0 < Hn; h0 += 256) {
        int h = h0 + tid;
        float b2r[Rn];
        const float4* p2 = (const float4*)(B2 + ((size_t)e * Hn + h) * Rn);
#pragma unroll
        for (int q = 0; q < 8; q++) {
            float4 v = p2[q];
            b2r[q * 4 + 0] = v.x; b2r[q * 4 + 1] = v.y;
            b2r[q * 4 + 2] = v.z; b2r[q * 4 + 3] = v.w;
        }
        for (int en = 0; en < nent; en++) {
            int id = ids[en];
            int t = id >> 1, kk = id & 1;
            float l2 = 0.f;
#pragma unroll
            for (int r = 0; r < Rn; r++) l2 += b2r[r] * a2s[en][r];
            (kk ? g_l2k1 : g_l2k0)[(size_t)t * Hn + h] = ws[en] * l2;
        }
    }
}

// -------- add lora2 contributions into out ---------------------------------
__global__ __launch_bounds__(256) void add_out(float* __restrict__ out)
{
    int i = (blockIdx.x * 256 + threadIdx.x) * 4;
    float4 o = *(float4*)(out + i);
    float4 a = *(const float4*)(g_l2k0 + i);
    float4 b = *(const float4*)(g_l2k1 + i);
    o.x += a.x + b.x; o.y += a.y + b.y;
    o.z += a.z + b.z; o.w += a.w + b.w;
    *(float4*)(out + i) = o;
}

// ---------------------------------------------------------------------------
extern "C" void kernel_launch(void* const* d_in, const int* in_sizes, int n_in,
                              void* d_out, int out_size)
{
    (void)in_sizes; (void)n_in; (void)out_size;
    const float* x  = (const float*)d_in[0];
    const float* Wg = (const float*)d_in[1];
    const float* W1 = (const float*)d_in[2];
    const float* W2 = (const float*)d_in[3];
    const float* W3 = (const float*)d_in[4];
    const float* A1 = (const float*)d_in[5];
    const float* B1 = (const float*)d_in[6];
    const float* A2 = (const float*)d_in[7];
    const float* B2 = (const float*)d_in[8];
    const float* A3 = (const float*)d_in[9];
    const float* B3 = (const float*)d_in[10];
    float* out = (float*)d_out;

    float *base1, *base3;
    __half *xs, *w1s, *w3s, *w2s, *x2s;
    cudaGetSymbolAddress((void**)&base1, g_base1);
    cudaGetSymbolAddress((void**)&base3, g_base3);
    cudaGetSymbolAddress((void**)&xs,  g_xs);
    cudaGetSymbolAddress((void**)&w1s, g_w1s);
    cudaGetSymbolAddress((void**)&w3s, g_w3s);
    cudaGetSymbolAddress((void**)&w2s, g_w2s);
    cudaGetSymbolAddress((void**)&x2s, g_x2s);

    cudaFuncSetAttribute(gemm_f16, cudaFuncAttributeMaxDynamicSharedMemorySize,
                         SMEM_TOTAL);

    static cudaStream_t s1 = nullptr, s2 = nullptr;
    static cudaEvent_t ev0 = nullptr, ev1 = nullptr, ev2 = nullptr, ev3 = nullptr;
    if (s1 == nullptr) {
        cudaStreamCreateWithFlags(&s1, cudaStreamNonBlocking);
        cudaStreamCreateWithFlags(&s2, cudaStreamNonBlocking);
        cudaEventCreateWithFlags(&ev0, cudaEventDisableTiming);
        cudaEventCreateWithFlags(&ev1, cudaEventDisableTiming);
        cudaEventCreateWithFlags(&ev2, cudaEventDisableTiming);
        cudaEventCreateWithFlags(&ev3, cudaEventDisableTiming);
    }

    // main chain: gate -> grouping
    gate_kernel<<<Tn, 256>>>(x, Wg);
    hist_kernel<<<1, 256>>>();
    scatter_kernel<<<(Tn * Kn + 255) / 256, 256>>>();

    // fork: a13_grouped concurrent with converts + base GEMMs
    cudaEventRecord(ev0, 0);
    cudaStreamWaitEvent(s1, ev0, 0);
    a13_grouped<<<Tn * Kn / CHA + En, 256, 0, s1>>>(x, A1, A3);
    cudaEventRecord(ev1, s1);

    convert_kernel<<<Tn, 256>>>(x,  xs,  Hn);
    convert_kernel<<<Fn, 256>>>(W1, w1s, Hn);
    convert_kernel<<<Fn, 256>>>(W3, w3s, Hn);
    convert_kernel<<<Hn, 256>>>(W2, w2s, Fn);

    gemm_f16<<<dim3(Fn / GBN, Tn / GBM), 512, SMEM_TOTAL>>>(xs, w1s, base1, Fn, Hn);
    gemm_f16<<<dim3(Fn / GBN, Tn / GBM), 512, SMEM_TOTAL>>>(xs, w3s, base3, Fn, Hn);

    // join a13 before fuse
    cudaStreamWaitEvent(0, ev1, 0);
    fuse_grouped<<<Tn * Kn / CHF + En, 256>>>(B1, B3);
    combine_x2<<<Tn, 256>>>();
    a2_grouped<<<Tn * Kn / CH2 + En, 256>>>(A2);

    // fork: final_grouped concurrent with down GEMM
    cudaEventRecord(ev2, 0);
    cudaStreamWaitEvent(s2, ev2, 0);
    final_grouped<<<Tn * Kn / CHL + En, 256, 0, s2>>>(B2);
    cudaEventRecord(ev3, s2);

    gemm_f16<<<dim3(Hn / GBN, Tn / GBM), 512, SMEM_TOTAL>>>(x2s, w2s, out, Hn, Fn);

    // join final before add
    cudaStreamWaitEvent(0, ev3, 0);
    add_out<<<Tn * Hn / 1024, 256>>>(out);
}

// round 11
// speedup vs baseline: 1.4223x; 1.0670x over previous
#include <cuda_runtime.h>
#include <cuda_fp16.h>
#include <math.h>
#include <stdint.h>

// Problem dims
#define Tn 2048   // tokens = B*S
#define Hn 2048   // hidden
#define Fn 7168   // ffn
#define En 8      // experts
#define Rn 32     // lora rank
#define Kn 2      // top-k

// HMMA GEMM tiling: 128x256, 512 threads, 3 stages (known-good config)
#define GBM 128
#define GBN 256
#define KBE 64                     // fp16 K elems per stage = 128B rows (SW128)
#define STAGES 3
#define A_TILE_B (GBM * 128)       // 16384
#define B_TILE_B (GBN * 128)       // 32768
#define STAGE_B  (A_TILE_B + B_TILE_B)       // 49152
#define SMEM_TOTAL (STAGES * STAGE_B)        // 147456

#define SWZ(o) ((o) ^ (((o) >> 3) & 0x70))

// ---------------- scratch (device globals) ---------------------------------
__device__ __align__(256) float g_base1[Tn * Fn];
__device__ __align__(256) float g_base3[Tn * Fn];
__device__ __align__(256) __half g_x2k0[Tn * Fn];   // per-slot x2 (fp16)
__device__ __align__(256) __half g_x2k1[Tn * Fn];
__device__ __align__(256) float g_l2k0[Tn * Hn];
__device__ __align__(256) float g_l2k1[Tn * Hn];
__device__ __align__(256) __half g_xs [Tn * Hn];    // x fp16
__device__ __align__(256) __half g_w1s[Fn * Hn];    // W1 fp16
__device__ __align__(256) __half g_w3s[Fn * Hn];    // W3 fp16
__device__ __align__(256) __half g_w2s[Hn * Fn];    // W2 fp16
__device__ __align__(256) __half g_x2s[Tn * Fn];    // weighted x2 fp16
__device__ int   g_sel[Tn * Kn];
__device__ float g_rw [Tn * Kn];
__device__ float g_a1 [Tn * Kn * Rn];
__device__ float g_a3 [Tn * Kn * Rn];
__device__ float g_a2 [Tn * Kn * Rn];
// expert grouping
__device__ int g_off [En + 1];
__device__ int g_cur [En];
__device__ int g_list[Tn * Kn];

// ---------------- helpers ---------------------------------------------------
__device__ __forceinline__ uint32_t smem_u32(const void* p) {
    uint32_t a;
    asm("{ .reg .u64 t; cvta.to.shared.u64 t, %1; cvt.u32.u64 %0, t; }"
        : "=r"(a) : "l"(p));
    return a;
}

__device__ __forceinline__ float warp_sum(float v) {
#pragma unroll
    for (int o = 16; o; o >>= 1) v += __shfl_xor_sync(0xffffffffu, v, o);
    return v;
}

__device__ __forceinline__ bool find_chunk(int b, int CH, int& e, int& start,
                                           int& nent) {
    int acc = 0;
    for (int ee = 0; ee < En; ee++) {
        int o0 = g_off[ee], o1 = g_off[ee + 1];
        int cnt = o1 - o0;
        int nch = (cnt + CH - 1) / CH;
        if (b < acc + nch) {
            e = ee;
            start = o0 + (b - acc) * CH;
            nent = min(CH, o1 - start);
            return true;
        }
        acc += nch;
    }
    return false;
}

#define LDSM4(r0, r1, r2, r3, addr) \
    asm volatile("ldmatrix.sync.aligned.m8n8.x4.shared.b16 {%0,%1,%2,%3}, [%4];" \
                 : "=r"(r0), "=r"(r1), "=r"(r2), "=r"(r3) : "r"(addr))

#define MMA16816(c, a, b0, b1) \
    asm volatile("mma.sync.aligned.m16n8k16.row.col.f32.f16.f16.f32 " \
                 "{%0,%1,%2,%3}, {%4,%5,%6,%7}, {%8,%9}, {%0,%1,%2,%3};" \
                 : "+f"((c)[0]), "+f"((c)[1]), "+f"((c)[2]), "+f"((c)[3]) \
                 : "r"((a)[0]), "r"((a)[1]), "r"((a)[2]), "r"((a)[3]), \
                   "r"(b0), "r"(b1))

// ---------------- fp32 -> fp16 convert (row per block) ---------------------
__global__ __launch_bounds__(256) void convert_kernel(
    const float* __restrict__ src, __half* __restrict__ dst, int cols)
{
    int r = blockIdx.x;
    const float* s = src + (size_t)r * cols;
    __half* d = dst + (size_t)r * cols;
    for (int c = threadIdx.x * 4; c < cols; c += 256 * 4) {
        float4 v = *(const float4*)(s + c);
        __half2 hA = __halves2half2(__float2half_rn(v.x), __float2half_rn(v.y));
        __half2 hB = __halves2half2(__float2half_rn(v.z), __float2half_rn(v.w));
        *(__half2*)(d + c)     = hA;
        *(__half2*)(d + c + 2) = hB;
    }
}

// ---------------- GEMM stage loader (cp.async, SW128) ----------------------
__device__ __forceinline__ void load_stage(
    uint32_t sb, const __half* Ab, const __half* Bb,
    int Kp, int it, int stage, int tid)
{
    uint32_t st = sb + stage * STAGE_B;
    int k0 = it * KBE;
#pragma unroll
    for (int i = 0; i < 6; i++) {
        int c = tid + i * 512;          // 0..3071
        uint32_t soff;
        const __half* g;
        if (c < 1024) {                 // A: 128 rows x 8 chunks
            int row = c >> 3, j = c & 7;
            soff = st + SWZ(row * 128 + j * 16);
            g = Ab + (size_t)row * Kp + k0 + j * 8;
        } else {                        // B: 256 rows x 8 chunks
            int cc = c - 1024;
            int row = cc >> 3, j = cc & 7;
            soff = st + A_TILE_B + SWZ(row * 128 + j * 16);
            g = Bb + (size_t)row * Kp + k0 + j * 8;
        }
        asm volatile("cp.async.cg.shared.global [%0], [%1], 16;"
                     :: "r"(soff), "l"(g) : "memory");
    }
}

// ---------------- HMMA fp16 GEMM: C[M,N] = A[M,Kp] @ B[N,Kp]^T -------------
__global__ __launch_bounds__(512, 1) void gemm_f16(
    const __half* __restrict__ A, const __half* __restrict__ B,
    float* __restrict__ C, int N, int Kp)
{
    extern __shared__ __align__(1024) char smem[];
    uint32_t sb = smem_u32(smem);
    int tid = threadIdx.x, wid = tid >> 5, lane = tid & 31;
    int wm = wid & 3, wn = wid >> 2;       // 4 warps in M, 4 in N
    int bx = blockIdx.x, by = blockIdx.y;
    const int niter = Kp / KBE;

    const __half* Ab = A + (size_t)(by * GBM) * Kp;
    const __half* Bb = B + (size_t)(bx * GBN) * Kp;

#pragma unroll
    for (int it = 0; it < STAGES - 1; it++) {
        load_stage(sb, Ab, Bb, Kp, it, it, tid);
        asm volatile("cp.async.commit_group;" ::: "memory");
    }

    float acc[2][8][4];
#pragma unroll
    for (int mi = 0; mi < 2; mi++)
#pragma unroll
        for (int nj = 0; nj < 8; nj++)
#pragma unroll
            for (int q = 0; q < 4; q++) acc[mi][nj][q] = 0.f;

    int gq = lane >> 3, rr = lane & 7;
    int kc = gq >> 1;
    uint32_t aRow[2]; int aXor[2];
#pragma unroll
    for (int mi = 0; mi < 2; mi++) {
        int m = wm * 32 + mi * 16 + (gq & 1) * 8 + rr;
        aRow[mi] = (uint32_t)(m * 128);
        aXor[mi] = m & 7;
    }
    uint32_t bRow[4]; int bXor[4];
#pragma unroll
    for (int ni = 0; ni < 4; ni++) {
        int n = wn * 64 + ni * 16 + (gq & 1) * 8 + rr;
        bRow[ni] = (uint32_t)(A_TILE_B + n * 128);
        bXor[ni] = n & 7;
    }

    int s = 0;
    for (int it = 0; it < niter; it++) {
        asm volatile("cp.async.wait_group %0;" :: "n"(STAGES - 2) : "memory");
        __syncthreads();
        int jt = it + STAGES - 1;
        if (jt < niter) {
            int sj = jt - (jt / STAGES) * STAGES;
            load_stage(sb, Ab, Bb, Kp, jt, sj, tid);
        }
        asm volatile("cp.async.commit_group;" ::: "memory");

        uint32_t stb = sb + s * STAGE_B;
        s++; if (s == STAGES) s = 0;
#pragma unroll
        for (int ks = 0; ks < 4; ks++) {
            uint32_t a[2][4];
#pragma unroll
            for (int mi = 0; mi < 2; mi++) {
                uint32_t ad = stb + aRow[mi]
                            + (uint32_t)((((ks << 1) + kc) ^ aXor[mi]) << 4);
                LDSM4(a[mi][0], a[mi][1], a[mi][2], a[mi][3], ad);
            }
            uint32_t b[4][4];
#pragma unroll
            for (int ni = 0; ni < 4; ni++) {
                uint32_t bd = stb + bRow[ni]
                            + (uint32_t)((((ks << 1) + kc) ^ bXor[ni]) << 4);
                LDSM4(b[ni][0], b[ni][1], b[ni][2], b[ni][3], bd);
            }
#pragma unroll
            for (int mi = 0; mi < 2; mi++)
#pragma unroll
                for (int ni = 0; ni < 4; ni++) {
                    MMA16816(acc[mi][ni * 2],     a[mi], b[ni][0], b[ni][2]);
                    MMA16816(acc[mi][ni * 2 + 1], a[mi], b[ni][1], b[ni][3]);
                }
        }
        __syncthreads();
    }

    int gid = lane >> 2, tig = lane & 3;
#pragma unroll
    for (int mi = 0; mi < 2; mi++) {
        int row = by * GBM + wm * 32 + mi * 16 + gid;
#pragma unroll
        for (int nj = 0; nj < 8; nj++) {
            float* p = C + (size_t)row * N + bx * GBN + wn * 64 + nj * 8 + tig * 2;
            *(float2*)p = make_float2(acc[mi][nj][0], acc[mi][nj][1]);
            *(float2*)(p + (size_t)8 * N) = make_float2(acc[mi][nj][2], acc[mi][nj][3]);
        }
    }
}

// ---------------- K1: gate -------------------------------------------------
__global__ __launch_bounds__(256) void gate_kernel(
    const float* __restrict__ x, const float* __restrict__ Wg)
{
    int t = blockIdx.x;
    int tid = threadIdx.x;
    int w = tid >> 5, lane = tid & 31;
    const float* xr = x + (size_t)t * Hn;
    const float* wr = Wg + (size_t)w * Hn;
    float s = 0.f;
    for (int h = lane * 4; h < Hn; h += 32 * 4) {
        float4 xv = *(const float4*)(xr + h);
        float4 wv = *(const float4*)(wr + h);
        s += xv.x * wv.x + xv.y * wv.y + xv.z * wv.z + xv.w * wv.w;
    }
    s = warp_sum(s);
    __shared__ float logits[En];
    if (lane == 0) logits[w] = s;
    __syncthreads();
    if (tid == 0) {
        int i0 = 0; float l0 = logits[0];
#pragma unroll
        for (int e = 1; e < En; e++) if (logits[e] > l0) { l0 = logits[e]; i0 = e; }
        int i1 = -1; float l1 = -3.0e38f;
#pragma unroll
        for (int e = 0; e < En; e++) if (e != i0 && logits[e] > l1) { l1 = logits[e]; i1 = e; }
        float r0 = 1.f / (1.f + expf(l1 - l0));
        g_sel[t * 2 + 0] = i0;
        g_sel[t * 2 + 1] = i1;
        g_rw [t * 2 + 0] = r0;
        g_rw [t * 2 + 1] = 1.f - r0;
    }
}

// ---------------- expert grouping ------------------------------------------
__global__ __launch_bounds__(256) void hist_kernel()
{
    __shared__ int hc[En];
    int tid = threadIdx.x;
    if (tid < En) hc[tid] = 0;
    __syncthreads();
    for (int i = tid; i < Tn * Kn; i += 256)
        atomicAdd(&hc[g_sel[i]], 1);
    __syncthreads();
    if (tid == 0) {
        int off = 0;
        for (int e = 0; e < En; e++) {
            g_off[e] = off;
            g_cur[e] = off;
            off += hc[e];
        }
        g_off[En] = off;
    }
}

__global__ __launch_bounds__(256) void scatter_kernel()
{
    int i = blockIdx.x * 256 + threadIdx.x;
    if (i < Tn * Kn) {
        int e = g_sel[i];
        int pos = atomicAdd(&g_cur[e], 1);
        g_list[pos] = i;
    }
}

// -------- grouped a1/a3 (CH=8 entries; float4 inner loop) ------------------
#define CHA 8
#define PAD 132
__global__ __launch_bounds__(256) void a13_grouped(
    const float* __restrict__ x, const float* __restrict__ A1,
    const float* __restrict__ A3)
{
    int e, start, nent;
    if (!find_chunk(blockIdx.x, CHA, e, start, nent)) return;
    __shared__ float xs[CHA][PAD];
    __shared__ float as[64][PAD];
    __shared__ int ids[CHA];
    int tid = threadIdx.x;
    if (tid < CHA)
        ids[tid] = (tid < nent) ? g_list[start + tid] : g_list[start];
    __syncthreads();

    int entry = tid >> 5, rg = tid & 31;
    float acc0 = 0.f, acc1 = 0.f;
    int myid = ids[entry];

    for (int h0 = 0; h0 < Hn; h0 += 128) {
#pragma unroll
        for (int i = 0; i < 4; i++) {
            int q = tid + i * 256;
            int row = q >> 7, col = q & 127;
            xs[row][col] = x[(size_t)(ids[row] >> 1) * Hn + h0 + col];
        }
#pragma unroll
        for (int i = 0; i < 32; i++) {
            int q = tid + i * 256;
            int row = q >> 7, col = q & 127;
            const float* src = (row < 32)
                ? A1 + ((size_t)(e * Rn + row) * Hn + h0 + col)
                : A3 + ((size_t)(e * Rn + row - 32) * Hn + h0 + col);
            as[row][col] = *src;
        }
        __syncthreads();
#pragma unroll
        for (int h = 0; h < 128; h += 4) {
            float4 xv = *(const float4*)&xs[entry][h];
            float4 a0 = *(const float4*)&as[rg][h];
            float4 a1 = *(const float4*)&as[rg + 32][h];
            acc0 += xv.x * a0.x + xv.y * a0.y + xv.z * a0.z + xv.w * a0.w;
            acc1 += xv.x * a1.x + xv.y * a1.y + xv.z * a1.z + xv.w * a1.w;
        }
        __syncthreads();
    }
    if (entry < nent) {
        g_a1[(size_t)myid * Rn + rg] = acc0;
        g_a3[(size_t)myid * Rn + rg] = acc1;
    }
}

// -------- grouped fuse (CH=32), writes fp16 per-slot x2 --------------------
#define CHF 32
__global__ __launch_bounds__(256) void fuse_grouped(
    const float* __restrict__ B1, const float* __restrict__ B3)
{
    int e, start, nent;
    if (!find_chunk(blockIdx.x, CHF, e, start, nent)) return;
    __shared__ float a1s[CHF][Rn];
    __shared__ float a3s[CHF][Rn];
    __shared__ int ids[CHF];
    int tid = threadIdx.x;
    if (tid < CHF)
        ids[tid] = (tid < nent) ? g_list[start + tid] : g_list[start];
    __syncthreads();
#pragma unroll
    for (int i = 0; i < 4; i++) {
        int q = tid + i * 256;
        int en = q >> 5, r = q & 31;
        int id = ids[en];
        a1s[en][r] = g_a1[(size_t)id * Rn + r];
        a3s[en][r] = g_a3[(size_t)id * Rn + r];
    }
    __syncthreads();

    for (int f0 = 0; f0 < Fn; f0 += 256) {
        int f = f0 + tid;
        float b1r[Rn], b3r[Rn];
        const float4* p1 = (const float4*)(B1 + ((size_t)e * Fn + f) * Rn);
        const float4* p3 = (const float4*)(B3 + ((size_t)e * Fn + f) * Rn);
#pragma unroll
        for (int q = 0; q < 8; q++) {
            float4 v1 = p1[q], v3 = p3[q];
            b1r[q * 4 + 0] = v1.x; b1r[q * 4 + 1] = v1.y;
            b1r[q * 4 + 2] = v1.z; b1r[q * 4 + 3] = v1.w;
            b3r[q * 4 + 0] = v3.x; b3r[q * 4 + 1] = v3.y;
            b3r[q * 4 + 2] = v3.z; b3r[q * 4 + 3] = v3.w;
        }
        for (int en = 0; en < nent; en++) {
            int id = ids[en];
            int t = id >> 1, kk = id & 1;
            float l1 = 0.f, l3 = 0.f;
#pragma unroll
            for (int r = 0; r < Rn; r++) {
                l1 += b1r[r] * a1s[en][r];
                l3 += b3r[r] * a3s[en][r];
            }
            float x1 = g_base1[(size_t)t * Fn + f] + l1;
            float x3 = g_base3[(size_t)t * Fn + f] + l3;
            float sig = 1.f / (1.f + expf(-x1));
            float x2 = x1 * sig * x3;
            (kk ? g_x2k1 : g_x2k0)[(size_t)t * Fn + f] = __float2half_rn(x2);
        }
    }
}

// -------- combine weighted x2 -> fp16 (half inputs) ------------------------
__global__ __launch_bounds__(256) void combine_x2()
{
    int t = blockIdx.x;
    float w0 = g_rw[t * 2], w1 = g_rw[t * 2 + 1];
    __half* d = g_x2s + (size_t)t * Fn;
    const __half* s0 = g_x2k0 + (size_t)t * Fn;
    const __half* s1 = g_x2k1 + (size_t)t * Fn;
    for (int f = threadIdx.x * 2; f < Fn; f += 256 * 2) {
        float2 v0 = __half22float2(*(const __half2*)(s0 + f));
        float2 v1 = __half22float2(*(const __half2*)(s1 + f));
        *(__half2*)(d + f) = __halves2half2(
            __float2half_rn(w0 * v0.x + w1 * v1.x),
            __float2half_rn(w0 * v0.y + w1 * v1.y));
    }
}

// -------- grouped a2 (CH=32; half x2 input, float4 inner loop) -------------
#define CH2 32
__global__ __launch_bounds__(256) void a2_grouped(const float* __restrict__ A2)
{
    int e, start, nent;
    if (!find_chunk(blockIdx.x, CH2, e, start, nent)) return;
    __shared__ float xs[CH2][PAD];
    __shared__ float as[Rn][PAD];
    __shared__ int ids[CH2];
    int tid = threadIdx.x;
    if (tid < CH2)
        ids[tid] = (tid < nent) ? g_list[start + tid] : g_list[start];
    __syncthreads();

    int entry = tid >> 3, rg = tid & 7;
    float acc[4] = {0.f, 0.f, 0.f, 0.f};
    int myid = ids[entry];

    for (int f0 = 0; f0 < Fn; f0 += 128) {
        // x2 tile: 32 rows x 128 cols, loaded as half2 (2048 chunks)
#pragma unroll
        for (int i = 0; i < 8; i++) {
            int q = tid + i * 256;
            int row = q >> 6, c2 = q & 63;
            int id = ids[row];
            const __half* src = (id & 1) ? g_x2k1 : g_x2k0;
            float2 fv = __half22float2(
                *(const __half2*)(src + (size_t)(id >> 1) * Fn + f0 + 2 * c2));
            xs[row][2 * c2]     = fv.x;
            xs[row][2 * c2 + 1] = fv.y;
        }
#pragma unroll
        for (int i = 0; i < 16; i++) {
            int q = tid + i * 256;
            int row = q >> 7, col = q & 127;
            as[row][col] = A2[(size_t)(e * Rn + row) * Fn + f0 + col];
        }
        __syncthreads();
#pragma unroll
        for (int h = 0; h < 128; h += 4) {
            float4 xv = *(const float4*)&xs[entry][h];
#pragma unroll
            for (int j = 0; j < 4; j++) {
                float4 av = *(const float4*)&as[rg + 8 * j][h];
                acc[j] += xv.x * av.x + xv.y * av.y + xv.z * av.z + xv.w * av.w;
            }
        }
        __syncthreads();
    }
    if (entry < nent) {
#pragma unroll
        for (int j = 0; j < 4; j++)
            g_a2[(size_t)myid * Rn + rg + 8 * j] = acc[j];
    }
}

// -------- grouped final (CH=64) --------------------------------------------
#define CHL 64
__global__ __launch_bounds__(256) void final_grouped(const float* __restrict__ B2)
{
    int e, start, nent;
    if (!find_chunk(blockIdx.x, CHL, e, start, nent)) return;
    __shared__ float a2s[CHL][Rn];
    __shared__ float ws[CHL];
    __shared__ int ids[CHL];
    int tid = threadIdx.x;
    if (tid < CHL) {
        int id = (tid < nent) ? g_list[start + tid] : g_list[start];
        ids[tid] = id;
        ws[tid] = g_rw[id];
    }
    __syncthreads();
#pragma unroll
    for (int i = 0; i < 8; i++) {
        int q = tid + i * 256;
        int en = q >> 5, r = q & 31;
        a2s[en][r] = g_a2[(size_t)ids[en] * Rn + r];
    }
    __syncthreads();

    for (int h0 = 0; h0 < Hn; h0 += 256) {
        int h = h0 + tid;
        float b2r[Rn];
        const float4* p2 = (const float4*)(B2 + ((size_t)e * Hn + h) * Rn);
#pragma unroll
        for (int q = 0; q < 8; q++) {
            float4 v = p2[q];
            b2r[q * 4 + 0] = v.x; b2r[q * 4 + 1] = v.y;
            b2r[q * 4 + 2] = v.z; b2r[q * 4 + 3] = v.w;
        }
        for (int en = 0; en < nent; en++) {
            int id = ids[en];
            int t = id >> 1, kk = id & 1;
            float l2 = 0.f;
#pragma unroll
            for (int r = 0; r < Rn; r++) l2 += b2r[r] * a2s[en][r];
            (kk ? g_l2k1 : g_l2k0)[(size_t)t * Hn + h] = ws[en] * l2;
        }
    }
}

// -------- add lora2 contributions into out ---------------------------------
__global__ __launch_bounds__(256) void add_out(float* __restrict__ out)
{
    int i = (blockIdx.x * 256 + threadIdx.x) * 4;
    float4 o = *(float4*)(out + i);
    float4 a = *(const float4*)(g_l2k0 + i);
    float4 b = *(const float4*)(g_l2k1 + i);
    o.x += a.x + b.x; o.y += a.y + b.y;
    o.z += a.z + b.z; o.w += a.w + b.w;
    *(float4*)(out + i) = o;
}

// ---------------------------------------------------------------------------
extern "C" void kernel_launch(void* const* d_in, const int* in_sizes, int n_in,
                              void* d_out, int out_size)
{
    (void)in_sizes; (void)n_in; (void)out_size;
    const float* x  = (const float*)d_in[0];
    const float* Wg = (const float*)d_in[1];
    const float* W1 = (const float*)d_in[2];
    const float* W2 = (const float*)d_in[3];
    const float* W3 = (const float*)d_in[4];
    const float* A1 = (const float*)d_in[5];
    const float* B1 = (const float*)d_in[6];
    const float* A2 = (const float*)d_in[7];
    const float* B2 = (const float*)d_in[8];
    const float* A3 = (const float*)d_in[9];
    const float* B3 = (const float*)d_in[10];
    float* out = (float*)d_out;

    float *base1, *base3;
    __half *xs, *w1s, *w3s, *w2s, *x2s;
    cudaGetSymbolAddress((void**)&base1, g_base1);
    cudaGetSymbolAddress((void**)&base3, g_base3);
    cudaGetSymbolAddress((void**)&xs,  g_xs);
    cudaGetSymbolAddress((void**)&w1s, g_w1s);
    cudaGetSymbolAddress((void**)&w3s, g_w3s);
    cudaGetSymbolAddress((void**)&w2s, g_w2s);
    cudaGetSymbolAddress((void**)&x2s, g_x2s);

    cudaFuncSetAttribute(gemm_f16, cudaFuncAttributeMaxDynamicSharedMemorySize,
                         SMEM_TOTAL);

    static cudaStream_t s1 = nullptr, s2 = nullptr;
    static cudaEvent_t evA = nullptr, ev1 = nullptr, ev2 = nullptr,
                       ev3 = nullptr, ev4 = nullptr;
    if (s1 == nullptr) {
        cudaStreamCreateWithFlags(&s1, cudaStreamNonBlocking);
        cudaStreamCreateWithFlags(&s2, cudaStreamNonBlocking);
        cudaEventCreateWithFlags(&evA, cudaEventDisableTiming);
        cudaEventCreateWithFlags(&ev1, cudaEventDisableTiming);
        cudaEventCreateWithFlags(&ev2, cudaEventDisableTiming);
        cudaEventCreateWithFlags(&ev3, cudaEventDisableTiming);
        cudaEventCreateWithFlags(&ev4, cudaEventDisableTiming);
    }

    // root fork
    cudaEventRecord(evA, 0);
    cudaStreamWaitEvent(s1, evA, 0);
    cudaStreamWaitEvent(s2, evA, 0);

    // s1: gate chain + a13 (independent of converts/GEMMs)
    gate_kernel<<<Tn, 256, 0, s1>>>(x, Wg);
    hist_kernel<<<1, 256, 0, s1>>>();
    scatter_kernel<<<(Tn * Kn + 255) / 256, 256, 0, s1>>>();
    a13_grouped<<<Tn * Kn / CHA + En, 256, 0, s1>>>(x, A1, A3);
    cudaEventRecord(ev1, s1);

    // s2: W2 convert (needed only by down GEMM)
    convert_kernel<<<Hn, 256, 0, s2>>>(W2, w2s, Fn);
    cudaEventRecord(ev4, s2);

    // main: converts + base GEMMs
    convert_kernel<<<Tn, 256>>>(x,  xs,  Hn);
    convert_kernel<<<Fn, 256>>>(W1, w1s, Hn);
    convert_kernel<<<Fn, 256>>>(W3, w3s, Hn);
    gemm_f16<<<dim3(Fn / GBN, Tn / GBM), 512, SMEM_TOTAL>>>(xs, w1s, base1, Fn, Hn);
    gemm_f16<<<dim3(Fn / GBN, Tn / GBM), 512, SMEM_TOTAL>>>(xs, w3s, base3, Fn, Hn);

    // join s1 chain before fuse
    cudaStreamWaitEvent(0, ev1, 0);
    fuse_grouped<<<Tn * Kn / CHF + En, 256>>>(B1, B3);

    // fork: a2 + final on s2 concurrent with combine + down GEMM
    cudaEventRecord(ev2, 0);
    cudaStreamWaitEvent(s2, ev2, 0);
    a2_grouped<<<Tn * Kn / CH2 + En, 256, 0, s2>>>(A2);
    final_grouped<<<Tn * Kn / CHL + En, 256, 0, s2>>>(B2);
    cudaEventRecord(ev3, s2);

    combine_x2<<<Tn, 256>>>();
    cudaStreamWaitEvent(0, ev4, 0);    // W2 fp16 ready
    gemm_f16<<<dim3(Hn / GBN, Tn / GBM), 512, SMEM_TOTAL>>>(x2s, w2s, out, Hn, Fn);

    // join lora2 path, then final add
    cudaStreamWaitEvent(0, ev3, 0);
    add_out<<<Tn * Hn / 1024, 256>>>(out);
}

// round 12
// speedup vs baseline: 1.4581x; 1.0252x over previous
#include <cuda_runtime.h>
#include <cuda_fp16.h>
#include <math.h>
#include <stdint.h>

// Problem dims
#define Tn 2048   // tokens = B*S
#define Hn 2048   // hidden
#define Fn 7168   // ffn
#define En 8      // experts
#define Rn 32     // lora rank
#define Kn 2      // top-k

// HMMA GEMM tiling: 128x256, 512 threads, 4 stages
#define GBM 128
#define GBN 256
#define KBE 64                     // fp16 K elems per stage = 128B rows (SW128)
#define STAGES 4
#define A_TILE_B (GBM * 128)       // 16384
#define B_TILE_B (GBN * 128)       // 32768
#define STAGE_B  (A_TILE_B + B_TILE_B)       // 49152
#define SMEM_TOTAL (STAGES * STAGE_B)        // 196608

#define SWZ(o) ((o) ^ (((o) >> 3) & 0x70))

// ---------------- scratch (device globals) ---------------------------------
__device__ __align__(256) __half g_base13[Tn * 2 * Fn];  // [base1 | base3] fp16
__device__ __align__(256) __half g_x2k0[Tn * Fn];        // per-slot x2 (fp16)
__device__ __align__(256) __half g_x2k1[Tn * Fn];
__device__ __align__(256) float g_l2k0[Tn * Hn];
__device__ __align__(256) float g_l2k1[Tn * Hn];
__device__ __align__(256) __half g_xs  [Tn * Hn];        // x fp16
__device__ __align__(256) __half g_w13s[2 * Fn * Hn];    // [W1; W3] fp16
__device__ __align__(256) __half g_w2s [Hn * Fn];        // W2 fp16
__device__ __align__(256) __half g_x2s [Tn * Fn];        // weighted x2 fp16
__device__ int   g_sel[Tn * Kn];
__device__ float g_rw [Tn * Kn];
__device__ float g_a1 [Tn * Kn * Rn];
__device__ float g_a3 [Tn * Kn * Rn];
__device__ float g_a2 [Tn * Kn * Rn];
// expert grouping
__device__ int g_off [En + 1];
__device__ int g_cur [En];
__device__ int g_list[Tn * Kn];

// ---------------- helpers ---------------------------------------------------
__device__ __forceinline__ uint32_t smem_u32(const void* p) {
    uint32_t a;
    asm("{ .reg .u64 t; cvta.to.shared.u64 t, %1; cvt.u32.u64 %0, t; }"
        : "=r"(a) : "l"(p));
    return a;
}

__device__ __forceinline__ float warp_sum(float v) {
#pragma unroll
    for (int o = 16; o; o >>= 1) v += __shfl_xor_sync(0xffffffffu, v, o);
    return v;
}

__device__ __forceinline__ bool find_chunk(int b, int CH, int& e, int& start,
                                           int& nent) {
    int acc = 0;
    for (int ee = 0; ee < En; ee++) {
        int o0 = g_off[ee], o1 = g_off[ee + 1];
        int cnt = o1 - o0;
        int nch = (cnt + CH - 1) / CH;
        if (b < acc + nch) {
            e = ee;
            start = o0 + (b - acc) * CH;
            nent = min(CH, o1 - start);
            return true;
        }
        acc += nch;
    }
    return false;
}

#define LDSM4(r0, r1, r2, r3, addr) \
    asm volatile("ldmatrix.sync.aligned.m8n8.x4.shared.b16 {%0,%1,%2,%3}, [%4];" \
                 : "=r"(r0), "=r"(r1), "=r"(r2), "=r"(r3) : "r"(addr))

#define MMA16816(c, a, b0, b1) \
    asm volatile("mma.sync.aligned.m16n8k16.row.col.f32.f16.f16.f32 " \
                 "{%0,%1,%2,%3}, {%4,%5,%6,%7}, {%8,%9}, {%0,%1,%2,%3};" \
                 : "+f"((c)[0]), "+f"((c)[1]), "+f"((c)[2]), "+f"((c)[3]) \
                 : "r"((a)[0]), "r"((a)[1]), "r"((a)[2]), "r"((a)[3]), \
                   "r"(b0), "r"(b1))

// ---------------- fp32 -> fp16 convert (row per block) ---------------------
__global__ __launch_bounds__(256) void convert_kernel(
    const float* __restrict__ src, __half* __restrict__ dst, int cols)
{
    int r = blockIdx.x;
    const float* s = src + (size_t)r * cols;
    __half* d = dst + (size_t)r * cols;
    for (int c = threadIdx.x * 4; c < cols; c += 256 * 4) {
        float4 v = *(const float4*)(s + c);
        __half2 hA = __halves2half2(__float2half_rn(v.x), __float2half_rn(v.y));
        __half2 hB = __halves2half2(__float2half_rn(v.z), __float2half_rn(v.w));
        *(__half2*)(d + c)     = hA;
        *(__half2*)(d + c + 2) = hB;
    }
}

// ---------------- GEMM stage loader (cp.async, SW128) ----------------------
__device__ __forceinline__ void load_stage(
    uint32_t sb, const __half* Ab, const __half* Bb,
    int Kp, int it, int stage, int tid)
{
    uint32_t st = sb + stage * STAGE_B;
    int k0 = it * KBE;
#pragma unroll
    for (int i = 0; i < 6; i++) {
        int c = tid + i * 512;          // 0..3071
        uint32_t soff;
        const __half* g;
        if (c < 1024) {                 // A: 128 rows x 8 chunks
            int row = c >> 3, j = c & 7;
            soff = st + SWZ(row * 128 + j * 16);
            g = Ab + (size_t)row * Kp + k0 + j * 8;
        } else {                        // B: 256 rows x 8 chunks
            int cc = c - 1024;
            int row = cc >> 3, j = cc & 7;
            soff = st + A_TILE_B + SWZ(row * 128 + j * 16);
            g = Bb + (size_t)row * Kp + k0 + j * 8;
        }
        asm volatile("cp.async.cg.shared.global [%0], [%1], 16;"
                     :: "r"(soff), "l"(g) : "memory");
    }
}

// ---------------- HMMA fp16 GEMM: C[M,N] = A[M,Kp] @ B[N,Kp]^T -------------
// half_out=1: C is __half*; half_out=0: C is float*
__global__ __launch_bounds__(512, 1) void gemm_f16(
    const __half* __restrict__ A, const __half* __restrict__ B,
    void* __restrict__ C, int N, int Kp, int half_out)
{
    extern __shared__ __align__(1024) char smem[];
    uint32_t sb = smem_u32(smem);
    int tid = threadIdx.x, wid = tid >> 5, lane = tid & 31;
    int wm = wid & 3, wn = wid >> 2;       // 4 warps in M, 4 in N
    int bx = blockIdx.x, by = blockIdx.y;
    const int niter = Kp / KBE;

    const __half* Ab = A + (size_t)(by * GBM) * Kp;
    const __half* Bb = B + (size_t)(bx * GBN) * Kp;

#pragma unroll
    for (int it = 0; it < STAGES - 1; it++) {
        load_stage(sb, Ab, Bb, Kp, it, it, tid);
        asm volatile("cp.async.commit_group;" ::: "memory");
    }

    float acc[2][8][4];
#pragma unroll
    for (int mi = 0; mi < 2; mi++)
#pragma unroll
        for (int nj = 0; nj < 8; nj++)
#pragma unroll
            for (int q = 0; q < 4; q++) acc[mi][nj][q] = 0.f;

    int gq = lane >> 3, rr = lane & 7;
    int kc = gq >> 1;
    uint32_t aRow[2]; int aXor[2];
#pragma unroll
    for (int mi = 0; mi < 2; mi++) {
        int m = wm * 32 + mi * 16 + (gq & 1) * 8 + rr;
        aRow[mi] = (uint32_t)(m * 128);
        aXor[mi] = m & 7;
    }
    uint32_t bRow[4]; int bXor[4];
#pragma unroll
    for (int ni = 0; ni < 4; ni++) {
        int n = wn * 64 + ni * 16 + (gq & 1) * 8 + rr;
        bRow[ni] = (uint32_t)(A_TILE_B + n * 128);
        bXor[ni] = n & 7;
    }

    int s = 0;
    for (int it = 0; it < niter; it++) {
        asm volatile("cp.async.wait_group %0;" :: "n"(STAGES - 2) : "memory");
        __syncthreads();
        int jt = it + STAGES - 1;
        if (jt < niter) {
            int sj = jt - (jt / STAGES) * STAGES;
            load_stage(sb, Ab, Bb, Kp, jt, sj, tid);
        }
        asm volatile("cp.async.commit_group;" ::: "memory");

        uint32_t stb = sb + s * STAGE_B;
        s++; if (s == STAGES) s = 0;
#pragma unroll
        for (int ks = 0; ks < 4; ks++) {
            uint32_t a[2][4];
#pragma unroll
            for (int mi = 0; mi < 2; mi++) {
                uint32_t ad = stb + aRow[mi]
                            + (uint32_t)((((ks << 1) + kc) ^ aXor[mi]) << 4);
                LDSM4(a[mi][0], a[mi][1], a[mi][2], a[mi][3], ad);
            }
            uint32_t b[4][4];
#pragma unroll
            for (int ni = 0; ni < 4; ni++) {
                uint32_t bd = stb + bRow[ni]
                            + (uint32_t)((((ks << 1) + kc) ^ bXor[ni]) << 4);
                LDSM4(b[ni][0], b[ni][1], b[ni][2], b[ni][3], bd);
            }
#pragma unroll
            for (int mi = 0; mi < 2; mi++)
#pragma unroll
                for (int ni = 0; ni < 4; ni++) {
                    MMA16816(acc[mi][ni * 2],     a[mi], b[ni][0], b[ni][2]);
                    MMA16816(acc[mi][ni * 2 + 1], a[mi], b[ni][1], b[ni][3]);
                }
        }
        __syncthreads();
    }

    int gid = lane >> 2, tig = lane & 3;
    if (half_out) {
        __half* Ch = (__half*)C;
#pragma unroll
        for (int mi = 0; mi < 2; mi++) {
            int row = by * GBM + wm * 32 + mi * 16 + gid;
#pragma unroll
            for (int nj = 0; nj < 8; nj++) {
                __half* p = Ch + (size_t)row * N + bx * GBN + wn * 64 + nj * 8 + tig * 2;
                *(__half2*)p = __halves2half2(__float2half_rn(acc[mi][nj][0]),
                                              __float2half_rn(acc[mi][nj][1]));
                *(__half2*)(p + (size_t)8 * N) =
                    __halves2half2(__float2half_rn(acc[mi][nj][2]),
                                   __float2half_rn(acc[mi][nj][3]));
            }
        }
    } else {
        float* Cf = (float*)C;
#pragma unroll
        for (int mi = 0; mi < 2; mi++) {
            int row = by * GBM + wm * 32 + mi * 16 + gid;
#pragma unroll
            for (int nj = 0; nj < 8; nj++) {
                float* p = Cf + (size_t)row * N + bx * GBN + wn * 64 + nj * 8 + tig * 2;
                *(float2*)p = make_float2(acc[mi][nj][0], acc[mi][nj][1]);
                *(float2*)(p + (size_t)8 * N) = make_float2(acc[mi][nj][2], acc[mi][nj][3]);
            }
        }
    }
}

// ---------------- K1: gate -------------------------------------------------
__global__ __launch_bounds__(256) void gate_kernel(
    const float* __restrict__ x, const float* __restrict__ Wg)
{
    int t = blockIdx.x;
    int tid = threadIdx.x;
    int w = tid >> 5, lane = tid & 31;
    const float* xr = x + (size_t)t * Hn;
    const float* wr = Wg + (size_t)w * Hn;
    float s = 0.f;
    for (int h = lane * 4; h < Hn; h += 32 * 4) {
        float4 xv = *(const float4*)(xr + h);
        float4 wv = *(const float4*)(wr + h);
        s += xv.x * wv.x + xv.y * wv.y + xv.z * wv.z + xv.w * wv.w;
    }
    s = warp_sum(s);
    __shared__ float logits[En];
    if (lane == 0) logits[w] = s;
    __syncthreads();
    if (tid == 0) {
        int i0 = 0; float l0 = logits[0];
#pragma unroll
        for (int e = 1; e < En; e++) if (logits[e] > l0) { l0 = logits[e]; i0 = e; }
        int i1 = -1; float l1 = -3.0e38f;
#pragma unroll
        for (int e = 0; e < En; e++) if (e != i0 && logits[e] > l1) { l1 = logits[e]; i1 = e; }
        float r0 = 1.f / (1.f + expf(l1 - l0));
        g_sel[t * 2 + 0] = i0;
        g_sel[t * 2 + 1] = i1;
        g_rw [t * 2 + 0] = r0;
        g_rw [t * 2 + 1] = 1.f - r0;
    }
}

// ---------------- expert grouping ------------------------------------------
__global__ __launch_bounds__(256) void hist_kernel()
{
    __shared__ int hc[En];
    int tid = threadIdx.x;
    if (tid < En) hc[tid] = 0;
    __syncthreads();
    for (int i = tid; i < Tn * Kn; i += 256)
        atomicAdd(&hc[g_sel[i]], 1);
    __syncthreads();
    if (tid == 0) {
        int off = 0;
        for (int e = 0; e < En; e++) {
            g_off[e] = off;
            g_cur[e] = off;
            off += hc[e];
        }
        g_off[En] = off;
    }
}

__global__ __launch_bounds__(256) void scatter_kernel()
{
    int i = blockIdx.x * 256 + threadIdx.x;
    if (i < Tn * Kn) {
        int e = g_sel[i];
        int pos = atomicAdd(&g_cur[e], 1);
        g_list[pos] = i;
    }
}

// -------- grouped a1/a3 (CH=8 entries; float4 inner loop) ------------------
#define CHA 8
#define PAD 132
__global__ __launch_bounds__(256) void a13_grouped(
    const float* __restrict__ x, const float* __restrict__ A1,
    const float* __restrict__ A3)
{
    int e, start, nent;
    if (!find_chunk(blockIdx.x, CHA, e, start, nent)) return;
    __shared__ float xs[CHA][PAD];
    __shared__ float as[64][PAD];
    __shared__ int ids[CHA];
    int tid = threadIdx.x;
    if (tid < CHA)
        ids[tid] = (tid < nent) ? g_list[start + tid] : g_list[start];
    __syncthreads();

    int entry = tid >> 5, rg = tid & 31;
    float acc0 = 0.f, acc1 = 0.f;
    int myid = ids[entry];

    for (int h0 = 0; h0 < Hn; h0 += 128) {
#pragma unroll
        for (int i = 0; i < 4; i++) {
            int q = tid + i * 256;
            int row = q >> 7, col = q & 127;
            xs[row][col] = x[(size_t)(ids[row] >> 1) * Hn + h0 + col];
        }
#pragma unroll
        for (int i = 0; i < 32; i++) {
            int q = tid + i * 256;
            int row = q >> 7, col = q & 127;
            const float* src = (row < 32)
                ? A1 + ((size_t)(e * Rn + row) * Hn + h0 + col)
                : A3 + ((size_t)(e * Rn + row - 32) * Hn + h0 + col);
            as[row][col] = *src;
        }
        __syncthreads();
#pragma unroll
        for (int h = 0; h < 128; h += 4) {
            float4 xv = *(const float4*)&xs[entry][h];
            float4 a0 = *(const float4*)&as[rg][h];
            float4 a1 = *(const float4*)&as[rg + 32][h];
            acc0 += xv.x * a0.x + xv.y * a0.y + xv.z * a0.z + xv.w * a0.w;
            acc1 += xv.x * a1.x + xv.y * a1.y + xv.z * a1.z + xv.w * a1.w;
        }
        __syncthreads();
    }
    if (entry < nent) {
        g_a1[(size_t)myid * Rn + rg] = acc0;
        g_a3[(size_t)myid * Rn + rg] = acc1;
    }
}

// -------- grouped fuse (CH=32), reads fp16 base13, writes fp16 x2 ----------
#define CHF 32
__global__ __launch_bounds__(256) void fuse_grouped(
    const float* __restrict__ B1, const float* __restrict__ B3)
{
    int e, start, nent;
    if (!find_chunk(blockIdx.x, CHF, e, start, nent)) return;
    __shared__ float a1s[CHF][Rn];
    __shared__ float a3s[CHF][Rn];
    __shared__ int ids[CHF];
    int tid = threadIdx.x;
    if (tid < CHF)
        ids[tid] = (tid < nent) ? g_list[start + tid] : g_list[start];
    __syncthreads();
#pragma unroll
    for (int i = 0; i < 4; i++) {
        int q = tid + i * 256;
        int en = q >> 5, r = q & 31;
        int id = ids[en];
        a1s[en][r] = g_a1[(size_t)id * Rn + r];
        a3s[en][r] = g_a3[(size_t)id * Rn + r];
    }
    __syncthreads();

    for (int f0 = 0; f0 < Fn; f0 += 256) {
        int f = f0 + tid;
        float b1r[Rn], b3r[Rn];
        const float4* p1 = (const float4*)(B1 + ((size_t)e * Fn + f) * Rn);
        const float4* p3 = (const float4*)(B3 + ((size_t)e * Fn + f) * Rn);
#pragma unroll
        for (int q = 0; q < 8; q++) {
            float4 v1 = p1[q], v3 = p3[q];
            b1r[q * 4 + 0] = v1.x; b1r[q * 4 + 1] = v1.y;
            b1r[q * 4 + 2] = v1.z; b1r[q * 4 + 3] = v1.w;
            b3r[q * 4 + 0] = v3.x; b3r[q * 4 + 1] = v3.y;
            b3r[q * 4 + 2] = v3.z; b3r[q * 4 + 3] = v3.w;
        }
        for (int en = 0; en < nent; en++) {
            int id = ids[en];
            int t = id >> 1, kk = id & 1;
            float l1 = 0.f, l3 = 0.f;
#pragma unroll
            for (int r = 0; r < Rn; r++) {
                l1 += b1r[r] * a1s[en][r];
                l3 += b3r[r] * a3s[en][r];
            }
            const __half* b13 = g_base13 + (size_t)t * (2 * Fn);
            float x1 = __half2float(b13[f]) + l1;
            float x3 = __half2float(b13[Fn + f]) + l3;
            float sig = 1.f / (1.f + expf(-x1));
            float x2 = x1 * sig * x3;
            (kk ? g_x2k1 : g_x2k0)[(size_t)t * Fn + f] = __float2half_rn(x2);
        }
    }
}

// -------- combine weighted x2 -> fp16 (half inputs) ------------------------
__global__ __launch_bounds__(256) void combine_x2()
{
    int t = blockIdx.x;
    float w0 = g_rw[t * 2], w1 = g_rw[t * 2 + 1];
    __half* d = g_x2s + (size_t)t * Fn;
    const __half* s0 = g_x2k0 + (size_t)t * Fn;
    const __half* s1 = g_x2k1 + (size_t)t * Fn;
    for (int f = threadIdx.x * 2; f < Fn; f += 256 * 2) {
        float2 v0 = __half22float2(*(const __half2*)(s0 + f));
        float2 v1 = __half22float2(*(const __half2*)(s1 + f));
        *(__half2*)(d + f) = __halves2half2(
            __float2half_rn(w0 * v0.x + w1 * v1.x),
            __float2half_rn(w0 * v0.y + w1 * v1.y));
    }
}

// -------- grouped a2 (CH=32; half x2 input, float4 inner loop) -------------
#define CH2 32
__global__ __launch_bounds__(256) void a2_grouped(const float* __restrict__ A2)
{
    int e, start, nent;
    if (!find_chunk(blockIdx.x, CH2, e, start, nent)) return;
    __shared__ float xs[CH2][PAD];
    __shared__ float as[Rn][PAD];
    __shared__ int ids[CH2];
    int tid = threadIdx.x;
    if (tid < CH2)
        ids[tid] = (tid < nent) ? g_list[start + tid] : g_list[start];
    __syncthreads();

    int entry = tid >> 3, rg = tid & 7;
    float acc[4] = {0.f, 0.f, 0.f, 0.f};
    int myid = ids[entry];

    for (int f0 = 0; f0 < Fn; f0 += 128) {
#pragma unroll
        for (int i = 0; i < 8; i++) {
            int q = tid + i * 256;
            int row = q >> 6, c2 = q & 63;
            int id = ids[row];
            const __half* src = (id & 1) ? g_x2k1 : g_x2k0;
            float2 fv = __half22float2(
                *(const __half2*)(src + (size_t)(id >> 1) * Fn + f0 + 2 * c2));
            xs[row][2 * c2]     = fv.x;
            xs[row][2 * c2 + 1] = fv.y;
        }
#pragma unroll
        for (int i = 0; i < 16; i++) {
            int q = tid + i * 256;
            int row = q >> 7, col = q & 127;
            as[row][col] = A2[(size_t)(e * Rn + row) * Fn + f0 + col];
        }
        __syncthreads();
#pragma unroll
        for (int h = 0; h < 128; h += 4) {
            float4 xv = *(const float4*)&xs[entry][h];
#pragma unroll
            for (int j = 0; j < 4; j++) {
                float4 av = *(const float4*)&as[rg + 8 * j][h];
                acc[j] += xv.x * av.x + xv.y * av.y + xv.z * av.z + xv.w * av.w;
            }
        }
        __syncthreads();
    }
    if (entry < nent) {
#pragma unroll
        for (int j = 0; j < 4; j++)
            g_a2[(size_t)myid * Rn + rg + 8 * j] = acc[j];
    }
}

// -------- grouped final (CH=64) --------------------------------------------
#define CHL 64
__global__ __launch_bounds__(256) void final_grouped(const float* __restrict__ B2)
{
    int e, start, nent;
    if (!find_chunk(blockIdx.x, CHL, e, start, nent)) return;
    __shared__ float a2s[CHL][Rn];
    __shared__ float ws[CHL];
    __shared__ int ids[CHL];
    int tid = threadIdx.x;
    if (tid < CHL) {
        int id = (tid < nent) ? g_list[start + tid] : g_list[start];
        ids[tid] = id;
        ws[tid] = g_rw[id];
    }
    __syncthreads();
#pragma unroll
    for (int i = 0; i < 8; i++) {
        int q = tid + i * 256;
        int en = q >> 5, r = q & 31;
        a2s[en][r] = g_a2[(size_t)ids[en] * Rn + r];
    }
    __syncthreads();

    for (int h0 = 0; h0 < Hn; h0 += 256) {
        int h = h0 + tid;
        float b2r[Rn];
        const float4* p2 = (const float4*)(B2 + ((size_t)e * Hn + h) * Rn);
#pragma unroll
        for (int q = 0; q < 8; q++) {
            float4 v = p2[q];
            b2r[q * 4 + 0] = v.x; b2r[q * 4 + 1] = v.y;
            b2r[q * 4 + 2] = v.z; b2r[q * 4 + 3] = v.w;
        }
        for (int en = 0; en < nent; en++) {
            int id = ids[en];
            int t = id >> 1, kk = id & 1;
            float l2 = 0.f;
#pragma unroll
            for (int r = 0; r < Rn; r++) l2 += b2r[r] * a2s[en][r];
            (kk ? g_l2k1 : g_l2k0)[(size_t)t * Hn + h] = ws[en] * l2;
        }
    }
}

// -------- add lora2 contributions into out ---------------------------------
__global__ __launch_bounds__(256) void add_out(float* __restrict__ out)
{
    int i = (blockIdx.x * 256 + threadIdx.x) * 4;
    float4 o = *(float4*)(out + i);
    float4 a = *(const float4*)(g_l2k0 + i);
    float4 b = *(const float4*)(g_l2k1 + i);
    o.x += a.x + b.x; o.y += a.y + b.y;
    o.z += a.z + b.z; o.w += a.w + b.w;
    *(float4*)(out + i) = o;
}

// ---------------------------------------------------------------------------
extern "C" void kernel_launch(void* const* d_in, const int* in_sizes, int n_in,
                              void* d_out, int out_size)
{
    (void)in_sizes; (void)n_in; (void)out_size;
    const float* x  = (const float*)d_in[0];
    const float* Wg = (const float*)d_in[1];
    const float* W1 = (const float*)d_in[2];
    const float* W2 = (const float*)d_in[3];
    const float* W3 = (const float*)d_in[4];
    const float* A1 = (const float*)d_in[5];
    const float* B1 = (const float*)d_in[6];
    const float* A2 = (const float*)d_in[7];
    const float* B2 = (const float*)d_in[8];
    const float* A3 = (const float*)d_in[9];
    const float* B3 = (const float*)d_in[10];
    float* out = (float*)d_out;

    __half *xs, *w13s, *w2s, *x2s, *base13;
    cudaGetSymbolAddress((void**)&base13, g_base13);
    cudaGetSymbolAddress((void**)&xs,   g_xs);
    cudaGetSymbolAddress((void**)&w13s, g_w13s);
    cudaGetSymbolAddress((void**)&w2s,  g_w2s);
    cudaGetSymbolAddress((void**)&x2s,  g_x2s);

    cudaFuncSetAttribute(gemm_f16, cudaFuncAttributeMaxDynamicSharedMemorySize,
                         SMEM_TOTAL);

    static cudaStream_t s1 = nullptr, s2 = nullptr;
    static cudaEvent_t evA = nullptr, ev1 = nullptr, ev2 = nullptr,
                       ev3 = nullptr, ev4 = nullptr;
    if (s1 == nullptr) {
        cudaStreamCreateWithFlags(&s1, cudaStreamNonBlocking);
        cudaStreamCreateWithFlags(&s2, cudaStreamNonBlocking);
        cudaEventCreateWithFlags(&evA, cudaEventDisableTiming);
        cudaEventCreateWithFlags(&ev1, cudaEventDisableTiming);
        cudaEventCreateWithFlags(&ev2, cudaEventDisableTiming);
        cudaEventCreateWithFlags(&ev3, cudaEventDisableTiming);
        cudaEventCreateWithFlags(&ev4, cudaEventDisableTiming);
    }

    // root fork
    cudaEventRecord(evA, 0);
    cudaStreamWaitEvent(s1, evA, 0);
    cudaStreamWaitEvent(s2, evA, 0);

    // s1: gate chain + a13 (independent of converts/GEMMs)
    gate_kernel<<<Tn, 256, 0, s1>>>(x, Wg);
    hist_kernel<<<1, 256, 0, s1>>>();
    scatter_kernel<<<(Tn * Kn + 255) / 256, 256, 0, s1>>>();
    a13_grouped<<<Tn * Kn / CHA + En, 256, 0, s1>>>(x, A1, A3);
    cudaEventRecord(ev1, s1);

    // s2: W2 convert (needed only by down GEMM)
    convert_kernel<<<Hn, 256, 0, s2>>>(W2, w2s, Fn);
    cudaEventRecord(ev4, s2);

    // main: converts + merged base GEMM (N = 2*Fn, fp16 output)
    convert_kernel<<<Tn, 256>>>(x,  xs,  Hn);
    convert_kernel<<<Fn, 256>>>(W1, w13s, Hn);
    convert_kernel<<<Fn, 256>>>(W3, w13s + (size_t)Fn * Hn, Hn);
    gemm_f16<<<dim3(2 * Fn / GBN, Tn / GBM), 512, SMEM_TOTAL>>>(
        xs, w13s, base13, 2 * Fn, Hn, 1);

    // join s1 chain before fuse
    cudaStreamWaitEvent(0, ev1, 0);
    fuse_grouped<<<Tn * Kn / CHF + En, 256>>>(B1, B3);

    // fork: a2 + final on s2 concurrent with combine + down GEMM
    cudaEventRecord(ev2, 0);
    cudaStreamWaitEvent(s2, ev2, 0);
    a2_grouped<<<Tn * Kn / CH2 + En, 256, 0, s2>>>(A2);
    final_grouped<<<Tn * Kn / CHL + En, 256, 0, s2>>>(B2);
    cudaEventRecord(ev3, s2);

    combine_x2<<<Tn, 256>>>();
    cudaStreamWaitEvent(0, ev4, 0);    // W2 fp16 ready
    gemm_f16<<<dim3(Hn / GBN, Tn / GBM), 512, SMEM_TOTAL>>>(
        x2s, w2s, out, Hn, Fn, 0);

    // join lora2 path, then final add
    cudaStreamWaitEvent(0, ev3, 0);
    add_out<<<Tn * Hn / 1024, 256>>>(out);
}

// round 13
// speedup vs baseline: 1.9492x; 1.3368x over previous
#include <cuda_runtime.h>
#include <cuda_fp16.h>
#include <math.h>
#include <stdint.h>

// Problem dims
#define Tn 2048   // tokens = B*S
#define Hn 2048   // hidden
#define Fn 7168   // ffn
#define En 8      // experts
#define Rn 32     // lora rank
#define Kn 2      // top-k

// HMMA GEMM tiling: 128x256, 512 threads, 4 stages
#define GBM 128
#define GBN 256
#define KBE 64                     // fp16 K elems per stage = 128B rows (SW128)
#define STAGES 4
#define A_TILE_B (GBM * 128)       // 16384
#define B_TILE_B (GBN * 128)       // 32768
#define STAGE_B  (A_TILE_B + B_TILE_B)       // 49152
#define SMEM_TOTAL (STAGES * STAGE_B)        // 196608

#define SWZ(o) ((o) ^ (((o) >> 3) & 0x70))

// ---------------- scratch (device globals) ---------------------------------
__device__ __align__(256) __half g_base13[Tn * 2 * Fn];  // [base1 | base3] fp16
__device__ __align__(256) __half g_x2k0[Tn * Fn];        // per-slot x2 (fp16)
__device__ __align__(256) __half g_x2k1[Tn * Fn];
__device__ __align__(256) float g_l2k0[Tn * Hn];
__device__ __align__(256) float g_l2k1[Tn * Hn];
__device__ __align__(256) __half g_xs  [Tn * Hn];        // x fp16
__device__ __align__(256) __half g_w13s[2 * Fn * Hn];    // [W1; W3] fp16
__device__ __align__(256) __half g_w2s [Hn * Fn];        // W2 fp16
__device__ __align__(256) __half g_x2s [Tn * Fn];        // weighted x2 fp16
__device__ int   g_sel[Tn * Kn];
__device__ float g_rw [Tn * Kn];
__device__ float g_a1 [Tn * Kn * Rn];
__device__ float g_a3 [Tn * Kn * Rn];
__device__ float g_a2 [Tn * Kn * Rn];
// expert grouping
__device__ int g_off [En + 1];
__device__ int g_cur [En];
__device__ int g_list[Tn * Kn];

// ---------------- helpers ---------------------------------------------------
__device__ __forceinline__ uint32_t smem_u32(const void* p) {
    uint32_t a;
    asm("{ .reg .u64 t; cvta.to.shared.u64 t, %1; cvt.u32.u64 %0, t; }"
        : "=r"(a) : "l"(p));
    return a;
}

__device__ __forceinline__ float warp_sum(float v) {
#pragma unroll
    for (int o = 16; o; o >>= 1) v += __shfl_xor_sync(0xffffffffu, v, o);
    return v;
}

__device__ __forceinline__ bool find_chunk(int b, int CH, int& e, int& start,
                                           int& nent) {
    int acc = 0;
    for (int ee = 0; ee < En; ee++) {
        int o0 = g_off[ee], o1 = g_off[ee + 1];
        int cnt = o1 - o0;
        int nch = (cnt + CH - 1) / CH;
        if (b < acc + nch) {
            e = ee;
            start = o0 + (b - acc) * CH;
            nent = min(CH, o1 - start);
            return true;
        }
        acc += nch;
    }
    return false;
}

#define LDSM4(r0, r1, r2, r3, addr) \
    asm volatile("ldmatrix.sync.aligned.m8n8.x4.shared.b16 {%0,%1,%2,%3}, [%4];" \
                 : "=r"(r0), "=r"(r1), "=r"(r2), "=r"(r3) : "r"(addr))

#define MMA16816(c, a, b0, b1) \
    asm volatile("mma.sync.aligned.m16n8k16.row.col.f32.f16.f16.f32 " \
                 "{%0,%1,%2,%3}, {%4,%5,%6,%7}, {%8,%9}, {%0,%1,%2,%3};" \
                 : "+f"((c)[0]), "+f"((c)[1]), "+f"((c)[2]), "+f"((c)[3]) \
                 : "r"((a)[0]), "r"((a)[1]), "r"((a)[2]), "r"((a)[3]), \
                   "r"(b0), "r"(b1))

// ---------------- fp32 -> fp16 convert (grid-stride, 8/thread) -------------
__global__ __launch_bounds__(256) void convert_kernel(
    const float* __restrict__ src, __half* __restrict__ dst, size_t n)
{
    for (size_t i = ((size_t)blockIdx.x * 256 + threadIdx.x) * 8; i < n;
         i += (size_t)gridDim.x * 256 * 8) {
        float4 v0 = *(const float4*)(src + i);
        float4 v1 = *(const float4*)(src + i + 4);
        *(__half2*)(dst + i)     = __halves2half2(__float2half_rn(v0.x), __float2half_rn(v0.y));
        *(__half2*)(dst + i + 2) = __halves2half2(__float2half_rn(v0.z), __float2half_rn(v0.w));
        *(__half2*)(dst + i + 4) = __halves2half2(__float2half_rn(v1.x), __float2half_rn(v1.y));
        *(__half2*)(dst + i + 6) = __halves2half2(__float2half_rn(v1.z), __float2half_rn(v1.w));
    }
}

// ---------------- GEMM stage loader (cp.async, SW128) ----------------------
__device__ __forceinline__ void load_stage(
    uint32_t sb, const __half* Ab, const __half* Bb,
    int Kp, int it, int stage, int tid)
{
    uint32_t st = sb + stage * STAGE_B;
    int k0 = it * KBE;
#pragma unroll
    for (int i = 0; i < 6; i++) {
        int c = tid + i * 512;          // 0..3071
        uint32_t soff;
        const __half* g;
        if (c < 1024) {                 // A: 128 rows x 8 chunks
            int row = c >> 3, j = c & 7;
            soff = st + SWZ(row * 128 + j * 16);
            g = Ab + (size_t)row * Kp + k0 + j * 8;
        } else {                        // B: 256 rows x 8 chunks
            int cc = c - 1024;
            int row = cc >> 3, j = cc & 7;
            soff = st + A_TILE_B + SWZ(row * 128 + j * 16);
            g = Bb + (size_t)row * Kp + k0 + j * 8;
        }
        asm volatile("cp.async.cg.shared.global [%0], [%1], 16;"
                     :: "r"(soff), "l"(g) : "memory");
    }
}

// ---------------- HMMA fp16 GEMM: C[M,N] = A[M,Kp] @ B[N,Kp]^T -------------
// half_out=1: C is __half*; half_out=0: C is float*
__global__ __launch_bounds__(512, 1) void gemm_f16(
    const __half* __restrict__ A, const __half* __restrict__ B,
    void* __restrict__ C, int N, int Kp, int half_out)
{
    extern __shared__ __align__(1024) char smem[];
    uint32_t sb = smem_u32(smem);
    int tid = threadIdx.x, wid = tid >> 5, lane = tid & 31;
    int wm = wid & 3, wn = wid >> 2;       // 4 warps in M, 4 in N
    int bx = blockIdx.x, by = blockIdx.y;
    const int niter = Kp / KBE;

    const __half* Ab = A + (size_t)(by * GBM) * Kp;
    const __half* Bb = B + (size_t)(bx * GBN) * Kp;

#pragma unroll
    for (int it = 0; it < STAGES - 1; it++) {
        load_stage(sb, Ab, Bb, Kp, it, it, tid);
        asm volatile("cp.async.commit_group;" ::: "memory");
    }

    float acc[2][8][4];
#pragma unroll
    for (int mi = 0; mi < 2; mi++)
#pragma unroll
        for (int nj = 0; nj < 8; nj++)
#pragma unroll
            for (int q = 0; q < 4; q++) acc[mi][nj][q] = 0.f;

    int gq = lane >> 3, rr = lane & 7;
    int kc = gq >> 1;
    uint32_t aRow[2]; int aXor[2];
#pragma unroll
    for (int mi = 0; mi < 2; mi++) {
        int m = wm * 32 + mi * 16 + (gq & 1) * 8 + rr;
        aRow[mi] = (uint32_t)(m * 128);
        aXor[mi] = m & 7;
    }
    uint32_t bRow[4]; int bXor[4];
#pragma unroll
    for (int ni = 0; ni < 4; ni++) {
        int n = wn * 64 + ni * 16 + (gq & 1) * 8 + rr;
        bRow[ni] = (uint32_t)(A_TILE_B + n * 128);
        bXor[ni] = n & 7;
    }

    int s = 0;
    for (int it = 0; it < niter; it++) {
        asm volatile("cp.async.wait_group %0;" :: "n"(STAGES - 2) : "memory");
        __syncthreads();
        int jt = it + STAGES - 1;
        if (jt < niter) {
            int sj = jt - (jt / STAGES) * STAGES;
            load_stage(sb, Ab, Bb, Kp, jt, sj, tid);
        }
        asm volatile("cp.async.commit_group;" ::: "memory");

        uint32_t stb = sb + s * STAGE_B;
        s++; if (s == STAGES) s = 0;
#pragma unroll
        for (int ks = 0; ks < 4; ks++) {
            uint32_t a[2][4];
#pragma unroll
            for (int mi = 0; mi < 2; mi++) {
                uint32_t ad = stb + aRow[mi]
                            + (uint32_t)((((ks << 1) + kc) ^ aXor[mi]) << 4);
                LDSM4(a[mi][0], a[mi][1], a[mi][2], a[mi][3], ad);
            }
            uint32_t b[4][4];
#pragma unroll
            for (int ni = 0; ni < 4; ni++) {
                uint32_t bd = stb + bRow[ni]
                            + (uint32_t)((((ks << 1) + kc) ^ bXor[ni]) << 4);
                LDSM4(b[ni][0], b[ni][1], b[ni][2], b[ni][3], bd);
            }
#pragma unroll
            for (int mi = 0; mi < 2; mi++)
#pragma unroll
                for (int ni = 0; ni < 4; ni++) {
                    MMA16816(acc[mi][ni * 2],     a[mi], b[ni][0], b[ni][2]);
                    MMA16816(acc[mi][ni * 2 + 1], a[mi], b[ni][1], b[ni][3]);
                }
        }
        __syncthreads();
    }

    int gid = lane >> 2, tig = lane & 3;
    if (half_out) {
        __half* Ch = (__half*)C;
#pragma unroll
        for (int mi = 0; mi < 2; mi++) {
            int row = by * GBM + wm * 32 + mi * 16 + gid;
#pragma unroll
            for (int nj = 0; nj < 8; nj++) {
                __half* p = Ch + (size_t)row * N + bx * GBN + wn * 64 + nj * 8 + tig * 2;
                *(__half2*)p = __halves2half2(__float2half_rn(acc[mi][nj][0]),
                                              __float2half_rn(acc[mi][nj][1]));
                *(__half2*)(p + (size_t)8 * N) =
                    __halves2half2(__float2half_rn(acc[mi][nj][2]),
                                   __float2half_rn(acc[mi][nj][3]));
            }
        }
    } else {
        float* Cf = (float*)C;
#pragma unroll
        for (int mi = 0; mi < 2; mi++) {
            int row = by * GBM + wm * 32 + mi * 16 + gid;
#pragma unroll
            for (int nj = 0; nj < 8; nj++) {
                float* p = Cf + (size_t)row * N + bx * GBN + wn * 64 + nj * 8 + tig * 2;
                *(float2*)p = make_float2(acc[mi][nj][0], acc[mi][nj][1]);
                *(float2*)(p + (size_t)8 * N) = make_float2(acc[mi][nj][2], acc[mi][nj][3]);
            }
        }
    }
}

// ---------------- K1: gate -------------------------------------------------
__global__ __launch_bounds__(256) void gate_kernel(
    const float* __restrict__ x, const float* __restrict__ Wg)
{
    int t = blockIdx.x;
    int tid = threadIdx.x;
    int w = tid >> 5, lane = tid & 31;
    const float* xr = x + (size_t)t * Hn;
    const float* wr = Wg + (size_t)w * Hn;
    float s = 0.f;
    for (int h = lane * 4; h < Hn; h += 32 * 4) {
        float4 xv = *(const float4*)(xr + h);
        float4 wv = *(const float4*)(wr + h);
        s += xv.x * wv.x + xv.y * wv.y + xv.z * wv.z + xv.w * wv.w;
    }
    s = warp_sum(s);
    __shared__ float logits[En];
    if (lane == 0) logits[w] = s;
    __syncthreads();
    if (tid == 0) {
        int i0 = 0; float l0 = logits[0];
#pragma unroll
        for (int e = 1; e < En; e++) if (logits[e] > l0) { l0 = logits[e]; i0 = e; }
        int i1 = -1; float l1 = -3.0e38f;
#pragma unroll
        for (int e = 0; e < En; e++) if (e != i0 && logits[e] > l1) { l1 = logits[e]; i1 = e; }
        float r0 = 1.f / (1.f + expf(l1 - l0));
        g_sel[t * 2 + 0] = i0;
        g_sel[t * 2 + 1] = i1;
        g_rw [t * 2 + 0] = r0;
        g_rw [t * 2 + 1] = 1.f - r0;
    }
}

// ---------------- expert grouping ------------------------------------------
__global__ __launch_bounds__(256) void hist_kernel()
{
    __shared__ int hc[En];
    int tid = threadIdx.x;
    if (tid < En) hc[tid] = 0;
    __syncthreads();
    for (int i = tid; i < Tn * Kn; i += 256)
        atomicAdd(&hc[g_sel[i]], 1);
    __syncthreads();
    if (tid == 0) {
        int off = 0;
        for (int e = 0; e < En; e++) {
            g_off[e] = off;
            g_cur[e] = off;
            off += hc[e];
        }
        g_off[En] = off;
    }
}

__global__ __launch_bounds__(256) void scatter_kernel()
{
    int i = blockIdx.x * 256 + threadIdx.x;
    if (i < Tn * Kn) {
        int e = g_sel[i];
        int pos = atomicAdd(&g_cur[e], 1);
        g_list[pos] = i;
    }
}

// -------- grouped a1/a3 (CH=4 entries; 4 x 64 threads) ---------------------
#define CHA 4
#define PAD 132
__global__ __launch_bounds__(256) void a13_grouped(
    const float* __restrict__ x, const float* __restrict__ A1,
    const float* __restrict__ A3)
{
    int e, start, nent;
    if (!find_chunk(blockIdx.x, CHA, e, start, nent)) return;
    __shared__ float xs[CHA][PAD];
    __shared__ float as[64][PAD];
    __shared__ int ids[CHA];
    int tid = threadIdx.x;
    if (tid < CHA)
        ids[tid] = (tid < nent) ? g_list[start + tid] : g_list[start];
    __syncthreads();

    int entry = tid >> 6, rg = tid & 63;    // 4 entries x 64 rows
    float acc = 0.f;
    int myid = ids[entry];

    for (int h0 = 0; h0 < Hn; h0 += 128) {
#pragma unroll
        for (int i = 0; i < 2; i++) {
            int q = tid + i * 256;
            int row = q >> 7, col = q & 127;
            xs[row][col] = x[(size_t)(ids[row] >> 1) * Hn + h0 + col];
        }
#pragma unroll
        for (int i = 0; i < 32; i++) {
            int q = tid + i * 256;
            int row = q >> 7, col = q & 127;
            const float* src = (row < 32)
                ? A1 + ((size_t)(e * Rn + row) * Hn + h0 + col)
                : A3 + ((size_t)(e * Rn + row - 32) * Hn + h0 + col);
            as[row][col] = *src;
        }
        __syncthreads();
#pragma unroll
        for (int h = 0; h < 128; h += 4) {
            float4 xv = *(const float4*)&xs[entry][h];
            float4 a0 = *(const float4*)&as[rg][h];
            acc += xv.x * a0.x + xv.y * a0.y + xv.z * a0.z + xv.w * a0.w;
        }
        __syncthreads();
    }
    if (entry < nent) {
        if (rg < 32) g_a1[(size_t)myid * Rn + rg] = acc;
        else         g_a3[(size_t)myid * Rn + rg - 32] = acc;
    }
}

// -------- grouped fuse (CH=16), reads fp16 base13, writes fp16 x2 ----------
#define CHF 16
__global__ __launch_bounds__(256) void fuse_grouped(
    const float* __restrict__ B1, const float* __restrict__ B3)
{
    int e, start, nent;
    if (!find_chunk(blockIdx.x, CHF, e, start, nent)) return;
    __shared__ float a1s[CHF][Rn];
    __shared__ float a3s[CHF][Rn];
    __shared__ int ids[CHF];
    int tid = threadIdx.x;
    if (tid < CHF)
        ids[tid] = (tid < nent) ? g_list[start + tid] : g_list[start];
    __syncthreads();
#pragma unroll
    for (int i = 0; i < 2; i++) {
        int q = tid + i * 256;
        int en = q >> 5, r = q & 31;
        int id = ids[en];
        a1s[en][r] = g_a1[(size_t)id * Rn + r];
        a3s[en][r] = g_a3[(size_t)id * Rn + r];
    }
    __syncthreads();

    for (int f0 = 0; f0 < Fn; f0 += 256) {
        int f = f0 + tid;
        float b1r[Rn], b3r[Rn];
        const float4* p1 = (const float4*)(B1 + ((size_t)e * Fn + f) * Rn);
        const float4* p3 = (const float4*)(B3 + ((size_t)e * Fn + f) * Rn);
#pragma unroll
        for (int q = 0; q < 8; q++) {
            float4 v1 = p1[q], v3 = p3[q];
            b1r[q * 4 + 0] = v1.x; b1r[q * 4 + 1] = v1.y;
            b1r[q * 4 + 2] = v1.z; b1r[q * 4 + 3] = v1.w;
            b3r[q * 4 + 0] = v3.x; b3r[q * 4 + 1] = v3.y;
            b3r[q * 4 + 2] = v3.z; b3r[q * 4 + 3] = v3.w;
        }
        for (int en = 0; en < nent; en++) {
            int id = ids[en];
            int t = id >> 1, kk = id & 1;
            float l1 = 0.f, l3 = 0.f;
#pragma unroll
            for (int r = 0; r < Rn; r++) {
                l1 += b1r[r] * a1s[en][r];
                l3 += b3r[r] * a3s[en][r];
            }
            const __half* b13 = g_base13 + (size_t)t * (2 * Fn);
            float x1 = __half2float(b13[f]) + l1;
            float x3 = __half2float(b13[Fn + f]) + l3;
            float sig = 1.f / (1.f + expf(-x1));
            float x2 = x1 * sig * x3;
            (kk ? g_x2k1 : g_x2k0)[(size_t)t * Fn + f] = __float2half_rn(x2);
        }
    }
}

// -------- combine weighted x2 -> fp16 (half inputs) ------------------------
__global__ __launch_bounds__(256) void combine_x2()
{
    int t = blockIdx.x;
    float w0 = g_rw[t * 2], w1 = g_rw[t * 2 + 1];
    __half* d = g_x2s + (size_t)t * Fn;
    const __half* s0 = g_x2k0 + (size_t)t * Fn;
    const __half* s1 = g_x2k1 + (size_t)t * Fn;
    for (int f = threadIdx.x * 2; f < Fn; f += 256 * 2) {
        float2 v0 = __half22float2(*(const __half2*)(s0 + f));
        float2 v1 = __half22float2(*(const __half2*)(s1 + f));
        *(__half2*)(d + f) = __halves2half2(
            __float2half_rn(w0 * v0.x + w1 * v1.x),
            __float2half_rn(w0 * v0.y + w1 * v1.y));
    }
}

// -------- grouped a2 (CH=16; 16 entries x 16 rg, 2 outputs each) -----------
#define CH2 16
__global__ __launch_bounds__(256) void a2_grouped(const float* __restrict__ A2)
{
    int e, start, nent;
    if (!find_chunk(blockIdx.x, CH2, e, start, nent)) return;
    __shared__ float xs[CH2][PAD];
    __shared__ float as[Rn][PAD];
    __shared__ int ids[CH2];
    int tid = threadIdx.x;
    if (tid < CH2)
        ids[tid] = (tid < nent) ? g_list[start + tid] : g_list[start];
    __syncthreads();

    int entry = tid >> 4, rg = tid & 15;
    float acc0 = 0.f, acc1 = 0.f;
    int myid = ids[entry];

    for (int f0 = 0; f0 < Fn; f0 += 128) {
        // x2 tile: 16 rows x 64 half2
#pragma unroll
        for (int i = 0; i < 4; i++) {
            int q = tid + i * 256;
            int row = q >> 6, c2 = q & 63;
            int id = ids[row];
            const __half* src = (id & 1) ? g_x2k1 : g_x2k0;
            float2 fv = __half22float2(
                *(const __half2*)(src + (size_t)(id >> 1) * Fn + f0 + 2 * c2));
            xs[row][2 * c2]     = fv.x;
            xs[row][2 * c2 + 1] = fv.y;
        }
#pragma unroll
        for (int i = 0; i < 16; i++) {
            int q = tid + i * 256;
            int row = q >> 7, col = q & 127;
            as[row][col] = A2[(size_t)(e * Rn + row) * Fn + f0 + col];
        }
        __syncthreads();
#pragma unroll
        for (int h = 0; h < 128; h += 4) {
            float4 xv = *(const float4*)&xs[entry][h];
            float4 a0 = *(const float4*)&as[rg][h];
            float4 a1 = *(const float4*)&as[rg + 16][h];
            acc0 += xv.x * a0.x + xv.y * a0.y + xv.z * a0.z + xv.w * a0.w;
            acc1 += xv.x * a1.x + xv.y * a1.y + xv.z * a1.z + xv.w * a1.w;
        }
        __syncthreads();
    }
    if (entry < nent) {
        g_a2[(size_t)myid * Rn + rg] = acc0;
        g_a2[(size_t)myid * Rn + rg + 16] = acc1;
    }
}

// -------- grouped final (CH=32) --------------------------------------------
#define CHL 32
__global__ __launch_bounds__(256) void final_grouped(const float* __restrict__ B2)
{
    int e, start, nent;
    if (!find_chunk(blockIdx.x, CHL, e, start, nent)) return;
    __shared__ float a2s[CHL][Rn];
    __shared__ float ws[CHL];
    __shared__ int ids[CHL];
    int tid = threadIdx.x;
    if (tid < CHL) {
        int id = (tid < nent) ? g_list[start + tid] : g_list[start];
        ids[tid] = id;
        ws[tid] = g_rw[id];
    }
    __syncthreads();
#pragma unroll
    for (int i = 0; i < 4; i++) {
        int q = tid + i * 256;
        int en = q >> 5, r = q & 31;
        a2s[en][r] = g_a2[(size_t)ids[en] * Rn + r];
    }
    __syncthreads();

    for (int h0 = 0; h0 < Hn; h0 += 256) {
        int h = h0 + tid;
        float b2r[Rn];
        const float4* p2 = (const float4*)(B2 + ((size_t)e * Hn + h) * Rn);
#pragma unroll
        for (int q = 0; q < 8; q++) {
            float4 v = p2[q];
            b2r[q * 4 + 0] = v.x; b2r[q * 4 + 1] = v.y;
            b2r[q * 4 + 2] = v.z; b2r[q * 4 + 3] = v.w;
        }
        for (int en = 0; en < nent; en++) {
            int id = ids[en];
            int t = id >> 1, kk = id & 1;
            float l2 = 0.f;
#pragma unroll
            for (int r = 0; r < Rn; r++) l2 += b2r[r] * a2s[en][r];
            (kk ? g_l2k1 : g_l2k0)[(size_t)t * Hn + h] = ws[en] * l2;
        }
    }
}

// -------- add lora2 contributions into out ---------------------------------
__global__ __launch_bounds__(256) void add_out(float* __restrict__ out)
{
    int i = (blockIdx.x * 256 + threadIdx.x) * 4;
    float4 o = *(float4*)(out + i);
    float4 a = *(const float4*)(g_l2k0 + i);
    float4 b = *(const float4*)(g_l2k1 + i);
    o.x += a.x + b.x; o.y += a.y + b.y;
    o.z += a.z + b.z; o.w += a.w + b.w;
    *(float4*)(out + i) = o;
}

// ---------------------------------------------------------------------------
extern "C" void kernel_launch(void* const* d_in, const int* in_sizes, int n_in,
                              void* d_out, int out_size)
{
    (void)in_sizes; (void)n_in; (void)out_size;
    const float* x  = (const float*)d_in[0];
    const float* Wg = (const float*)d_in[1];
    const float* W1 = (const float*)d_in[2];
    const float* W2 = (const float*)d_in[3];
    const float* W3 = (const float*)d_in[4];
    const float* A1 = (const float*)d_in[5];
    const float* B1 = (const float*)d_in[6];
    const float* A2 = (const float*)d_in[7];
    const float* B2 = (const float*)d_in[8];
    const float* A3 = (const float*)d_in[9];
    const float* B3 = (const float*)d_in[10];
    float* out = (float*)d_out;

    __half *xs, *w13s, *w2s, *x2s, *base13;
    cudaGetSymbolAddress((void**)&base13, g_base13);
    cudaGetSymbolAddress((void**)&xs,   g_xs);
    cudaGetSymbolAddress((void**)&w13s, g_w13s);
    cudaGetSymbolAddress((void**)&w2s,  g_w2s);
    cudaGetSymbolAddress((void**)&x2s,  g_x2s);

    cudaFuncSetAttribute(gemm_f16, cudaFuncAttributeMaxDynamicSharedMemorySize,
                         SMEM_TOTAL);

    static cudaStream_t s1 = nullptr, s2 = nullptr;
    static cudaEvent_t evA = nullptr, ev1 = nullptr, ev2 = nullptr,
                       ev3 = nullptr, ev4 = nullptr;
    if (s1 == nullptr) {
        cudaStreamCreateWithFlags(&s1, cudaStreamNonBlocking);
        cudaStreamCreateWithFlags(&s2, cudaStreamNonBlocking);
        cudaEventCreateWithFlags(&evA, cudaEventDisableTiming);
        cudaEventCreateWithFlags(&ev1, cudaEventDisableTiming);
        cudaEventCreateWithFlags(&ev2, cudaEventDisableTiming);
        cudaEventCreateWithFlags(&ev3, cudaEventDisableTiming);
        cudaEventCreateWithFlags(&ev4, cudaEventDisableTiming);
    }

    // root fork
    cudaEventRecord(evA, 0);
    cudaStreamWaitEvent(s1, evA, 0);
    cudaStreamWaitEvent(s2, evA, 0);

    // s1: gate chain + a13 (independent of converts/GEMMs)
    gate_kernel<<<Tn, 256, 0, s1>>>(x, Wg);
    hist_kernel<<<1, 256, 0, s1>>>();
    scatter_kernel<<<(Tn * Kn + 255) / 256, 256, 0, s1>>>();
    a13_grouped<<<Tn * Kn / CHA + En, 256, 0, s1>>>(x, A1, A3);
    cudaEventRecord(ev1, s1);

    // s2: W2 convert (needed only by down GEMM)
    convert_kernel<<<1024, 256, 0, s2>>>(W2, w2s, (size_t)Hn * Fn);
    cudaEventRecord(ev4, s2);

    // main: converts + merged base GEMM (N = 2*Fn, fp16 output)
    convert_kernel<<<512, 256>>>(x, xs, (size_t)Tn * Hn);
    convert_kernel<<<1024, 256>>>(W1, w13s, (size_t)Fn * Hn);
    convert_kernel<<<1024, 256>>>(W3, w13s + (size_t)Fn * Hn, (size_t)Fn * Hn);
    gemm_f16<<<dim3(2 * Fn / GBN, Tn / GBM), 512, SMEM_TOTAL>>>(
        xs, w13s, base13, 2 * Fn, Hn, 1);

    // join s1 chain before fuse
    cudaStreamWaitEvent(0, ev1, 0);
    fuse_grouped<<<Tn * Kn / CHF + En, 256>>>(B1, B3);

    // fork: a2 + final on s2 concurrent with combine + down GEMM
    cudaEventRecord(ev2, 0);
    cudaStreamWaitEvent(s2, ev2, 0);
    a2_grouped<<<Tn * Kn / CH2 + En, 256, 0, s2>>>(A2);
    final_grouped<<<Tn * Kn / CHL + En, 256, 0, s2>>>(B2);
    cudaEventRecord(ev3, s2);

    combine_x2<<<Tn, 256>>>();
    cudaStreamWaitEvent(0, ev4, 0);    // W2 fp16 ready
    gemm_f16<<<dim3(Hn / GBN, Tn / GBM), 512, SMEM_TOTAL>>>(
        x2s, w2s, out, Hn, Fn, 0);

    // join lora2 path, then final add
    cudaStreamWaitEvent(0, ev3, 0);
    add_out<<<Tn * Hn / 1024, 256>>>(out);
}

// round 14
// speedup vs baseline: 2.0426x; 1.0479x over previous
#include <cuda_runtime.h>
#include <cuda_fp16.h>
#include <math.h>
#include <stdint.h>

// Problem dims
#define Tn 2048   // tokens = B*S
#define Hn 2048   // hidden
#define Fn 7168   // ffn
#define En 8      // experts
#define Rn 32     // lora rank
#define Kn 2      // top-k

// HMMA GEMM tiling: 128x256, 512 threads, 4 stages
#define GBM 128
#define GBN 256
#define KBE 64                     // fp16 K elems per stage = 128B rows (SW128)
#define STAGES 4
#define A_TILE_B (GBM * 128)       // 16384
#define B_TILE_B (GBN * 128)       // 32768
#define STAGE_B  (A_TILE_B + B_TILE_B)       // 49152
#define SMEM_TOTAL (STAGES * STAGE_B)        // 196608

#define SWZ(o) ((o) ^ (((o) >> 3) & 0x70))

// ---------------- scratch (device globals) ---------------------------------
__device__ __align__(256) __half g_base13[Tn * 2 * Fn];  // [base1 | base3] fp16
__device__ __align__(256) __half g_x2k0[Tn * Fn];        // per-slot x2 (fp16)
__device__ __align__(256) __half g_x2k1[Tn * Fn];
__device__ __align__(256) float g_l2k0[Tn * Hn];
__device__ __align__(256) float g_l2k1[Tn * Hn];
__device__ __align__(256) __half g_xs  [Tn * Hn];        // x fp16
__device__ __align__(256) __half g_w13s[2 * Fn * Hn];    // [W1; W3] fp16
__device__ __align__(256) __half g_w2s [Hn * Fn];        // W2 fp16
__device__ __align__(256) __half g_x2s [Tn * Fn];        // weighted x2 fp16
__device__ int   g_sel[Tn * Kn];
__device__ float g_rw [Tn * Kn];
__device__ float g_a1 [Tn * Kn * Rn];
__device__ float g_a3 [Tn * Kn * Rn];
__device__ float g_a2 [Tn * Kn * Rn];
// expert grouping
__device__ int g_off [En + 1];
__device__ int g_cur [En];
__device__ int g_list[Tn * Kn];

// ---------------- helpers ---------------------------------------------------
__device__ __forceinline__ uint32_t smem_u32(const void* p) {
    uint32_t a;
    asm("{ .reg .u64 t; cvta.to.shared.u64 t, %1; cvt.u32.u64 %0, t; }"
        : "=r"(a) : "l"(p));
    return a;
}

__device__ __forceinline__ float warp_sum(float v) {
#pragma unroll
    for (int o = 16; o; o >>= 1) v += __shfl_xor_sync(0xffffffffu, v, o);
    return v;
}

__device__ __forceinline__ bool find_chunk(int b, int CH, int& e, int& start,
                                           int& nent) {
    int acc = 0;
    for (int ee = 0; ee < En; ee++) {
        int o0 = g_off[ee], o1 = g_off[ee + 1];
        int cnt = o1 - o0;
        int nch = (cnt + CH - 1) / CH;
        if (b < acc + nch) {
            e = ee;
            start = o0 + (b - acc) * CH;
            nent = min(CH, o1 - start);
            return true;
        }
        acc += nch;
    }
    return false;
}

#define LDSM4(r0, r1, r2, r3, addr) \
    asm volatile("ldmatrix.sync.aligned.m8n8.x4.shared.b16 {%0,%1,%2,%3}, [%4];" \
                 : "=r"(r0), "=r"(r1), "=r"(r2), "=r"(r3) : "r"(addr))

#define MMA16816(c, a, b0, b1) \
    asm volatile("mma.sync.aligned.m16n8k16.row.col.f32.f16.f16.f32 " \
                 "{%0,%1,%2,%3}, {%4,%5,%6,%7}, {%8,%9}, {%0,%1,%2,%3};" \
                 : "+f"((c)[0]), "+f"((c)[1]), "+f"((c)[2]), "+f"((c)[3]) \
                 : "r"((a)[0]), "r"((a)[1]), "r"((a)[2]), "r"((a)[3]), \
                   "r"(b0), "r"(b1))

// ---------------- fp32 -> fp16 convert (grid-stride, 8/thread) -------------
__global__ __launch_bounds__(256) void convert_kernel(
    const float* __restrict__ src, __half* __restrict__ dst, size_t n)
{
    for (size_t i = ((size_t)blockIdx.x * 256 + threadIdx.x) * 8; i < n;
         i += (size_t)gridDim.x * 256 * 8) {
        float4 v0 = *(const float4*)(src + i);
        float4 v1 = *(const float4*)(src + i + 4);
        *(__half2*)(dst + i)     = __halves2half2(__float2half_rn(v0.x), __float2half_rn(v0.y));
        *(__half2*)(dst + i + 2) = __halves2half2(__float2half_rn(v0.z), __float2half_rn(v0.w));
        *(__half2*)(dst + i + 4) = __halves2half2(__float2half_rn(v1.x), __float2half_rn(v1.y));
        *(__half2*)(dst + i + 6) = __halves2half2(__float2half_rn(v1.z), __float2half_rn(v1.w));
    }
}

// ---------------- GEMM stage loader (cp.async, SW128) ----------------------
__device__ __forceinline__ void load_stage(
    uint32_t sb, const __half* Ab, const __half* Bb,
    int Kp, int it, int stage, int tid)
{
    uint32_t st = sb + stage * STAGE_B;
    int k0 = it * KBE;
#pragma unroll
    for (int i = 0; i < 6; i++) {
        int c = tid + i * 512;          // 0..3071
        uint32_t soff;
        const __half* g;
        if (c < 1024) {                 // A: 128 rows x 8 chunks
            int row = c >> 3, j = c & 7;
            soff = st + SWZ(row * 128 + j * 16);
            g = Ab + (size_t)row * Kp + k0 + j * 8;
        } else {                        // B: 256 rows x 8 chunks
            int cc = c - 1024;
            int row = cc >> 3, j = cc & 7;
            soff = st + A_TILE_B + SWZ(row * 128 + j * 16);
            g = Bb + (size_t)row * Kp + k0 + j * 8;
        }
        asm volatile("cp.async.cg.shared.global [%0], [%1], 16;"
                     :: "r"(soff), "l"(g) : "memory");
    }
}

// ---------------- HMMA fp16 GEMM: C[M,N] = A[M,Kp] @ B[N,Kp]^T -------------
// half_out=1: C is __half*; half_out=0: C is float*
__global__ __launch_bounds__(512, 1) void gemm_f16(
    const __half* __restrict__ A, const __half* __restrict__ B,
    void* __restrict__ C, int N, int Kp, int half_out)
{
    extern __shared__ __align__(1024) char smem[];
    uint32_t sb = smem_u32(smem);
    int tid = threadIdx.x, wid = tid >> 5, lane = tid & 31;
    int wm = wid & 3, wn = wid >> 2;       // 4 warps in M, 4 in N
    int bx = blockIdx.x, by = blockIdx.y;
    const int niter = Kp / KBE;

    const __half* Ab = A + (size_t)(by * GBM) * Kp;
    const __half* Bb = B + (size_t)(bx * GBN) * Kp;

#pragma unroll
    for (int it = 0; it < STAGES - 1; it++) {
        load_stage(sb, Ab, Bb, Kp, it, it, tid);
        asm volatile("cp.async.commit_group;" ::: "memory");
    }

    float acc[2][8][4];
#pragma unroll
    for (int mi = 0; mi < 2; mi++)
#pragma unroll
        for (int nj = 0; nj < 8; nj++)
#pragma unroll
            for (int q = 0; q < 4; q++) acc[mi][nj][q] = 0.f;

    int gq = lane >> 3, rr = lane & 7;
    int kc = gq >> 1;
    uint32_t aRow[2]; int aXor[2];
#pragma unroll
    for (int mi = 0; mi < 2; mi++) {
        int m = wm * 32 + mi * 16 + (gq & 1) * 8 + rr;
        aRow[mi] = (uint32_t)(m * 128);
        aXor[mi] = m & 7;
    }
    uint32_t bRow[4]; int bXor[4];
#pragma unroll
    for (int ni = 0; ni < 4; ni++) {
        int n = wn * 64 + ni * 16 + (gq & 1) * 8 + rr;
        bRow[ni] = (uint32_t)(A_TILE_B + n * 128);
        bXor[ni] = n & 7;
    }

    int s = 0;
    for (int it = 0; it < niter; it++) {
        asm volatile("cp.async.wait_group %0;" :: "n"(STAGES - 2) : "memory");
        // single barrier per iter: all warps finished previous stage's compute
        // before anyone overwrites its buffer (loads are issued after this).
        __syncthreads();
        int jt = it + STAGES - 1;
        if (jt < niter) {
            int sj = jt - (jt / STAGES) * STAGES;
            load_stage(sb, Ab, Bb, Kp, jt, sj, tid);
        }
        asm volatile("cp.async.commit_group;" ::: "memory");

        uint32_t stb = sb + s * STAGE_B;
        s++; if (s == STAGES) s = 0;
#pragma unroll
        for (int ks = 0; ks < 4; ks++) {
            uint32_t a[2][4];
#pragma unroll
            for (int mi = 0; mi < 2; mi++) {
                uint32_t ad = stb + aRow[mi]
                            + (uint32_t)((((ks << 1) + kc) ^ aXor[mi]) << 4);
                LDSM4(a[mi][0], a[mi][1], a[mi][2], a[mi][3], ad);
            }
            uint32_t b[4][4];
#pragma unroll
            for (int ni = 0; ni < 4; ni++) {
                uint32_t bd = stb + bRow[ni]
                            + (uint32_t)((((ks << 1) + kc) ^ bXor[ni]) << 4);
                LDSM4(b[ni][0], b[ni][1], b[ni][2], b[ni][3], bd);
            }
#pragma unroll
            for (int mi = 0; mi < 2; mi++)
#pragma unroll
                for (int ni = 0; ni < 4; ni++) {
                    MMA16816(acc[mi][ni * 2],     a[mi], b[ni][0], b[ni][2]);
                    MMA16816(acc[mi][ni * 2 + 1], a[mi], b[ni][1], b[ni][3]);
                }
        }
    }

    int gid = lane >> 2, tig = lane & 3;
    if (half_out) {
        __half* Ch = (__half*)C;
#pragma unroll
        for (int mi = 0; mi < 2; mi++) {
            int row = by * GBM + wm * 32 + mi * 16 + gid;
#pragma unroll
            for (int nj = 0; nj < 8; nj++) {
                __half* p = Ch + (size_t)row * N + bx * GBN + wn * 64 + nj * 8 + tig * 2;
                *(__half2*)p = __halves2half2(__float2half_rn(acc[mi][nj][0]),
                                              __float2half_rn(acc[mi][nj][1]));
                *(__half2*)(p + (size_t)8 * N) =
                    __halves2half2(__float2half_rn(acc[mi][nj][2]),
                                   __float2half_rn(acc[mi][nj][3]));
            }
        }
    } else {
        float* Cf = (float*)C;
#pragma unroll
        for (int mi = 0; mi < 2; mi++) {
            int row = by * GBM + wm * 32 + mi * 16 + gid;
#pragma unroll
            for (int nj = 0; nj < 8; nj++) {
                float* p = Cf + (size_t)row * N + bx * GBN + wn * 64 + nj * 8 + tig * 2;
                *(float2*)p = make_float2(acc[mi][nj][0], acc[mi][nj][1]);
                *(float2*)(p + (size_t)8 * N) = make_float2(acc[mi][nj][2], acc[mi][nj][3]);
            }
        }
    }
}

// ---------------- K1: gate -------------------------------------------------
__global__ __launch_bounds__(256) void gate_kernel(
    const float* __restrict__ x, const float* __restrict__ Wg)
{
    int t = blockIdx.x;
    int tid = threadIdx.x;
    int w = tid >> 5, lane = tid & 31;
    const float* xr = x + (size_t)t * Hn;
    const float* wr = Wg + (size_t)w * Hn;
    float s = 0.f;
    for (int h = lane * 4; h < Hn; h += 32 * 4) {
        float4 xv = *(const float4*)(xr + h);
        float4 wv = *(const float4*)(wr + h);
        s += xv.x * wv.x + xv.y * wv.y + xv.z * wv.z + xv.w * wv.w;
    }
    s = warp_sum(s);
    __shared__ float logits[En];
    if (lane == 0) logits[w] = s;
    __syncthreads();
    if (tid == 0) {
        int i0 = 0; float l0 = logits[0];
#pragma unroll
        for (int e = 1; e < En; e++) if (logits[e] > l0) { l0 = logits[e]; i0 = e; }
        int i1 = -1; float l1 = -3.0e38f;
#pragma unroll
        for (int e = 0; e < En; e++) if (e != i0 && logits[e] > l1) { l1 = logits[e]; i1 = e; }
        float r0 = 1.f / (1.f + expf(l1 - l0));
        g_sel[t * 2 + 0] = i0;
        g_sel[t * 2 + 1] = i1;
        g_rw [t * 2 + 0] = r0;
        g_rw [t * 2 + 1] = 1.f - r0;
    }
}

// ---------------- expert grouping ------------------------------------------
__global__ __launch_bounds__(256) void hist_kernel()
{
    __shared__ int hc[En];
    int tid = threadIdx.x;
    if (tid < En) hc[tid] = 0;
    __syncthreads();
    for (int i = tid; i < Tn * Kn; i += 256)
        atomicAdd(&hc[g_sel[i]], 1);
    __syncthreads();
    if (tid == 0) {
        int off = 0;
        for (int e = 0; e < En; e++) {
            g_off[e] = off;
            g_cur[e] = off;
            off += hc[e];
        }
        g_off[En] = off;
    }
}

__global__ __launch_bounds__(256) void scatter_kernel()
{
    int i = blockIdx.x * 256 + threadIdx.x;
    if (i < Tn * Kn) {
        int e = g_sel[i];
        int pos = atomicAdd(&g_cur[e], 1);
        g_list[pos] = i;
    }
}

// -------- grouped a1/a3 (CH=8 entries; float4 inner loop) ------------------
#define CHA 8
#define PAD 132
__global__ __launch_bounds__(256) void a13_grouped(
    const float* __restrict__ x, const float* __restrict__ A1,
    const float* __restrict__ A3)
{
    int e, start, nent;
    if (!find_chunk(blockIdx.x, CHA, e, start, nent)) return;
    __shared__ float xs[CHA][PAD];
    __shared__ float as[64][PAD];
    __shared__ int ids[CHA];
    int tid = threadIdx.x;
    if (tid < CHA)
        ids[tid] = (tid < nent) ? g_list[start + tid] : g_list[start];
    __syncthreads();

    int entry = tid >> 5, rg = tid & 31;
    float acc0 = 0.f, acc1 = 0.f;
    int myid = ids[entry];

    for (int h0 = 0; h0 < Hn; h0 += 128) {
#pragma unroll
        for (int i = 0; i < 4; i++) {
            int q = tid + i * 256;
            int row = q >> 7, col = q & 127;
            xs[row][col] = x[(size_t)(ids[row] >> 1) * Hn + h0 + col];
        }
#pragma unroll
        for (int i = 0; i < 32; i++) {
            int q = tid + i * 256;
            int row = q >> 7, col = q & 127;
            const float* src = (row < 32)
                ? A1 + ((size_t)(e * Rn + row) * Hn + h0 + col)
                : A3 + ((size_t)(e * Rn + row - 32) * Hn + h0 + col);
            as[row][col] = *src;
        }
        __syncthreads();
#pragma unroll
        for (int h = 0; h < 128; h += 4) {
            float4 xv = *(const float4*)&xs[entry][h];
            float4 a0 = *(const float4*)&as[rg][h];
            float4 a1 = *(const float4*)&as[rg + 32][h];
            acc0 += xv.x * a0.x + xv.y * a0.y + xv.z * a0.z + xv.w * a0.w;
            acc1 += xv.x * a1.x + xv.y * a1.y + xv.z * a1.z + xv.w * a1.w;
        }
        __syncthreads();
    }
    if (entry < nent) {
        g_a1[(size_t)myid * Rn + rg] = acc0;
        g_a3[(size_t)myid * Rn + rg] = acc1;
    }
}

// -------- grouped fuse (CH=16), reads fp16 base13, writes fp16 x2 ----------
#define CHF 16
__global__ __launch_bounds__(256) void fuse_grouped(
    const float* __restrict__ B1, const float* __restrict__ B3)
{
    int e, start, nent;
    if (!find_chunk(blockIdx.x, CHF, e, start, nent)) return;
    __shared__ float a1s[CHF][Rn];
    __shared__ float a3s[CHF][Rn];
    __shared__ int ids[CHF];
    int tid = threadIdx.x;
    if (tid < CHF)
        ids[tid] = (tid < nent) ? g_list[start + tid] : g_list[start];
    __syncthreads();
#pragma unroll
    for (int i = 0; i < 2; i++) {
        int q = tid + i * 256;
        int en = q >> 5, r = q & 31;
        int id = ids[en];
        a1s[en][r] = g_a1[(size_t)id * Rn + r];
        a3s[en][r] = g_a3[(size_t)id * Rn + r];
    }
    __syncthreads();

    for (int f0 = 0; f0 < Fn; f0 += 256) {
        int f = f0 + tid;
        float b1r[Rn], b3r[Rn];
        const float4* p1 = (const float4*)(B1 + ((size_t)e * Fn + f) * Rn);
        const float4* p3 = (const float4*)(B3 + ((size_t)e * Fn + f) * Rn);
#pragma unroll
        for (int q = 0; q < 8; q++) {
            float4 v1 = p1[q], v3 = p3[q];
            b1r[q * 4 + 0] = v1.x; b1r[q * 4 + 1] = v1.y;
            b1r[q * 4 + 2] = v1.z; b1r[q * 4 + 3] = v1.w;
            b3r[q * 4 + 0] = v3.x; b3r[q * 4 + 1] = v3.y;
            b3r[q * 4 + 2] = v3.z; b3r[q * 4 + 3] = v3.w;
        }
        for (int en = 0; en < nent; en++) {
            int id = ids[en];
            int t = id >> 1, kk = id & 1;
            float l1 = 0.f, l3 = 0.f;
#pragma unroll
            for (int r = 0; r < Rn; r++) {
                l1 += b1r[r] * a1s[en][r];
                l3 += b3r[r] * a3s[en][r];
            }
            const __half* b13 = g_base13 + (size_t)t * (2 * Fn);
            float x1 = __half2float(b13[f]) + l1;
            float x3 = __half2float(b13[Fn + f]) + l3;
            float sig = 1.f / (1.f + expf(-x1));
            float x2 = x1 * sig * x3;
            (kk ? g_x2k1 : g_x2k0)[(size_t)t * Fn + f] = __float2half_rn(x2);
        }
    }
}

// -------- combine weighted x2 -> fp16 (half inputs) ------------------------
__global__ __launch_bounds__(256) void combine_x2()
{
    int t = blockIdx.x;
    float w0 = g_rw[t * 2], w1 = g_rw[t * 2 + 1];
    __half* d = g_x2s + (size_t)t * Fn;
    const __half* s0 = g_x2k0 + (size_t)t * Fn;
    const __half* s1 = g_x2k1 + (size_t)t * Fn;
    for (int f = threadIdx.x * 2; f < Fn; f += 256 * 2) {
        float2 v0 = __half22float2(*(const __half2*)(s0 + f));
        float2 v1 = __half22float2(*(const __half2*)(s1 + f));
        *(__half2*)(d + f) = __halves2half2(
            __float2half_rn(w0 * v0.x + w1 * v1.x),
            __float2half_rn(w0 * v0.y + w1 * v1.y));
    }
}

// -------- grouped a2 (CH=16; 16 entries x 16 rg, 2 outputs each) -----------
#define CH2 16
__global__ __launch_bounds__(256) void a2_grouped(const float* __restrict__ A2)
{
    int e, start, nent;
    if (!find_chunk(blockIdx.x, CH2, e, start, nent)) return;
    __shared__ float xs[CH2][PAD];
    __shared__ float as[Rn][PAD];
    __shared__ int ids[CH2];
    int tid = threadIdx.x;
    if (tid < CH2)
        ids[tid] = (tid < nent) ? g_list[start + tid] : g_list[start];
    __syncthreads();

    int entry = tid >> 4, rg = tid & 15;
    float acc0 = 0.f, acc1 = 0.f;
    int myid = ids[entry];

    for (int f0 = 0; f0 < Fn; f0 += 128) {
        // x2 tile: 16 rows x 64 half2
#pragma unroll
        for (int i = 0; i < 4; i++) {
            int q = tid + i * 256;
            int row = q >> 6, c2 = q & 63;
            int id = ids[row];
            const __half* src = (id & 1) ? g_x2k1 : g_x2k0;
            float2 fv = __half22float2(
                *(const __half2*)(src + (size_t)(id >> 1) * Fn + f0 + 2 * c2));
            xs[row][2 * c2]     = fv.x;
            xs[row][2 * c2 + 1] = fv.y;
        }
#pragma unroll
        for (int i = 0; i < 16; i++) {
            int q = tid + i * 256;
            int row = q >> 7, col = q & 127;
            as[row][col] = A2[(size_t)(e * Rn + row) * Fn + f0 + col];
        }
        __syncthreads();
#pragma unroll
        for (int h = 0; h < 128; h += 4) {
            float4 xv = *(const float4*)&xs[entry][h];
            float4 a0 = *(const float4*)&as[rg][h];
            float4 a1 = *(const float4*)&as[rg + 16][h];
            acc0 += xv.x * a0.x + xv.y * a0.y + xv.z * a0.z + xv.w * a0.w;
            acc1 += xv.x * a1.x + xv.y * a1.y + xv.z * a1.z + xv.w * a1.w;
        }
        __syncthreads();
    }
    if (entry < nent) {
        g_a2[(size_t)myid * Rn + rg] = acc0;
        g_a2[(size_t)myid * Rn + rg + 16] = acc1;
    }
}

// -------- grouped final (CH=32) --------------------------------------------
#define CHL 32
__global__ __launch_bounds__(256) void final_grouped(const float* __restrict__ B2)
{
    int e, start, nent;
    if (!find_chunk(blockIdx.x, CHL, e, start, nent)) return;
    __shared__ float a2s[CHL][Rn];
    __shared__ float ws[CHL];
    __shared__ int ids[CHL];
    int tid = threadIdx.x;
    if (tid < CHL) {
        int id = (tid < nent) ? g_list[start + tid] : g_list[start];
        ids[tid] = id;
        ws[tid] = g_rw[id];
    }
    __syncthreads();
#pragma unroll
    for (int i = 0; i < 4; i++) {
        int q = tid + i * 256;
        int en = q >> 5, r = q & 31;
        a2s[en][r] = g_a2[(size_t)ids[en] * Rn + r];
    }
    __syncthreads();

    for (int h0 = 0; h0 < Hn; h0 += 256) {
        int h = h0 + tid;
        float b2r[Rn];
        const float4* p2 = (const float4*)(B2 + ((size_t)e * Hn + h) * Rn);
#pragma unroll
        for (int q = 0; q < 8; q++) {
            float4 v = p2[q];
            b2r[q * 4 + 0] = v.x; b2r[q * 4 + 1] = v.y;
            b2r[q * 4 + 2] = v.z; b2r[q * 4 + 3] = v.w;
        }
        for (int en = 0; en < nent; en++) {
            int id = ids[en];
            int t = id >> 1, kk = id & 1;
            float l2 = 0.f;
#pragma unroll
            for (int r = 0; r < Rn; r++) l2 += b2r[r] * a2s[en][r];
            (kk ? g_l2k1 : g_l2k0)[(size_t)t * Hn + h] = ws[en] * l2;
        }
    }
}

// -------- add lora2 contributions into out ---------------------------------
__global__ __launch_bounds__(256) void add_out(float* __restrict__ out)
{
    int i = (blockIdx.x * 256 + threadIdx.x) * 4;
    float4 o = *(float4*)(out + i);
    float4 a = *(const float4*)(g_l2k0 + i);
    float4 b = *(const float4*)(g_l2k1 + i);
    o.x += a.x + b.x; o.y += a.y + b.y;
    o.z += a.z + b.z; o.w += a.w + b.w;
    *(float4*)(out + i) = o;
}

// ---------------------------------------------------------------------------
extern "C" void kernel_launch(void* const* d_in, const int* in_sizes, int n_in,
                              void* d_out, int out_size)
{
    (void)in_sizes; (void)n_in; (void)out_size;
    const float* x  = (const float*)d_in[0];
    const float* Wg = (const float*)d_in[1];
    const float* W1 = (const float*)d_in[2];
    const float* W2 = (const float*)d_in[3];
    const float* W3 = (const float*)d_in[4];
    const float* A1 = (const float*)d_in[5];
    const float* B1 = (const float*)d_in[6];
    const float* A2 = (const float*)d_in[7];
    const float* B2 = (const float*)d_in[8];
    const float* A3 = (const float*)d_in[9];
    const float* B3 = (const float*)d_in[10];
    float* out = (float*)d_out;

    __half *xs, *w13s, *w2s, *x2s, *base13;
    cudaGetSymbolAddress((void**)&base13, g_base13);
    cudaGetSymbolAddress((void**)&xs,   g_xs);
    cudaGetSymbolAddress((void**)&w13s, g_w13s);
    cudaGetSymbolAddress((void**)&w2s,  g_w2s);
    cudaGetSymbolAddress((void**)&x2s,  g_x2s);

    cudaFuncSetAttribute(gemm_f16, cudaFuncAttributeMaxDynamicSharedMemorySize,
                         SMEM_TOTAL);

    static cudaStream_t s1 = nullptr, s2 = nullptr;
    static cudaEvent_t evA = nullptr, ev1 = nullptr, ev2 = nullptr,
                       ev3 = nullptr, ev4 = nullptr;
    if (s1 == nullptr) {
        cudaStreamCreateWithFlags(&s1, cudaStreamNonBlocking);
        cudaStreamCreateWithFlags(&s2, cudaStreamNonBlocking);
        cudaEventCreateWithFlags(&evA, cudaEventDisableTiming);
        cudaEventCreateWithFlags(&ev1, cudaEventDisableTiming);
        cudaEventCreateWithFlags(&ev2, cudaEventDisableTiming);
        cudaEventCreateWithFlags(&ev3, cudaEventDisableTiming);
        cudaEventCreateWithFlags(&ev4, cudaEventDisableTiming);
    }

    // root fork
    cudaEventRecord(evA, 0);
    cudaStreamWaitEvent(s1, evA, 0);
    cudaStreamWaitEvent(s2, evA, 0);

    // s1: gate chain + a13 (independent of converts/GEMMs)
    gate_kernel<<<Tn, 256, 0, s1>>>(x, Wg);
    hist_kernel<<<1, 256, 0, s1>>>();
    scatter_kernel<<<(Tn * Kn + 255) / 256, 256, 0, s1>>>();
    a13_grouped<<<Tn * Kn / CHA + En, 256, 0, s1>>>(x, A1, A3);
    cudaEventRecord(ev1, s1);

    // s2: W2 convert (needed only by down GEMM)
    convert_kernel<<<1024, 256, 0, s2>>>(W2, w2s, (size_t)Hn * Fn);
    cudaEventRecord(ev4, s2);

    // main: converts + merged base GEMM (N = 2*Fn, fp16 output)
    convert_kernel<<<512, 256>>>(x, xs, (size_t)Tn * Hn);
    convert_kernel<<<1024, 256>>>(W1, w13s, (size_t)Fn * Hn);
    convert_kernel<<<1024, 256>>>(W3, w13s + (size_t)Fn * Hn, (size_t)Fn * Hn);
    gemm_f16<<<dim3(2 * Fn / GBN, Tn / GBM), 512, SMEM_TOTAL>>>(
        xs, w13s, base13, 2 * Fn, Hn, 1);

    // join s1 chain before fuse
    cudaStreamWaitEvent(0, ev1, 0);
    fuse_grouped<<<Tn * Kn / CHF + En, 256>>>(B1, B3);

    // fork: a2 + final on s2 concurrent with combine + down GEMM
    cudaEventRecord(ev2, 0);
    cudaStreamWaitEvent(s2, ev2, 0);
    a2_grouped<<<Tn * Kn / CH2 + En, 256, 0, s2>>>(A2);
    final_grouped<<<Tn * Kn / CHL + En, 256, 0, s2>>>(B2);
    cudaEventRecord(ev3, s2);

    combine_x2<<<Tn, 256>>>();
    cudaStreamWaitEvent(0, ev4, 0);    // W2 fp16 ready
    gemm_f16<<<dim3(Hn / GBN, Tn / GBM), 512, SMEM_TOTAL>>>(
        x2s, w2s, out, Hn, Fn, 0);

    // join lora2 path, then final add
    cudaStreamWaitEvent(0, ev3, 0);
    add_out<<<Tn * Hn / 1024, 256>>>(out);
}

// round 15
// speedup vs baseline: 2.1782x; 1.0664x over previous
#include <cuda_runtime.h>
#include <cuda_fp16.h>
#include <math.h>
#include <stdint.h>

// Problem dims
#define Tn 2048   // tokens = B*S
#define Hn 2048   // hidden
#define Fn 7168   // ffn
#define En 8      // experts
#define Rn 32     // lora rank
#define Kn 2      // top-k

// Extended base GEMM N: [W1 | W3 | A1_all | A3_all]
#define NEXT (2 * Fn + 2 * En * Rn)   // 14848 = 58 * 256

// HMMA GEMM tiling: 128x256, 512 threads, 4 stages
#define GBM 128
#define GBN 256
#define KBE 64                     // fp16 K elems per stage = 128B rows (SW128)
#define STAGES 4
#define A_TILE_B (GBM * 128)       // 16384
#define B_TILE_B (GBN * 128)       // 32768
#define STAGE_B  (A_TILE_B + B_TILE_B)       // 49152
#define SMEM_TOTAL (STAGES * STAGE_B)        // 196608

#define SWZ(o) ((o) ^ (((o) >> 3) & 0x70))

// ---------------- scratch (device globals) ---------------------------------
__device__ __align__(256) __half g_base13[Tn * NEXT];   // [b1|b3|a1_all|a3_all]
__device__ __align__(256) __half g_x2k0[Tn * Fn];       // per-slot x2 (fp16)
__device__ __align__(256) __half g_x2k1[Tn * Fn];
__device__ __align__(256) float g_l2k0[Tn * Hn];
__device__ __align__(256) float g_l2k1[Tn * Hn];
__device__ __align__(256) __half g_xs  [Tn * Hn];       // x fp16
__device__ __align__(256) __half g_w13s[NEXT * Hn];     // [W1;W3;A1;A3] fp16
__device__ __align__(256) __half g_w2s [Hn * Fn];       // W2 fp16
__device__ __align__(256) __half g_x2s [Tn * Fn];       // weighted x2 fp16
__device__ int   g_sel[Tn * Kn];
__device__ float g_rw [Tn * Kn];
__device__ float g_a2 [Tn * Kn * Rn];
// expert grouping
__device__ int g_off [En + 1];
__device__ int g_cur [En];
__device__ int g_list[Tn * Kn];

// ---------------- helpers ---------------------------------------------------
__device__ __forceinline__ uint32_t smem_u32(const void* p) {
    uint32_t a;
    asm("{ .reg .u64 t; cvta.to.shared.u64 t, %1; cvt.u32.u64 %0, t; }"
        : "=r"(a) : "l"(p));
    return a;
}

__device__ __forceinline__ float warp_sum(float v) {
#pragma unroll
    for (int o = 16; o; o >>= 1) v += __shfl_xor_sync(0xffffffffu, v, o);
    return v;
}

__device__ __forceinline__ bool find_chunk(int b, int CH, int& e, int& start,
                                           int& nent) {
    int acc = 0;
    for (int ee = 0; ee < En; ee++) {
        int o0 = g_off[ee], o1 = g_off[ee + 1];
        int cnt = o1 - o0;
        int nch = (cnt + CH - 1) / CH;
        if (b < acc + nch) {
            e = ee;
            start = o0 + (b - acc) * CH;
            nent = min(CH, o1 - start);
            return true;
        }
        acc += nch;
    }
    return false;
}

#define LDSM4(r0, r1, r2, r3, addr) \
    asm volatile("ldmatrix.sync.aligned.m8n8.x4.shared.b16 {%0,%1,%2,%3}, [%4];" \
                 : "=r"(r0), "=r"(r1), "=r"(r2), "=r"(r3) : "r"(addr))

#define MMA16816(c, a, b0, b1) \
    asm volatile("mma.sync.aligned.m16n8k16.row.col.f32.f16.f16.f32 " \
                 "{%0,%1,%2,%3}, {%4,%5,%6,%7}, {%8,%9}, {%0,%1,%2,%3};" \
                 : "+f"((c)[0]), "+f"((c)[1]), "+f"((c)[2]), "+f"((c)[3]) \
                 : "r"((a)[0]), "r"((a)[1]), "r"((a)[2]), "r"((a)[3]), \
                   "r"(b0), "r"(b1))

// ---------------- fp32 -> fp16 convert (grid-stride, 8/thread) -------------
__global__ __launch_bounds__(256) void convert_kernel(
    const float* __restrict__ src, __half* __restrict__ dst, size_t n)
{
    for (size_t i = ((size_t)blockIdx.x * 256 + threadIdx.x) * 8; i < n;
         i += (size_t)gridDim.x * 256 * 8) {
        float4 v0 = *(const float4*)(src + i);
        float4 v1 = *(const float4*)(src + i + 4);
        *(__half2*)(dst + i)     = __halves2half2(__float2half_rn(v0.x), __float2half_rn(v0.y));
        *(__half2*)(dst + i + 2) = __halves2half2(__float2half_rn(v0.z), __float2half_rn(v0.w));
        *(__half2*)(dst + i + 4) = __halves2half2(__float2half_rn(v1.x), __float2half_rn(v1.y));
        *(__half2*)(dst + i + 6) = __halves2half2(__float2half_rn(v1.z), __float2half_rn(v1.w));
    }
}

// ---------------- GEMM stage loader (cp.async, SW128) ----------------------
__device__ __forceinline__ void load_stage(
    uint32_t sb, const __half* Ab, const __half* Bb,
    int Kp, int it, int stage, int tid)
{
    uint32_t st = sb + stage * STAGE_B;
    int k0 = it * KBE;
#pragma unroll
    for (int i = 0; i < 6; i++) {
        int c = tid + i * 512;          // 0..3071
        uint32_t soff;
        const __half* g;
        if (c < 1024) {                 // A: 128 rows x 8 chunks
            int row = c >> 3, j = c & 7;
            soff = st + SWZ(row * 128 + j * 16);
            g = Ab + (size_t)row * Kp + k0 + j * 8;
        } else {                        // B: 256 rows x 8 chunks
            int cc = c - 1024;
            int row = cc >> 3, j = cc & 7;
            soff = st + A_TILE_B + SWZ(row * 128 + j * 16);
            g = Bb + (size_t)row * Kp + k0 + j * 8;
        }
        asm volatile("cp.async.cg.shared.global [%0], [%1], 16;"
                     :: "r"(soff), "l"(g) : "memory");
    }
}

// ---------------- HMMA fp16 GEMM: C[M,N] = A[M,Kp] @ B[N,Kp]^T -------------
// half_out=1: C is __half*; half_out=0: C is float*
__global__ __launch_bounds__(512, 1) void gemm_f16(
    const __half* __restrict__ A, const __half* __restrict__ B,
    void* __restrict__ C, int N, int Kp, int half_out)
{
    extern __shared__ __align__(1024) char smem[];
    uint32_t sb = smem_u32(smem);
    int tid = threadIdx.x, wid = tid >> 5, lane = tid & 31;
    int wm = wid & 3, wn = wid >> 2;       // 4 warps in M, 4 in N
    int bx = blockIdx.x, by = blockIdx.y;
    const int niter = Kp / KBE;

    const __half* Ab = A + (size_t)(by * GBM) * Kp;
    const __half* Bb = B + (size_t)(bx * GBN) * Kp;

#pragma unroll
    for (int it = 0; it < STAGES - 1; it++) {
        load_stage(sb, Ab, Bb, Kp, it, it, tid);
        asm volatile("cp.async.commit_group;" ::: "memory");
    }

    float acc[2][8][4];
#pragma unroll
    for (int mi = 0; mi < 2; mi++)
#pragma unroll
        for (int nj = 0; nj < 8; nj++)
#pragma unroll
            for (int q = 0; q < 4; q++) acc[mi][nj][q] = 0.f;

    int gq = lane >> 3, rr = lane & 7;
    int kc = gq >> 1;
    uint32_t aRow[2]; int aXor[2];
#pragma unroll
    for (int mi = 0; mi < 2; mi++) {
        int m = wm * 32 + mi * 16 + (gq & 1) * 8 + rr;
        aRow[mi] = (uint32_t)(m * 128);
        aXor[mi] = m & 7;
    }
    uint32_t bRow[4]; int bXor[4];
#pragma unroll
    for (int ni = 0; ni < 4; ni++) {
        int n = wn * 64 + ni * 16 + (gq & 1) * 8 + rr;
        bRow[ni] = (uint32_t)(A_TILE_B + n * 128);
        bXor[ni] = n & 7;
    }

    int s = 0;
    for (int it = 0; it < niter; it++) {
        asm volatile("cp.async.wait_group %0;" :: "n"(STAGES - 2) : "memory");
        __syncthreads();
        int jt = it + STAGES - 1;
        if (jt < niter) {
            int sj = jt - (jt / STAGES) * STAGES;
            load_stage(sb, Ab, Bb, Kp, jt, sj, tid);
        }
        asm volatile("cp.async.commit_group;" ::: "memory");

        uint32_t stb = sb + s * STAGE_B;
        s++; if (s == STAGES) s = 0;
#pragma unroll
        for (int ks = 0; ks < 4; ks++) {
            uint32_t a[2][4];
#pragma unroll
            for (int mi = 0; mi < 2; mi++) {
                uint32_t ad = stb + aRow[mi]
                            + (uint32_t)((((ks << 1) + kc) ^ aXor[mi]) << 4);
                LDSM4(a[mi][0], a[mi][1], a[mi][2], a[mi][3], ad);
            }
            uint32_t b[4][4];
#pragma unroll
            for (int ni = 0; ni < 4; ni++) {
                uint32_t bd = stb + bRow[ni]
                            + (uint32_t)((((ks << 1) + kc) ^ bXor[ni]) << 4);
                LDSM4(b[ni][0], b[ni][1], b[ni][2], b[ni][3], bd);
            }
#pragma unroll
            for (int mi = 0; mi < 2; mi++)
#pragma unroll
                for (int ni = 0; ni < 4; ni++) {
                    MMA16816(acc[mi][ni * 2],     a[mi], b[ni][0], b[ni][2]);
                    MMA16816(acc[mi][ni * 2 + 1], a[mi], b[ni][1], b[ni][3]);
                }
        }
    }

    int gid = lane >> 2, tig = lane & 3;
    if (half_out) {
        __half* Ch = (__half*)C;
#pragma unroll
        for (int mi = 0; mi < 2; mi++) {
            int row = by * GBM + wm * 32 + mi * 16 + gid;
#pragma unroll
            for (int nj = 0; nj < 8; nj++) {
                __half* p = Ch + (size_t)row * N + bx * GBN + wn * 64 + nj * 8 + tig * 2;
                *(__half2*)p = __halves2half2(__float2half_rn(acc[mi][nj][0]),
                                              __float2half_rn(acc[mi][nj][1]));
                *(__half2*)(p + (size_t)8 * N) =
                    __halves2half2(__float2half_rn(acc[mi][nj][2]),
                                   __float2half_rn(acc[mi][nj][3]));
            }
        }
    } else {
        float* Cf = (float*)C;
#pragma unroll
        for (int mi = 0; mi < 2; mi++) {
            int row = by * GBM + wm * 32 + mi * 16 + gid;
#pragma unroll
            for (int nj = 0; nj < 8; nj++) {
                float* p = Cf + (size_t)row * N + bx * GBN + wn * 64 + nj * 8 + tig * 2;
                *(float2*)p = make_float2(acc[mi][nj][0], acc[mi][nj][1]);
                *(float2*)(p + (size_t)8 * N) = make_float2(acc[mi][nj][2], acc[mi][nj][3]);
            }
        }
    }
}

// ---------------- K1: gate -------------------------------------------------
__global__ __launch_bounds__(256) void gate_kernel(
    const float* __restrict__ x, const float* __restrict__ Wg)
{
    int t = blockIdx.x;
    int tid = threadIdx.x;
    int w = tid >> 5, lane = tid & 31;
    const float* xr = x + (size_t)t * Hn;
    const float* wr = Wg + (size_t)w * Hn;
    float s = 0.f;
    for (int h = lane * 4; h < Hn; h += 32 * 4) {
        float4 xv = *(const float4*)(xr + h);
        float4 wv = *(const float4*)(wr + h);
        s += xv.x * wv.x + xv.y * wv.y + xv.z * wv.z + xv.w * wv.w;
    }
    s = warp_sum(s);
    __shared__ float logits[En];
    if (lane == 0) logits[w] = s;
    __syncthreads();
    if (tid == 0) {
        int i0 = 0; float l0 = logits[0];
#pragma unroll
        for (int e = 1; e < En; e++) if (logits[e] > l0) { l0 = logits[e]; i0 = e; }
        int i1 = -1; float l1 = -3.0e38f;
#pragma unroll
        for (int e = 0; e < En; e++) if (e != i0 && logits[e] > l1) { l1 = logits[e]; i1 = e; }
        float r0 = 1.f / (1.f + expf(l1 - l0));
        g_sel[t * 2 + 0] = i0;
        g_sel[t * 2 + 1] = i1;
        g_rw [t * 2 + 0] = r0;
        g_rw [t * 2 + 1] = 1.f - r0;
    }
}

// ---------------- expert grouping ------------------------------------------
__global__ __launch_bounds__(256) void hist_kernel()
{
    __shared__ int hc[En];
    int tid = threadIdx.x;
    if (tid < En) hc[tid] = 0;
    __syncthreads();
    for (int i = tid; i < Tn * Kn; i += 256)
        atomicAdd(&hc[g_sel[i]], 1);
    __syncthreads();
    if (tid == 0) {
        int off = 0;
        for (int e = 0; e < En; e++) {
            g_off[e] = off;
            g_cur[e] = off;
            off += hc[e];
        }
        g_off[En] = off;
    }
}

__global__ __launch_bounds__(256) void scatter_kernel()
{
    int i = blockIdx.x * 256 + threadIdx.x;
    if (i < Tn * Kn) {
        int e = g_sel[i];
        int pos = atomicAdd(&g_cur[e], 1);
        g_list[pos] = i;
    }
}

// -------- grouped fuse (CH=16): a1/a3 read from extended base13 ------------
#define CHF 16
#define PAD 132
__global__ __launch_bounds__(256) void fuse_grouped(
    const float* __restrict__ B1, const float* __restrict__ B3)
{
    int e, start, nent;
    if (!find_chunk(blockIdx.x, CHF, e, start, nent)) return;
    __shared__ float a1s[CHF][Rn];
    __shared__ float a3s[CHF][Rn];
    __shared__ int ids[CHF];
    int tid = threadIdx.x;
    if (tid < CHF)
        ids[tid] = (tid < nent) ? g_list[start + tid] : g_list[start];
    __syncthreads();
    // a1_all at col 2*Fn + e*Rn; a3_all at col 2*Fn + En*Rn + e*Rn
#pragma unroll
    for (int i = 0; i < 2; i++) {
        int q = tid + i * 256;
        int en = q >> 5, r = q & 31;
        const __half* b13 = g_base13 + (size_t)(ids[en] >> 1) * NEXT + 2 * Fn;
        a1s[en][r] = __half2float(b13[e * Rn + r]);
        a3s[en][r] = __half2float(b13[En * Rn + e * Rn + r]);
    }
    __syncthreads();

    for (int f0 = 0; f0 < Fn; f0 += 256) {
        int f = f0 + tid;
        float b1r[Rn], b3r[Rn];
        const float4* p1 = (const float4*)(B1 + ((size_t)e * Fn + f) * Rn);
        const float4* p3 = (const float4*)(B3 + ((size_t)e * Fn + f) * Rn);
#pragma unroll
        for (int q = 0; q < 8; q++) {
            float4 v1 = p1[q], v3 = p3[q];
            b1r[q * 4 + 0] = v1.x; b1r[q * 4 + 1] = v1.y;
            b1r[q * 4 + 2] = v1.z; b1r[q * 4 + 3] = v1.w;
            b3r[q * 4 + 0] = v3.x; b3r[q * 4 + 1] = v3.y;
            b3r[q * 4 + 2] = v3.z; b3r[q * 4 + 3] = v3.w;
        }
        for (int en = 0; en < nent; en++) {
            int id = ids[en];
            int t = id >> 1, kk = id & 1;
            float l1 = 0.f, l3 = 0.f;
#pragma unroll
            for (int r = 0; r < Rn; r++) {
                l1 += b1r[r] * a1s[en][r];
                l3 += b3r[r] * a3s[en][r];
            }
            const __half* b13 = g_base13 + (size_t)t * NEXT;
            float x1 = __half2float(b13[f]) + l1;
            float x3 = __half2float(b13[Fn + f]) + l3;
            float sig = 1.f / (1.f + expf(-x1));
            float x2 = x1 * sig * x3;
            (kk ? g_x2k1 : g_x2k0)[(size_t)t * Fn + f] = __float2half_rn(x2);
        }
    }
}

// -------- combine weighted x2 -> fp16 (half inputs) ------------------------
__global__ __launch_bounds__(256) void combine_x2()
{
    int t = blockIdx.x;
    float w0 = g_rw[t * 2], w1 = g_rw[t * 2 + 1];
    __half* d = g_x2s + (size_t)t * Fn;
    const __half* s0 = g_x2k0 + (size_t)t * Fn;
    const __half* s1 = g_x2k1 + (size_t)t * Fn;
    for (int f = threadIdx.x * 2; f < Fn; f += 256 * 2) {
        float2 v0 = __half22float2(*(const __half2*)(s0 + f));
        float2 v1 = __half22float2(*(const __half2*)(s1 + f));
        *(__half2*)(d + f) = __halves2half2(
            __float2half_rn(w0 * v0.x + w1 * v1.x),
            __float2half_rn(w0 * v0.y + w1 * v1.y));
    }
}

// -------- grouped a2 (CH=16; 16 entries x 16 rg, 2 outputs each) -----------
#define CH2 16
__global__ __launch_bounds__(256) void a2_grouped(const float* __restrict__ A2)
{
    int e, start, nent;
    if (!find_chunk(blockIdx.x, CH2, e, start, nent)) return;
    __shared__ float xs[CH2][PAD];
    __shared__ float as[Rn][PAD];
    __shared__ int ids[CH2];
    int tid = threadIdx.x;
    if (tid < CH2)
        ids[tid] = (tid < nent) ? g_list[start + tid] : g_list[start];
    __syncthreads();

    int entry = tid >> 4, rg = tid & 15;
    float acc0 = 0.f, acc1 = 0.f;
    int myid = ids[entry];

    for (int f0 = 0; f0 < Fn; f0 += 128) {
#pragma unroll
        for (int i = 0; i < 4; i++) {
            int q = tid + i * 256;
            int row = q >> 6, c2 = q & 63;
            int id = ids[row];
            const __half* src = (id & 1) ? g_x2k1 : g_x2k0;
            float2 fv = __half22float2(
                *(const __half2*)(src + (size_t)(id >> 1) * Fn + f0 + 2 * c2));
            xs[row][2 * c2]     = fv.x;
            xs[row][2 * c2 + 1] = fv.y;
        }
#pragma unroll
        for (int i = 0; i < 16; i++) {
            int q = tid + i * 256;
            int row = q >> 7, col = q & 127;
            as[row][col] = A2[(size_t)(e * Rn + row) * Fn + f0 + col];
        }
        __syncthreads();
#pragma unroll
        for (int h = 0; h < 128; h += 4) {
            float4 xv = *(const float4*)&xs[entry][h];
            float4 a0 = *(const float4*)&as[rg][h];
            float4 a1 = *(const float4*)&as[rg + 16][h];
            acc0 += xv.x * a0.x + xv.y * a0.y + xv.z * a0.z + xv.w * a0.w;
            acc1 += xv.x * a1.x + xv.y * a1.y + xv.z * a1.z + xv.w * a1.w;
        }
        __syncthreads();
    }
    if (entry < nent) {
        g_a2[(size_t)myid * Rn + rg] = acc0;
        g_a2[(size_t)myid * Rn + rg + 16] = acc1;
    }
}

// -------- grouped final (CH=32) --------------------------------------------
#define CHL 32
__global__ __launch_bounds__(256) void final_grouped(const float* __restrict__ B2)
{
    int e, start, nent;
    if (!find_chunk(blockIdx.x, CHL, e, start, nent)) return;
    __shared__ float a2s[CHL][Rn];
    __shared__ float ws[CHL];
    __shared__ int ids[CHL];
    int tid = threadIdx.x;
    if (tid < CHL) {
        int id = (tid < nent) ? g_list[start + tid] : g_list[start];
        ids[tid] = id;
        ws[tid] = g_rw[id];
    }
    __syncthreads();
#pragma unroll
    for (int i = 0; i < 4; i++) {
        int q = tid + i * 256;
        int en = q >> 5, r = q & 31;
        a2s[en][r] = g_a2[(size_t)ids[en] * Rn + r];
    }
    __syncthreads();

    for (int h0 = 0; h0 < Hn; h0 += 256) {
        int h = h0 + tid;
        float b2r[Rn];
        const float4* p2 = (const float4*)(B2 + ((size_t)e * Hn + h) * Rn);
#pragma unroll
        for (int q = 0; q < 8; q++) {
            float4 v = p2[q];
            b2r[q * 4 + 0] = v.x; b2r[q * 4 + 1] = v.y;
            b2r[q * 4 + 2] = v.z; b2r[q * 4 + 3] = v.w;
        }
        for (int en = 0; en < nent; en++) {
            int id = ids[en];
            int t = id >> 1, kk = id & 1;
            float l2 = 0.f;
#pragma unroll
            for (int r = 0; r < Rn; r++) l2 += b2r[r] * a2s[en][r];
            (kk ? g_l2k1 : g_l2k0)[(size_t)t * Hn + h] = ws[en] * l2;
        }
    }
}

// -------- add lora2 contributions into out ---------------------------------
__global__ __launch_bounds__(256) void add_out(float* __restrict__ out)
{
    int i = (blockIdx.x * 256 + threadIdx.x) * 4;
    float4 o = *(float4*)(out + i);
    float4 a = *(const float4*)(g_l2k0 + i);
    float4 b = *(const float4*)(g_l2k1 + i);
    o.x += a.x + b.x; o.y += a.y + b.y;
    o.z += a.z + b.z; o.w += a.w + b.w;
    *(float4*)(out + i) = o;
}

// ---------------------------------------------------------------------------
extern "C" void kernel_launch(void* const* d_in, const int* in_sizes, int n_in,
                              void* d_out, int out_size)
{
    (void)in_sizes; (void)n_in; (void)out_size;
    const float* x  = (const float*)d_in[0];
    const float* Wg = (const float*)d_in[1];
    const float* W1 = (const float*)d_in[2];
    const float* W2 = (const float*)d_in[3];
    const float* W3 = (const float*)d_in[4];
    const float* A1 = (const float*)d_in[5];
    const float* B1 = (const float*)d_in[6];
    const float* A2 = (const float*)d_in[7];
    const float* B2 = (const float*)d_in[8];
    const float* A3 = (const float*)d_in[9];
    const float* B3 = (const float*)d_in[10];
    float* out = (float*)d_out;

    __half *xs, *w13s, *w2s, *x2s, *base13;
    cudaGetSymbolAddress((void**)&base13, g_base13);
    cudaGetSymbolAddress((void**)&xs,   g_xs);
    cudaGetSymbolAddress((void**)&w13s, g_w13s);
    cudaGetSymbolAddress((void**)&w2s,  g_w2s);
    cudaGetSymbolAddress((void**)&x2s,  g_x2s);

    cudaFuncSetAttribute(gemm_f16, cudaFuncAttributeMaxDynamicSharedMemorySize,
                         SMEM_TOTAL);

    static cudaStream_t s1 = nullptr, s2 = nullptr;
    static cudaEvent_t evA = nullptr, ev1 = nullptr, ev2 = nullptr,
                       ev3 = nullptr, ev4 = nullptr;
    if (s1 == nullptr) {
        cudaStreamCreateWithFlags(&s1, cudaStreamNonBlocking);
        cudaStreamCreateWithFlags(&s2, cudaStreamNonBlocking);
        cudaEventCreateWithFlags(&evA, cudaEventDisableTiming);
        cudaEventCreateWithFlags(&ev1, cudaEventDisableTiming);
        cudaEventCreateWithFlags(&ev2, cudaEventDisableTiming);
        cudaEventCreateWithFlags(&ev3, cudaEventDisableTiming);
        cudaEventCreateWithFlags(&ev4, cudaEventDisableTiming);
    }

    // root fork
    cudaEventRecord(evA, 0);
    cudaStreamWaitEvent(s1, evA, 0);
    cudaStreamWaitEvent(s2, evA, 0);

    // s1: gate chain (tiny; only needed before fuse)
    gate_kernel<<<Tn, 256, 0, s1>>>(x, Wg);
    hist_kernel<<<1, 256, 0, s1>>>();
    scatter_kernel<<<(Tn * Kn + 255) / 256, 256, 0, s1>>>();
    cudaEventRecord(ev1, s1);

    // s2: W2 convert (needed only by down GEMM)
    convert_kernel<<<1024, 256, 0, s2>>>(W2, w2s, (size_t)Hn * Fn);
    cudaEventRecord(ev4, s2);

    // main: converts + extended base GEMM (N = NEXT, fp16 output)
    convert_kernel<<<512, 256>>>(x, xs, (size_t)Tn * Hn);
    convert_kernel<<<1024, 256>>>(W1, w13s, (size_t)Fn * Hn);
    convert_kernel<<<1024, 256>>>(W3, w13s + (size_t)Fn * Hn, (size_t)Fn * Hn);
    convert_kernel<<<64, 256>>>(A1, w13s + (size_t)2 * Fn * Hn,
                                (size_t)En * Rn * Hn);
    convert_kernel<<<64, 256>>>(A3, w13s + ((size_t)2 * Fn + En * Rn) * Hn,
                                (size_t)En * Rn * Hn);
    gemm_f16<<<dim3(NEXT / GBN, Tn / GBM), 512, SMEM_TOTAL>>>(
        xs, w13s, base13, NEXT, Hn, 1);

    // join gate chain before fuse
    cudaStreamWaitEvent(0, ev1, 0);
    fuse_grouped<<<Tn * Kn / CHF + En, 256>>>(B1, B3);

    // fork: a2 + final on s2 concurrent with combine + down GEMM
    cudaEventRecord(ev2, 0);
    cudaStreamWaitEvent(s2, ev2, 0);
    a2_grouped<<<Tn * Kn / CH2 + En, 256, 0, s2>>>(A2);
    final_grouped<<<Tn * Kn / CHL + En, 256, 0, s2>>>(B2);
    cudaEventRecord(ev3, s2);

    combine_x2<<<Tn, 256>>>();
    cudaStreamWaitEvent(0, ev4, 0);    // W2 fp16 ready
    gemm_f16<<<dim3(Hn / GBN, Tn / GBM), 512, SMEM_TOTAL>>>(
        x2s, w2s, out, Hn, Fn, 0);

    // join lora2 path, then final add
    cudaStreamWaitEvent(0, ev3, 0);
    add_out<<<Tn * Hn / 1024, 256>>>(out);
}

// round 16
// speedup vs baseline: 2.3678x; 1.0870x over previous
#include <cuda_runtime.h>
#include <cuda_fp16.h>
#include <math.h>
#include <stdint.h>

// Problem dims
#define Tn 2048   // tokens = B*S
#define Hn 2048   // hidden
#define Fn 7168   // ffn
#define En 8      // experts
#define Rn 32     // lora rank
#define Kn 2      // top-k

// Extended base GEMM N: [W1 | W3 | A1_all | A3_all]
#define NEXT (2 * Fn + 2 * En * Rn)   // 14848 = 58 * 256

// HMMA GEMM tiling: 128x256, 512 threads, 4 stages
#define GBM 128
#define GBN 256
#define KBE 64                     // fp16 K elems per stage = 128B rows (SW128)
#define STAGES 4
#define A_TILE_B (GBM * 128)       // 16384
#define B_TILE_B (GBN * 128)       // 32768
#define STAGE_B  (A_TILE_B + B_TILE_B)       // 49152
#define SMEM_TOTAL (STAGES * STAGE_B)        // 196608

#define SWZ(o) ((o) ^ (((o) >> 3) & 0x70))

// ---------------- scratch (device globals) ---------------------------------
__device__ __align__(256) __half g_base13[Tn * NEXT];   // [b1|b3|a1_all|a3_all]
__device__ __align__(256) __half g_x2k0[Tn * Fn];       // per-slot x2 (fp16)
__device__ __align__(256) __half g_x2k1[Tn * Fn];
__device__ __align__(256) float g_l2k0[Tn * Hn];
__device__ __align__(256) float g_l2k1[Tn * Hn];
__device__ __align__(256) __half g_xs  [Tn * Hn];       // x fp16
__device__ __align__(256) __half g_w13s[NEXT * Hn];     // [W1;W3;A1;A3] fp16
__device__ __align__(256) __half g_w2s [Hn * Fn];       // W2 fp16
__device__ __align__(256) __half g_x2s [Tn * Fn];       // weighted x2 fp16
__device__ __align__(256) __half g_b1h [En * Fn * Rn];  // B1 fp16
__device__ __align__(256) __half g_b3h [En * Fn * Rn];  // B3 fp16
__device__ int   g_sel[Tn * Kn];
__device__ float g_rw [Tn * Kn];
__device__ float g_a2 [Tn * Kn * Rn];
// expert grouping
__device__ int g_off [En + 1];
__device__ int g_cur [En];
__device__ int g_list[Tn * Kn];

// ---------------- helpers ---------------------------------------------------
__device__ __forceinline__ uint32_t smem_u32(const void* p) {
    uint32_t a;
    asm("{ .reg .u64 t; cvta.to.shared.u64 t, %1; cvt.u32.u64 %0, t; }"
        : "=r"(a) : "l"(p));
    return a;
}

__device__ __forceinline__ float warp_sum(float v) {
#pragma unroll
    for (int o = 16; o; o >>= 1) v += __shfl_xor_sync(0xffffffffu, v, o);
    return v;
}

__device__ __forceinline__ bool find_chunk(int b, int CH, int& e, int& start,
                                           int& nent) {
    int acc = 0;
    for (int ee = 0; ee < En; ee++) {
        int o0 = g_off[ee], o1 = g_off[ee + 1];
        int cnt = o1 - o0;
        int nch = (cnt + CH - 1) / CH;
        if (b < acc + nch) {
            e = ee;
            start = o0 + (b - acc) * CH;
            nent = min(CH, o1 - start);
            return true;
        }
        acc += nch;
    }
    return false;
}

#define LDSM4(r0, r1, r2, r3, addr) \
    asm volatile("ldmatrix.sync.aligned.m8n8.x4.shared.b16 {%0,%1,%2,%3}, [%4];" \
                 : "=r"(r0), "=r"(r1), "=r"(r2), "=r"(r3) : "r"(addr))

#define MMA16816(c, a, b0, b1) \
    asm volatile("mma.sync.aligned.m16n8k16.row.col.f32.f16.f16.f32 " \
                 "{%0,%1,%2,%3}, {%4,%5,%6,%7}, {%8,%9}, {%0,%1,%2,%3};" \
                 : "+f"((c)[0]), "+f"((c)[1]), "+f"((c)[2]), "+f"((c)[3]) \
                 : "r"((a)[0]), "r"((a)[1]), "r"((a)[2]), "r"((a)[3]), \
                   "r"(b0), "r"(b1))

// ---------------- fp32 -> fp16 convert (grid-stride, 8/thread) -------------
__global__ __launch_bounds__(256) void convert_kernel(
    const float* __restrict__ src, __half* __restrict__ dst, size_t n)
{
    for (size_t i = ((size_t)blockIdx.x * 256 + threadIdx.x) * 8; i < n;
         i += (size_t)gridDim.x * 256 * 8) {
        float4 v0 = *(const float4*)(src + i);
        float4 v1 = *(const float4*)(src + i + 4);
        *(__half2*)(dst + i)     = __halves2half2(__float2half_rn(v0.x), __float2half_rn(v0.y));
        *(__half2*)(dst + i + 2) = __halves2half2(__float2half_rn(v0.z), __float2half_rn(v0.w));
        *(__half2*)(dst + i + 4) = __halves2half2(__float2half_rn(v1.x), __float2half_rn(v1.y));
        *(__half2*)(dst + i + 6) = __halves2half2(__float2half_rn(v1.z), __float2half_rn(v1.w));
    }
}

// ---------------- GEMM stage loader (cp.async, SW128) ----------------------
__device__ __forceinline__ void load_stage(
    uint32_t sb, const __half* Ab, const __half* Bb,
    int Kp, int it, int stage, int tid)
{
    uint32_t st = sb + stage * STAGE_B;
    int k0 = it * KBE;
#pragma unroll
    for (int i = 0; i < 6; i++) {
        int c = tid + i * 512;          // 0..3071
        uint32_t soff;
        const __half* g;
        if (c < 1024) {                 // A: 128 rows x 8 chunks
            int row = c >> 3, j = c & 7;
            soff = st + SWZ(row * 128 + j * 16);
            g = Ab + (size_t)row * Kp + k0 + j * 8;
        } else {                        // B: 256 rows x 8 chunks
            int cc = c - 1024;
            int row = cc >> 3, j = cc & 7;
            soff = st + A_TILE_B + SWZ(row * 128 + j * 16);
            g = Bb + (size_t)row * Kp + k0 + j * 8;
        }
        asm volatile("cp.async.cg.shared.global [%0], [%1], 16;"
                     :: "r"(soff), "l"(g) : "memory");
    }
}

// ---------------- HMMA fp16 GEMM: C[M,N] = A[M,Kp] @ B[N,Kp]^T -------------
// half_out=1: C is __half*; half_out=0: C is float*
__global__ __launch_bounds__(512, 1) void gemm_f16(
    const __half* __restrict__ A, const __half* __restrict__ B,
    void* __restrict__ C, int N, int Kp, int half_out)
{
    extern __shared__ __align__(1024) char smem[];
    uint32_t sb = smem_u32(smem);
    int tid = threadIdx.x, wid = tid >> 5, lane = tid & 31;
    int wm = wid & 3, wn = wid >> 2;       // 4 warps in M, 4 in N
    int bx = blockIdx.x, by = blockIdx.y;
    const int niter = Kp / KBE;

    const __half* Ab = A + (size_t)(by * GBM) * Kp;
    const __half* Bb = B + (size_t)(bx * GBN) * Kp;

#pragma unroll
    for (int it = 0; it < STAGES - 1; it++) {
        load_stage(sb, Ab, Bb, Kp, it, it, tid);
        asm volatile("cp.async.commit_group;" ::: "memory");
    }

    float acc[2][8][4];
#pragma unroll
    for (int mi = 0; mi < 2; mi++)
#pragma unroll
        for (int nj = 0; nj < 8; nj++)
#pragma unroll
            for (int q = 0; q < 4; q++) acc[mi][nj][q] = 0.f;

    int gq = lane >> 3, rr = lane & 7;
    int kc = gq >> 1;
    uint32_t aRow[2]; int aXor[2];
#pragma unroll
    for (int mi = 0; mi < 2; mi++) {
        int m = wm * 32 + mi * 16 + (gq & 1) * 8 + rr;
        aRow[mi] = (uint32_t)(m * 128);
        aXor[mi] = m & 7;
    }
    uint32_t bRow[4]; int bXor[4];
#pragma unroll
    for (int ni = 0; ni < 4; ni++) {
        int n = wn * 64 + ni * 16 + (gq & 1) * 8 + rr;
        bRow[ni] = (uint32_t)(A_TILE_B + n * 128);
        bXor[ni] = n & 7;
    }

    int s = 0;
    for (int it = 0; it < niter; it++) {
        asm volatile("cp.async.wait_group %0;" :: "n"(STAGES - 2) : "memory");
        __syncthreads();
        int jt = it + STAGES - 1;
        if (jt < niter) {
            int sj = jt - (jt / STAGES) * STAGES;
            load_stage(sb, Ab, Bb, Kp, jt, sj, tid);
        }
        asm volatile("cp.async.commit_group;" ::: "memory");

        uint32_t stb = sb + s * STAGE_B;
        s++; if (s == STAGES) s = 0;
#pragma unroll
        for (int ks = 0; ks < 4; ks++) {
            uint32_t a[2][4];
#pragma unroll
            for (int mi = 0; mi < 2; mi++) {
                uint32_t ad = stb + aRow[mi]
                            + (uint32_t)((((ks << 1) + kc) ^ aXor[mi]) << 4);
                LDSM4(a[mi][0], a[mi][1], a[mi][2], a[mi][3], ad);
            }
            uint32_t b[4][4];
#pragma unroll
            for (int ni = 0; ni < 4; ni++) {
                uint32_t bd = stb + bRow[ni]
                            + (uint32_t)((((ks << 1) + kc) ^ bXor[ni]) << 4);
                LDSM4(b[ni][0], b[ni][1], b[ni][2], b[ni][3], bd);
            }
#pragma unroll
            for (int mi = 0; mi < 2; mi++)
#pragma unroll
                for (int ni = 0; ni < 4; ni++) {
                    MMA16816(acc[mi][ni * 2],     a[mi], b[ni][0], b[ni][2]);
                    MMA16816(acc[mi][ni * 2 + 1], a[mi], b[ni][1], b[ni][3]);
                }
        }
    }

    int gid = lane >> 2, tig = lane & 3;
    if (half_out) {
        __half* Ch = (__half*)C;
#pragma unroll
        for (int mi = 0; mi < 2; mi++) {
            int row = by * GBM + wm * 32 + mi * 16 + gid;
#pragma unroll
            for (int nj = 0; nj < 8; nj++) {
                __half* p = Ch + (size_t)row * N + bx * GBN + wn * 64 + nj * 8 + tig * 2;
                *(__half2*)p = __halves2half2(__float2half_rn(acc[mi][nj][0]),
                                              __float2half_rn(acc[mi][nj][1]));
                *(__half2*)(p + (size_t)8 * N) =
                    __halves2half2(__float2half_rn(acc[mi][nj][2]),
                                   __float2half_rn(acc[mi][nj][3]));
            }
        }
    } else {
        float* Cf = (float*)C;
#pragma unroll
        for (int mi = 0; mi < 2; mi++) {
            int row = by * GBM + wm * 32 + mi * 16 + gid;
#pragma unroll
            for (int nj = 0; nj < 8; nj++) {
                float* p = Cf + (size_t)row * N + bx * GBN + wn * 64 + nj * 8 + tig * 2;
                *(float2*)p = make_float2(acc[mi][nj][0], acc[mi][nj][1]);
                *(float2*)(p + (size_t)8 * N) = make_float2(acc[mi][nj][2], acc[mi][nj][3]);
            }
        }
    }
}

// ---------------- K1: gate -------------------------------------------------
__global__ __launch_bounds__(256) void gate_kernel(
    const float* __restrict__ x, const float* __restrict__ Wg)
{
    int t = blockIdx.x;
    int tid = threadIdx.x;
    int w = tid >> 5, lane = tid & 31;
    const float* xr = x + (size_t)t * Hn;
    const float* wr = Wg + (size_t)w * Hn;
    float s = 0.f;
    for (int h = lane * 4; h < Hn; h += 32 * 4) {
        float4 xv = *(const float4*)(xr + h);
        float4 wv = *(const float4*)(wr + h);
        s += xv.x * wv.x + xv.y * wv.y + xv.z * wv.z + xv.w * wv.w;
    }
    s = warp_sum(s);
    __shared__ float logits[En];
    if (lane == 0) logits[w] = s;
    __syncthreads();
    if (tid == 0) {
        int i0 = 0; float l0 = logits[0];
#pragma unroll
        for (int e = 1; e < En; e++) if (logits[e] > l0) { l0 = logits[e]; i0 = e; }
        int i1 = -1; float l1 = -3.0e38f;
#pragma unroll
        for (int e = 0; e < En; e++) if (e != i0 && logits[e] > l1) { l1 = logits[e]; i1 = e; }
        float r0 = 1.f / (1.f + expf(l1 - l0));
        g_sel[t * 2 + 0] = i0;
        g_sel[t * 2 + 1] = i1;
        g_rw [t * 2 + 0] = r0;
        g_rw [t * 2 + 1] = 1.f - r0;
    }
}

// ---------------- expert grouping ------------------------------------------
__global__ __launch_bounds__(256) void hist_kernel()
{
    __shared__ int hc[En];
    int tid = threadIdx.x;
    if (tid < En) hc[tid] = 0;
    __syncthreads();
    for (int i = tid; i < Tn * Kn; i += 256)
        atomicAdd(&hc[g_sel[i]], 1);
    __syncthreads();
    if (tid == 0) {
        int off = 0;
        for (int e = 0; e < En; e++) {
            g_off[e] = off;
            g_cur[e] = off;
            off += hc[e];
        }
        g_off[En] = off;
    }
}

__global__ __launch_bounds__(256) void scatter_kernel()
{
    int i = blockIdx.x * 256 + threadIdx.x;
    if (i < Tn * Kn) {
        int e = g_sel[i];
        int pos = atomicAdd(&g_cur[e], 1);
        g_list[pos] = i;
    }
}

// -------- grouped fuse (CH=16): HFMA2, fp16 B1/B3, a1/a3 from base13 -------
#define CHF 16
#define PAD 132
__global__ __launch_bounds__(256) void fuse_grouped(
    const __half* __restrict__ B1h, const __half* __restrict__ B3h)
{
    int e, start, nent;
    if (!find_chunk(blockIdx.x, CHF, e, start, nent)) return;
    __shared__ __half2 a1h[CHF][Rn / 2];
    __shared__ __half2 a3h[CHF][Rn / 2];
    __shared__ int ids[CHF];
    int tid = threadIdx.x;
    if (tid < CHF)
        ids[tid] = (tid < nent) ? g_list[start + tid] : g_list[start];
    __syncthreads();
    if (tid < CHF * (Rn / 2)) {
        int en = tid >> 4, i = tid & 15;
        const __half* b13 = g_base13 + (size_t)(ids[en] >> 1) * NEXT + 2 * Fn;
        a1h[en][i] = *(const __half2*)(b13 + e * Rn + 2 * i);
        a3h[en][i] = *(const __half2*)(b13 + En * Rn + e * Rn + 2 * i);
    }
    __syncthreads();

    for (int f0 = 0; f0 < Fn; f0 += 256) {
        int f = f0 + tid;
        __align__(16) __half2 b1r[16];
        __align__(16) __half2 b3r[16];
        const float4* p1 = (const float4*)(B1h + ((size_t)e * Fn + f) * Rn);
        const float4* p3 = (const float4*)(B3h + ((size_t)e * Fn + f) * Rn);
#pragma unroll
        for (int q = 0; q < 4; q++) {
            *((float4*)b1r + q) = p1[q];
            *((float4*)b3r + q) = p3[q];
        }
        for (int en = 0; en < nent; en++) {
            int id = ids[en];
            int t = id >> 1, kk = id & 1;
            __half2 s1[4], s3[4];
#pragma unroll
            for (int q = 0; q < 4; q++) {
                s1[q] = __float2half2_rn(0.f);
                s3[q] = __float2half2_rn(0.f);
            }
#pragma unroll
            for (int j = 0; j < 16; j += 4) {
#pragma unroll
                for (int q = 0; q < 4; q++) {
                    s1[q] = __hfma2(b1r[j + q], a1h[en][j + q], s1[q]);
                    s3[q] = __hfma2(b3r[j + q], a3h[en][j + q], s3[q]);
                }
            }
            float l1 = 0.f, l3 = 0.f;
#pragma unroll
            for (int q = 0; q < 4; q++) {
                float2 u1 = __half22float2(s1[q]);
                float2 u3 = __half22float2(s3[q]);
                l1 += u1.x + u1.y;
                l3 += u3.x + u3.y;
            }
            const __half* b13 = g_base13 + (size_t)t * NEXT;
            float x1 = __half2float(b13[f]) + l1;
            float x3 = __half2float(b13[Fn + f]) + l3;
            float sig = 1.f / (1.f + expf(-x1));
            float x2 = x1 * sig * x3;
            (kk ? g_x2k1 : g_x2k0)[(size_t)t * Fn + f] = __float2half_rn(x2);
        }
    }
}

// -------- combine weighted x2 -> fp16 (half inputs) ------------------------
__global__ __launch_bounds__(256) void combine_x2()
{
    int t = blockIdx.x;
    float w0 = g_rw[t * 2], w1 = g_rw[t * 2 + 1];
    __half* d = g_x2s + (size_t)t * Fn;
    const __half* s0 = g_x2k0 + (size_t)t * Fn;
    const __half* s1 = g_x2k1 + (size_t)t * Fn;
    for (int f = threadIdx.x * 2; f < Fn; f += 256 * 2) {
        float2 v0 = __half22float2(*(const __half2*)(s0 + f));
        float2 v1 = __half22float2(*(const __half2*)(s1 + f));
        *(__half2*)(d + f) = __halves2half2(
            __float2half_rn(w0 * v0.x + w1 * v1.x),
            __float2half_rn(w0 * v0.y + w1 * v1.y));
    }
}

// -------- grouped a2 (CH=16; 16 entries x 16 rg, 2 outputs each) -----------
#define CH2 16
__global__ __launch_bounds__(256) void a2_grouped(const float* __restrict__ A2)
{
    int e, start, nent;
    if (!find_chunk(blockIdx.x, CH2, e, start, nent)) return;
    __shared__ float xs[CH2][PAD];
    __shared__ float as[Rn][PAD];
    __shared__ int ids[CH2];
    int tid = threadIdx.x;
    if (tid < CH2)
        ids[tid] = (tid < nent) ? g_list[start + tid] : g_list[start];
    __syncthreads();

    int entry = tid >> 4, rg = tid & 15;
    float acc0 = 0.f, acc1 = 0.f;
    int myid = ids[entry];

    for (int f0 = 0; f0 < Fn; f0 += 128) {
#pragma unroll
        for (int i = 0; i < 4; i++) {
            int q = tid + i * 256;
            int row = q >> 6, c2 = q & 63;
            int id = ids[row];
            const __half* src = (id & 1) ? g_x2k1 : g_x2k0;
            float2 fv = __half22float2(
                *(const __half2*)(src + (size_t)(id >> 1) * Fn + f0 + 2 * c2));
            xs[row][2 * c2]     = fv.x;
            xs[row][2 * c2 + 1] = fv.y;
        }
#pragma unroll
        for (int i = 0; i < 16; i++) {
            int q = tid + i * 256;
            int row = q >> 7, col = q & 127;
            as[row][col] = A2[(size_t)(e * Rn + row) * Fn + f0 + col];
        }
        __syncthreads();
#pragma unroll
        for (int h = 0; h < 128; h += 4) {
            float4 xv = *(const float4*)&xs[entry][h];
            float4 a0 = *(const float4*)&as[rg][h];
            float4 a1 = *(const float4*)&as[rg + 16][h];
            acc0 += xv.x * a0.x + xv.y * a0.y + xv.z * a0.z + xv.w * a0.w;
            acc1 += xv.x * a1.x + xv.y * a1.y + xv.z * a1.z + xv.w * a1.w;
        }
        __syncthreads();
    }
    if (entry < nent) {
        g_a2[(size_t)myid * Rn + rg] = acc0;
        g_a2[(size_t)myid * Rn + rg + 16] = acc1;
    }
}

// -------- grouped final (CH=32) --------------------------------------------
#define CHL 32
__global__ __launch_bounds__(256) void final_grouped(const float* __restrict__ B2)
{
    int e, start, nent;
    if (!find_chunk(blockIdx.x, CHL, e, start, nent)) return;
    __shared__ float a2s[CHL][Rn];
    __shared__ float ws[CHL];
    __shared__ int ids[CHL];
    int tid = threadIdx.x;
    if (tid < CHL) {
        int id = (tid < nent) ? g_list[start + tid] : g_list[start];
        ids[tid] = id;
        ws[tid] = g_rw[id];
    }
    __syncthreads();
#pragma unroll
    for (int i = 0; i < 4; i++) {
        int q = tid + i * 256;
        int en = q >> 5, r = q & 31;
        a2s[en][r] = g_a2[(size_t)ids[en] * Rn + r];
    }
    __syncthreads();

    for (int h0 = 0; h0 < Hn; h0 += 256) {
        int h = h0 + tid;
        float b2r[Rn];
        const float4* p2 = (const float4*)(B2 + ((size_t)e * Hn + h) * Rn);
#pragma unroll
        for (int q = 0; q < 8; q++) {
            float4 v = p2[q];
            b2r[q * 4 + 0] = v.x; b2r[q * 4 + 1] = v.y;
            b2r[q * 4 + 2] = v.z; b2r[q * 4 + 3] = v.w;
        }
        for (int en = 0; en < nent; en++) {
            int id = ids[en];
            int t = id >> 1, kk = id & 1;
            float l2 = 0.f;
#pragma unroll
            for (int r = 0; r < Rn; r++) l2 += b2r[r] * a2s[en][r];
            (kk ? g_l2k1 : g_l2k0)[(size_t)t * Hn + h] = ws[en] * l2;
        }
    }
}

// -------- add lora2 contributions into out ---------------------------------
__global__ __launch_bounds__(256) void add_out(float* __restrict__ out)
{
    int i = (blockIdx.x * 256 + threadIdx.x) * 4;
    float4 o = *(float4*)(out + i);
    float4 a = *(const float4*)(g_l2k0 + i);
    float4 b = *(const float4*)(g_l2k1 + i);
    o.x += a.x + b.x; o.y += a.y + b.y;
    o.z += a.z + b.z; o.w += a.w + b.w;
    *(float4*)(out + i) = o;
}

// ---------------------------------------------------------------------------
extern "C" void kernel_launch(void* const* d_in, const int* in_sizes, int n_in,
                              void* d_out, int out_size)
{
    (void)in_sizes; (void)n_in; (void)out_size;
    const float* x  = (const float*)d_in[0];
    const float* Wg = (const float*)d_in[1];
    const float* W1 = (const float*)d_in[2];
    const float* W2 = (const float*)d_in[3];
    const float* W3 = (const float*)d_in[4];
    const float* A1 = (const float*)d_in[5];
    const float* B1 = (const float*)d_in[6];
    const float* A2 = (const float*)d_in[7];
    const float* B2 = (const float*)d_in[8];
    const float* A3 = (const float*)d_in[9];
    const float* B3 = (const float*)d_in[10];
    float* out = (float*)d_out;

    __half *xs, *w13s, *w2s, *x2s, *base13, *b1h, *b3h;
    cudaGetSymbolAddress((void**)&base13, g_base13);
    cudaGetSymbolAddress((void**)&xs,   g_xs);
    cudaGetSymbolAddress((void**)&w13s, g_w13s);
    cudaGetSymbolAddress((void**)&w2s,  g_w2s);
    cudaGetSymbolAddress((void**)&x2s,  g_x2s);
    cudaGetSymbolAddress((void**)&b1h,  g_b1h);
    cudaGetSymbolAddress((void**)&b3h,  g_b3h);

    cudaFuncSetAttribute(gemm_f16, cudaFuncAttributeMaxDynamicSharedMemorySize,
                         SMEM_TOTAL);

    static cudaStream_t s1 = nullptr, s2 = nullptr;
    static cudaEvent_t evA = nullptr, ev1 = nullptr, ev2 = nullptr,
                       ev3 = nullptr, ev4 = nullptr, ev5 = nullptr;
    if (s1 == nullptr) {
        cudaStreamCreateWithFlags(&s1, cudaStreamNonBlocking);
        cudaStreamCreateWithFlags(&s2, cudaStreamNonBlocking);
        cudaEventCreateWithFlags(&evA, cudaEventDisableTiming);
        cudaEventCreateWithFlags(&ev1, cudaEventDisableTiming);
        cudaEventCreateWithFlags(&ev2, cudaEventDisableTiming);
        cudaEventCreateWithFlags(&ev3, cudaEventDisableTiming);
        cudaEventCreateWithFlags(&ev4, cudaEventDisableTiming);
        cudaEventCreateWithFlags(&ev5, cudaEventDisableTiming);
    }

    // root fork
    cudaEventRecord(evA, 0);
    cudaStreamWaitEvent(s1, evA, 0);
    cudaStreamWaitEvent(s2, evA, 0);

    // s1: gate chain (tiny; only needed before fuse)
    gate_kernel<<<Tn, 256, 0, s1>>>(x, Wg);
    hist_kernel<<<1, 256, 0, s1>>>();
    scatter_kernel<<<(Tn * Kn + 255) / 256, 256, 0, s1>>>();
    cudaEventRecord(ev1, s1);

    // s2: W2 convert + B1/B3 fp16 converts
    convert_kernel<<<1024, 256, 0, s2>>>(W2, w2s, (size_t)Hn * Fn);
    cudaEventRecord(ev4, s2);
    convert_kernel<<<64, 256, 0, s2>>>(B1, b1h, (size_t)En * Fn * Rn);
    convert_kernel<<<64, 256, 0, s2>>>(B3, b3h, (size_t)En * Fn * Rn);
    cudaEventRecord(ev5, s2);

    // main: converts + extended base GEMM (N = NEXT, fp16 output)
    convert_kernel<<<512, 256>>>(x, xs, (size_t)Tn * Hn);
    convert_kernel<<<1024, 256>>>(W1, w13s, (size_t)Fn * Hn);
    convert_kernel<<<1024, 256>>>(W3, w13s + (size_t)Fn * Hn, (size_t)Fn * Hn);
    convert_kernel<<<64, 256>>>(A1, w13s + (size_t)2 * Fn * Hn,
                                (size_t)En * Rn * Hn);
    convert_kernel<<<64, 256>>>(A3, w13s + ((size_t)2 * Fn + En * Rn) * Hn,
                                (size_t)En * Rn * Hn);
    gemm_f16<<<dim3(NEXT / GBN, Tn / GBM), 512, SMEM_TOTAL>>>(
        xs, w13s, base13, NEXT, Hn, 1);

    // join gate chain + fp16 B converts before fuse
    cudaStreamWaitEvent(0, ev1, 0);
    cudaStreamWaitEvent(0, ev5, 0);
    fuse_grouped<<<Tn * Kn / CHF + En, 256>>>(b1h, b3h);

    // fork: a2 + final on s2 concurrent with combine + down GEMM
    cudaEventRecord(ev2, 0);
    cudaStreamWaitEvent(s2, ev2, 0);
    a2_grouped<<<Tn * Kn / CH2 + En, 256, 0, s2>>>(A2);
    final_grouped<<<Tn * Kn / CHL + En, 256, 0, s2>>>(B2);
    cudaEventRecord(ev3, s2);

    combine_x2<<<Tn, 256>>>();
    cudaStreamWaitEvent(0, ev4, 0);    // W2 fp16 ready
    gemm_f16<<<dim3(Hn / GBN, Tn / GBM), 512, SMEM_TOTAL>>>(
        x2s, w2s, out, Hn, Fn, 0);

    // join lora2 path, then final add
    cudaStreamWaitEvent(0, ev3, 0);
    add_out<<<Tn * Hn / 1024, 256>>>(out);
}

// round 17
// speedup vs baseline: 2.4923x; 1.0526x over previous
#include <cuda_runtime.h>
#include <cuda_fp16.h>
#include <math.h>
#include <stdint.h>

// Problem dims
#define Tn 2048
#define Hn 2048
#define Fn 7168
#define En 8
#define Rn 32
#define Kn 2

// Column split for gemm1a/gemm1b (wave-aligned: 37 tiles = 592 CTAs = 4 waves)
#define FLO 4480                       // W1/W3 low split point
#define FHI (Fn - FLO)                 // 2688
// w13s layout: [W1lo | W3lo | A1 | A3 | W1hi | W3hi]
#define C_W1LO 0
#define C_W3LO FLO
#define C_A1   (2 * FLO)               // 8960
#define C_A3   (2 * FLO + En * Rn)     // 9216
#define C_W1HI (2 * FLO + 2 * En * Rn) // 9472
#define C_W3HI (C_W1HI + FHI)          // 12160
#define NEXT   (C_W1HI + 2 * FHI)      // 14848 = 58*256
#define TILES_A 37
#define TILES_B 21

// HMMA GEMM tiling: 128x256, 512 threads, 4 stages
#define GBM 128
#define GBN 256
#define KBE 64
#define STAGES 4
#define A_TILE_B (GBM * 128)
#define B_TILE_B (GBN * 128)
#define STAGE_B  (A_TILE_B + B_TILE_B)
#define SMEM_TOTAL (STAGES * STAGE_B)

#define SWZ(o) ((o) ^ (((o) >> 3) & 0x70))

// ---------------- scratch ---------------------------------------------------
__device__ __align__(256) __half g_base13[Tn * NEXT];
__device__ __align__(256) __half g_x2k0[Tn * Fn];
__device__ __align__(256) __half g_x2k1[Tn * Fn];
__device__ __align__(256) float g_l2k0[Tn * Hn];
__device__ __align__(256) float g_l2k1[Tn * Hn];
__device__ __align__(256) __half g_xs  [Tn * Hn];
__device__ __align__(256) __half g_w13s[NEXT * Hn];
__device__ __align__(256) __half g_w2s [Hn * Fn];
__device__ __align__(256) __half g_x2s [Tn * Fn];
__device__ __align__(256) __half g_b1h [En * Fn * Rn];
__device__ __align__(256) __half g_b3h [En * Fn * Rn];
__device__ int   g_sel[Tn * Kn];
__device__ float g_rw [Tn * Kn];
__device__ float g_a2 [Tn * Kn * Rn];
__device__ int g_off [En + 1];
__device__ int g_cur [En];
__device__ int g_list[Tn * Kn];

// ---------------- helpers ---------------------------------------------------
__device__ __forceinline__ uint32_t smem_u32(const void* p) {
    uint32_t a;
    asm("{ .reg .u64 t; cvta.to.shared.u64 t, %1; cvt.u32.u64 %0, t; }"
        : "=r"(a) : "l"(p));
    return a;
}

__device__ __forceinline__ float warp_sum(float v) {
#pragma unroll
    for (int o = 16; o; o >>= 1) v += __shfl_xor_sync(0xffffffffu, v, o);
    return v;
}

__device__ __forceinline__ bool find_chunk(int b, int CH, int& e, int& start,
                                           int& nent) {
    int acc = 0;
    for (int ee = 0; ee < En; ee++) {
        int o0 = g_off[ee], o1 = g_off[ee + 1];
        int cnt = o1 - o0;
        int nch = (cnt + CH - 1) / CH;
        if (b < acc + nch) {
            e = ee;
            start = o0 + (b - acc) * CH;
            nent = min(CH, o1 - start);
            return true;
        }
        acc += nch;
    }
    return false;
}

#define LDSM4(r0, r1, r2, r3, addr) \
    asm volatile("ldmatrix.sync.aligned.m8n8.x4.shared.b16 {%0,%1,%2,%3}, [%4];" \
                 : "=r"(r0), "=r"(r1), "=r"(r2), "=r"(r3) : "r"(addr))

#define MMA16816(c, a, b0, b1) \
    asm volatile("mma.sync.aligned.m16n8k16.row.col.f32.f16.f16.f32 " \
                 "{%0,%1,%2,%3}, {%4,%5,%6,%7}, {%8,%9}, {%0,%1,%2,%3};" \
                 : "+f"((c)[0]), "+f"((c)[1]), "+f"((c)[2]), "+f"((c)[3]) \
                 : "r"((a)[0]), "r"((a)[1]), "r"((a)[2]), "r"((a)[3]), \
                   "r"(b0), "r"(b1))

// ---------------- fp32 -> fp16 convert -------------------------------------
__global__ __launch_bounds__(256) void convert_kernel(
    const float* __restrict__ src, __half* __restrict__ dst, size_t n)
{
    for (size_t i = ((size_t)blockIdx.x * 256 + threadIdx.x) * 8; i < n;
         i += (size_t)gridDim.x * 256 * 8) {
        float4 v0 = *(const float4*)(src + i);
        float4 v1 = *(const float4*)(src + i + 4);
        *(__half2*)(dst + i)     = __halves2half2(__float2half_rn(v0.x), __float2half_rn(v0.y));
        *(__half2*)(dst + i + 2) = __halves2half2(__float2half_rn(v0.z), __float2half_rn(v0.w));
        *(__half2*)(dst + i + 4) = __halves2half2(__float2half_rn(v1.x), __float2half_rn(v1.y));
        *(__half2*)(dst + i + 6) = __halves2half2(__float2half_rn(v1.z), __float2half_rn(v1.w));
    }
}

// ---------------- GEMM stage loader ----------------------------------------
__device__ __forceinline__ void load_stage(
    uint32_t sb, const __half* Ab, const __half* Bb,
    int Kp, int it, int stage, int tid)
{
    uint32_t st = sb + stage * STAGE_B;
    int k0 = it * KBE;
#pragma unroll
    for (int i = 0; i < 6; i++) {
        int c = tid + i * 512;
        uint32_t soff;
        const __half* g;
        if (c < 1024) {
            int row = c >> 3, j = c & 7;
            soff = st + SWZ(row * 128 + j * 16);
            g = Ab + (size_t)row * Kp + k0 + j * 8;
        } else {
            int cc = c - 1024;
            int row = cc >> 3, j = cc & 7;
            soff = st + A_TILE_B + SWZ(row * 128 + j * 16);
            g = Bb + (size_t)row * Kp + k0 + j * 8;
        }
        asm volatile("cp.async.cg.shared.global [%0], [%1], 16;"
                     :: "r"(soff), "l"(g) : "memory");
    }
}

// ---------------- HMMA fp16 GEMM (bxoff for split launches) ----------------
__global__ __launch_bounds__(512, 1) void gemm_f16(
    const __half* __restrict__ A, const __half* __restrict__ B,
    void* __restrict__ C, int N, int Kp, int half_out, int bxoff)
{
    extern __shared__ __align__(1024) char smem[];
    uint32_t sb = smem_u32(smem);
    int tid = threadIdx.x, wid = tid >> 5, lane = tid & 31;
    int wm = wid & 3, wn = wid >> 2;
    int bx = blockIdx.x + bxoff, by = blockIdx.y;
    const int niter = Kp / KBE;

    const __half* Ab = A + (size_t)(by * GBM) * Kp;
    const __half* Bb = B + (size_t)(bx * GBN) * Kp;

#pragma unroll
    for (int it = 0; it < STAGES - 1; it++) {
        load_stage(sb, Ab, Bb, Kp, it, it, tid);
        asm volatile("cp.async.commit_group;" ::: "memory");
    }

    float acc[2][8][4];
#pragma unroll
    for (int mi = 0; mi < 2; mi++)
#pragma unroll
        for (int nj = 0; nj < 8; nj++)
#pragma unroll
            for (int q = 0; q < 4; q++) acc[mi][nj][q] = 0.f;

    int gq = lane >> 3, rr = lane & 7;
    int kc = gq >> 1;
    uint32_t aRow[2]; int aXor[2];
#pragma unroll
    for (int mi = 0; mi < 2; mi++) {
        int m = wm * 32 + mi * 16 + (gq & 1) * 8 + rr;
        aRow[mi] = (uint32_t)(m * 128);
        aXor[mi] = m & 7;
    }
    uint32_t bRow[4]; int bXor[4];
#pragma unroll
    for (int ni = 0; ni < 4; ni++) {
        int n = wn * 64 + ni * 16 + (gq & 1) * 8 + rr;
        bRow[ni] = (uint32_t)(A_TILE_B + n * 128);
        bXor[ni] = n & 7;
    }

    int s = 0;
    for (int it = 0; it < niter; it++) {
        asm volatile("cp.async.wait_group %0;" :: "n"(STAGES - 2) : "memory");
        __syncthreads();
        int jt = it + STAGES - 1;
        if (jt < niter) {
            int sj = jt - (jt / STAGES) * STAGES;
            load_stage(sb, Ab, Bb, Kp, jt, sj, tid);
        }
        asm volatile("cp.async.commit_group;" ::: "memory");

        uint32_t stb = sb + s * STAGE_B;
        s++; if (s == STAGES) s = 0;
#pragma unroll
        for (int ks = 0; ks < 4; ks++) {
            uint32_t a[2][4];
#pragma unroll
            for (int mi = 0; mi < 2; mi++) {
                uint32_t ad = stb + aRow[mi]
                            + (uint32_t)((((ks << 1) + kc) ^ aXor[mi]) << 4);
                LDSM4(a[mi][0], a[mi][1], a[mi][2], a[mi][3], ad);
            }
            uint32_t b[4][4];
#pragma unroll
            for (int ni = 0; ni < 4; ni++) {
                uint32_t bd = stb + bRow[ni]
                            + (uint32_t)((((ks << 1) + kc) ^ bXor[ni]) << 4);
                LDSM4(b[ni][0], b[ni][1], b[ni][2], b[ni][3], bd);
            }
#pragma unroll
            for (int mi = 0; mi < 2; mi++)
#pragma unroll
                for (int ni = 0; ni < 4; ni++) {
                    MMA16816(acc[mi][ni * 2],     a[mi], b[ni][0], b[ni][2]);
                    MMA16816(acc[mi][ni * 2 + 1], a[mi], b[ni][1], b[ni][3]);
                }
        }
    }

    int gid = lane >> 2, tig = lane & 3;
    if (half_out) {
        __half* Ch = (__half*)C;
#pragma unroll
        for (int mi = 0; mi < 2; mi++) {
            int row = by * GBM + wm * 32 + mi * 16 + gid;
#pragma unroll
            for (int nj = 0; nj < 8; nj++) {
                __half* p = Ch + (size_t)row * N + bx * GBN + wn * 64 + nj * 8 + tig * 2;
                *(__half2*)p = __halves2half2(__float2half_rn(acc[mi][nj][0]),
                                              __float2half_rn(acc[mi][nj][1]));
                *(__half2*)(p + (size_t)8 * N) =
                    __halves2half2(__float2half_rn(acc[mi][nj][2]),
                                   __float2half_rn(acc[mi][nj][3]));
            }
        }
    } else {
        float* Cf = (float*)C;
#pragma unroll
        for (int mi = 0; mi < 2; mi++) {
            int row = by * GBM + wm * 32 + mi * 16 + gid;
#pragma unroll
            for (int nj = 0; nj < 8; nj++) {
                float* p = Cf + (size_t)row * N + bx * GBN + wn * 64 + nj * 8 + tig * 2;
                *(float2*)p = make_float2(acc[mi][nj][0], acc[mi][nj][1]);
                *(float2*)(p + (size_t)8 * N) = make_float2(acc[mi][nj][2], acc[mi][nj][3]);
            }
        }
    }
}

// ---------------- gate ------------------------------------------------------
__global__ __launch_bounds__(256) void gate_kernel(
    const float* __restrict__ x, const float* __restrict__ Wg)
{
    int t = blockIdx.x;
    int tid = threadIdx.x;
    int w = tid >> 5, lane = tid & 31;
    const float* xr = x + (size_t)t * Hn;
    const float* wr = Wg + (size_t)w * Hn;
    float s = 0.f;
    for (int h = lane * 4; h < Hn; h += 32 * 4) {
        float4 xv = *(const float4*)(xr + h);
        float4 wv = *(const float4*)(wr + h);
        s += xv.x * wv.x + xv.y * wv.y + xv.z * wv.z + xv.w * wv.w;
    }
    s = warp_sum(s);
    __shared__ float logits[En];
    if (lane == 0) logits[w] = s;
    __syncthreads();
    if (tid == 0) {
        int i0 = 0; float l0 = logits[0];
#pragma unroll
        for (int e = 1; e < En; e++) if (logits[e] > l0) { l0 = logits[e]; i0 = e; }
        int i1 = -1; float l1 = -3.0e38f;
#pragma unroll
        for (int e = 0; e < En; e++) if (e != i0 && logits[e] > l1) { l1 = logits[e]; i1 = e; }
        float r0 = 1.f / (1.f + expf(l1 - l0));
        g_sel[t * 2 + 0] = i0;
        g_sel[t * 2 + 1] = i1;
        g_rw [t * 2 + 0] = r0;
        g_rw [t * 2 + 1] = 1.f - r0;
    }
}

// ---------------- expert grouping ------------------------------------------
__global__ __launch_bounds__(256) void hist_kernel()
{
    __shared__ int hc[En];
    int tid = threadIdx.x;
    if (tid < En) hc[tid] = 0;
    __syncthreads();
    for (int i = tid; i < Tn * Kn; i += 256)
        atomicAdd(&hc[g_sel[i]], 1);
    __syncthreads();
    if (tid == 0) {
        int off = 0;
        for (int e = 0; e < En; e++) {
            g_off[e] = off;
            g_cur[e] = off;
            off += hc[e];
        }
        g_off[En] = off;
    }
}

__global__ __launch_bounds__(256) void scatter_kernel()
{
    int i = blockIdx.x * 256 + threadIdx.x;
    if (i < Tn * Kn) {
        int e = g_sel[i];
        int pos = atomicAdd(&g_cur[e], 1);
        g_list[pos] = i;
    }
}

// -------- grouped fuse (CH=8): f-range [fbeg,fend), col offsets ------------
#define CHF 8
#define PAD 132
__global__ __launch_bounds__(256) void fuse_grouped(
    const __half* __restrict__ B1h, const __half* __restrict__ B3h,
    int fbeg, int fend, int c1off, int c3off)
{
    int e, start, nent;
    if (!find_chunk(blockIdx.x, CHF, e, start, nent)) return;
    __shared__ __half2 a1h[CHF][Rn / 2];
    __shared__ __half2 a3h[CHF][Rn / 2];
    __shared__ int ids[CHF];
    int tid = threadIdx.x;
    if (tid < CHF)
        ids[tid] = (tid < nent) ? g_list[start + tid] : g_list[start];
    __syncthreads();
    if (tid < CHF * (Rn / 2)) {
        int en = tid >> 4, i = tid & 15;
        const __half* b13 = g_base13 + (size_t)(ids[en] >> 1) * NEXT;
        a1h[en][i] = *(const __half2*)(b13 + C_A1 + e * Rn + 2 * i);
        a3h[en][i] = *(const __half2*)(b13 + C_A3 + e * Rn + 2 * i);
    }
    __syncthreads();

    for (int f0 = fbeg; f0 < fend; f0 += 256) {
        int f = f0 + tid;
        if (f >= fend) continue;
        __align__(16) __half2 b1r[16];
        __align__(16) __half2 b3r[16];
        const float4* p1 = (const float4*)(B1h + ((size_t)e * Fn + f) * Rn);
        const float4* p3 = (const float4*)(B3h + ((size_t)e * Fn + f) * Rn);
#pragma unroll
        for (int q = 0; q < 4; q++) {
            *((float4*)b1r + q) = p1[q];
            *((float4*)b3r + q) = p3[q];
        }
        for (int en = 0; en < nent; en++) {
            int id = ids[en];
            int t = id >> 1, kk = id & 1;
            __half2 s1[4], s3[4];
#pragma unroll
            for (int q = 0; q < 4; q++) {
                s1[q] = __float2half2_rn(0.f);
                s3[q] = __float2half2_rn(0.f);
            }
#pragma unroll
            for (int j = 0; j < 16; j += 4) {
#pragma unroll
                for (int q = 0; q < 4; q++) {
                    s1[q] = __hfma2(b1r[j + q], a1h[en][j + q], s1[q]);
                    s3[q] = __hfma2(b3r[j + q], a3h[en][j + q], s3[q]);
                }
            }
            float l1 = 0.f, l3 = 0.f;
#pragma unroll
            for (int q = 0; q < 4; q++) {
                float2 u1 = __half22float2(s1[q]);
                float2 u3 = __half22float2(s3[q]);
                l1 += u1.x + u1.y;
                l3 += u3.x + u3.y;
            }
            const __half* b13 = g_base13 + (size_t)t * NEXT;
            float x1 = __half2float(b13[f + c1off]) + l1;
            float x3 = __half2float(b13[f + c3off]) + l3;
            float sig = 1.f / (1.f + expf(-x1));
            float x2 = x1 * sig * x3;
            (kk ? g_x2k1 : g_x2k0)[(size_t)t * Fn + f] = __float2half_rn(x2);
        }
    }
}

// -------- combine weighted x2 -> fp16 --------------------------------------
__global__ __launch_bounds__(256) void combine_x2()
{
    int t = blockIdx.x;
    float w0 = g_rw[t * 2], w1 = g_rw[t * 2 + 1];
    __half* d = g_x2s + (size_t)t * Fn;
    const __half* s0 = g_x2k0 + (size_t)t * Fn;
    const __half* s1 = g_x2k1 + (size_t)t * Fn;
    for (int f = threadIdx.x * 2; f < Fn; f += 256 * 2) {
        float2 v0 = __half22float2(*(const __half2*)(s0 + f));
        float2 v1 = __half22float2(*(const __half2*)(s1 + f));
        *(__half2*)(d + f) = __halves2half2(
            __float2half_rn(w0 * v0.x + w1 * v1.x),
            __float2half_rn(w0 * v0.y + w1 * v1.y));
    }
}

// -------- grouped a2 (CH=16) -----------------------------------------------
#define CH2 16
__global__ __launch_bounds__(256) void a2_grouped(const float* __restrict__ A2)
{
    int e, start, nent;
    if (!find_chunk(blockIdx.x, CH2, e, start, nent)) return;
    __shared__ float xs[CH2][PAD];
    __shared__ float as[Rn][PAD];
    __shared__ int ids[CH2];
    int tid = threadIdx.x;
    if (tid < CH2)
        ids[tid] = (tid < nent) ? g_list[start + tid] : g_list[start];
    __syncthreads();

    int entry = tid >> 4, rg = tid & 15;
    float acc0 = 0.f, acc1 = 0.f;
    int myid = ids[entry];

    for (int f0 = 0; f0 < Fn; f0 += 128) {
#pragma unroll
        for (int i = 0; i < 4; i++) {
            int q = tid + i * 256;
            int row = q >> 6, c2 = q & 63;
            int id = ids[row];
            const __half* src = (id & 1) ? g_x2k1 : g_x2k0;
            float2 fv = __half22float2(
                *(const __half2*)(src + (size_t)(id >> 1) * Fn + f0 + 2 * c2));
            xs[row][2 * c2]     = fv.x;
            xs[row][2 * c2 + 1] = fv.y;
        }
#pragma unroll
        for (int i = 0; i < 16; i++) {
            int q = tid + i * 256;
            int row = q >> 7, col = q & 127;
            as[row][col] = A2[(size_t)(e * Rn + row) * Fn + f0 + col];
        }
        __syncthreads();
#pragma unroll
        for (int h = 0; h < 128; h += 4) {
            float4 xv = *(const float4*)&xs[entry][h];
            float4 a0 = *(const float4*)&as[rg][h];
            float4 a1 = *(const float4*)&as[rg + 16][h];
            acc0 += xv.x * a0.x + xv.y * a0.y + xv.z * a0.z + xv.w * a0.w;
            acc1 += xv.x * a1.x + xv.y * a1.y + xv.z * a1.z + xv.w * a1.w;
        }
        __syncthreads();
    }
    if (entry < nent) {
        g_a2[(size_t)myid * Rn + rg] = acc0;
        g_a2[(size_t)myid * Rn + rg + 16] = acc1;
    }
}

// -------- grouped final (CH=32) --------------------------------------------
#define CHL 32
__global__ __launch_bounds__(256) void final_grouped(const float* __restrict__ B2)
{
    int e, start, nent;
    if (!find_chunk(blockIdx.x, CHL, e, start, nent)) return;
    __shared__ float a2s[CHL][Rn];
    __shared__ float ws[CHL];
    __shared__ int ids[CHL];
    int tid = threadIdx.x;
    if (tid < CHL) {
        int id = (tid < nent) ? g_list[start + tid] : g_list[start];
        ids[tid] = id;
        ws[tid] = g_rw[id];
    }
    __syncthreads();
#pragma unroll
    for (int i = 0; i < 4; i++) {
        int q = tid + i * 256;
        int en = q >> 5, r = q & 31;
        a2s[en][r] = g_a2[(size_t)ids[en] * Rn + r];
    }
    __syncthreads();

    for (int h0 = 0; h0 < Hn; h0 += 256) {
        int h = h0 + tid;
        float b2r[Rn];
        const float4* p2 = (const float4*)(B2 + ((size_t)e * Hn + h) * Rn);
#pragma unroll
        for (int q = 0; q < 8; q++) {
            float4 v = p2[q];
            b2r[q * 4 + 0] = v.x; b2r[q * 4 + 1] = v.y;
            b2r[q * 4 + 2] = v.z; b2r[q * 4 + 3] = v.w;
        }
        for (int en = 0; en < nent; en++) {
            int id = ids[en];
            int t = id >> 1, kk = id & 1;
            float l2 = 0.f;
#pragma unroll
            for (int r = 0; r < Rn; r++) l2 += b2r[r] * a2s[en][r];
            (kk ? g_l2k1 : g_l2k0)[(size_t)t * Hn + h] = ws[en] * l2;
        }
    }
}

// -------- add lora2 into out ------------------------------------------------
__global__ __launch_bounds__(256) void add_out(float* __restrict__ out)
{
    int i = (blockIdx.x * 256 + threadIdx.x) * 4;
    float4 o = *(float4*)(out + i);
    float4 a = *(const float4*)(g_l2k0 + i);
    float4 b = *(const float4*)(g_l2k1 + i);
    o.x += a.x + b.x; o.y += a.y + b.y;
    o.z += a.z + b.z; o.w += a.w + b.w;
    *(float4*)(out + i) = o;
}

// ---------------------------------------------------------------------------
extern "C" void kernel_launch(void* const* d_in, const int* in_sizes, int n_in,
                              void* d_out, int out_size)
{
    (void)in_sizes; (void)n_in; (void)out_size;
    const float* x  = (const float*)d_in[0];
    const float* Wg = (const float*)d_in[1];
    const float* W1 = (const float*)d_in[2];
    const float* W2 = (const float*)d_in[3];
    const float* W3 = (const float*)d_in[4];
    const float* A1 = (const float*)d_in[5];
    const float* B1 = (const float*)d_in[6];
    const float* A2 = (const float*)d_in[7];
    const float* B2 = (const float*)d_in[8];
    const float* A3 = (const float*)d_in[9];
    const float* B3 = (const float*)d_in[10];
    float* out = (float*)d_out;

    __half *xs, *w13s, *w2s, *x2s, *base13, *b1h, *b3h;
    cudaGetSymbolAddress((void**)&base13, g_base13);
    cudaGetSymbolAddress((void**)&xs,   g_xs);
    cudaGetSymbolAddress((void**)&w13s, g_w13s);
    cudaGetSymbolAddress((void**)&w2s,  g_w2s);
    cudaGetSymbolAddress((void**)&x2s,  g_x2s);
    cudaGetSymbolAddress((void**)&b1h,  g_b1h);
    cudaGetSymbolAddress((void**)&b3h,  g_b3h);

    cudaFuncSetAttribute(gemm_f16, cudaFuncAttributeMaxDynamicSharedMemorySize,
                         SMEM_TOTAL);

    static cudaStream_t s1 = nullptr, s2 = nullptr;
    static cudaEvent_t evA = nullptr, evGate = nullptr, ev2 = nullptr,
                       ev3 = nullptr, ev4 = nullptr, ev5 = nullptr,
                       evGa = nullptr, evGb = nullptr, evFH = nullptr;
    if (s1 == nullptr) {
        cudaStreamCreateWithFlags(&s1, cudaStreamNonBlocking);
        cudaStreamCreateWithFlags(&s2, cudaStreamNonBlocking);
        cudaEventCreateWithFlags(&evA, cudaEventDisableTiming);
        cudaEventCreateWithFlags(&evGate, cudaEventDisableTiming);
        cudaEventCreateWithFlags(&ev2, cudaEventDisableTiming);
        cudaEventCreateWithFlags(&ev3, cudaEventDisableTiming);
        cudaEventCreateWithFlags(&ev4, cudaEventDisableTiming);
        cudaEventCreateWithFlags(&ev5, cudaEventDisableTiming);
        cudaEventCreateWithFlags(&evGa, cudaEventDisableTiming);
        cudaEventCreateWithFlags(&evGb, cudaEventDisableTiming);
        cudaEventCreateWithFlags(&evFH, cudaEventDisableTiming);
    }

    // root fork
    cudaEventRecord(evA, 0);
    cudaStreamWaitEvent(s1, evA, 0);
    cudaStreamWaitEvent(s2, evA, 0);

    // s1: gate chain
    gate_kernel<<<Tn, 256, 0, s1>>>(x, Wg);
    hist_kernel<<<1, 256, 0, s1>>>();
    scatter_kernel<<<(Tn * Kn + 255) / 256, 256, 0, s1>>>();

    // s2: W2 + B1/B3 fp16 converts
    convert_kernel<<<1024, 256, 0, s2>>>(W2, w2s, (size_t)Hn * Fn);
    cudaEventRecord(ev4, s2);
    convert_kernel<<<64, 256, 0, s2>>>(B1, b1h, (size_t)En * Fn * Rn);
    convert_kernel<<<64, 256, 0, s2>>>(B3, b3h, (size_t)En * Fn * Rn);
    cudaEventRecord(ev5, s2);
    cudaStreamWaitEvent(s1, ev5, 0);   // fuse needs B converts

    // main: converts into split layout
    convert_kernel<<<512, 256>>>(x, xs, (size_t)Tn * Hn);
    convert_kernel<<<1024, 256>>>(W1, w13s + (size_t)C_W1LO * Hn, (size_t)FLO * Hn);
    convert_kernel<<<1024, 256>>>(W3, w13s + (size_t)C_W3LO * Hn, (size_t)FLO * Hn);
    convert_kernel<<<64, 256>>>(A1, w13s + (size_t)C_A1 * Hn, (size_t)En * Rn * Hn);
    convert_kernel<<<64, 256>>>(A3, w13s + (size_t)C_A3 * Hn, (size_t)En * Rn * Hn);
    convert_kernel<<<1024, 256>>>(W1 + (size_t)FLO * Hn,
                                  w13s + (size_t)C_W1HI * Hn, (size_t)FHI * Hn);
    convert_kernel<<<1024, 256>>>(W3 + (size_t)FLO * Hn,
                                  w13s + (size_t)C_W3HI * Hn, (size_t)FHI * Hn);

    // gemm1a: first 37 N-tiles (W1lo, W3lo, A1, A3) = 592 CTAs = 4 waves
    gemm_f16<<<dim3(TILES_A, Tn / GBM), 512, SMEM_TOTAL>>>(
        xs, w13s, base13, NEXT, Hn, 1, 0);
    cudaEventRecord(evGa, 0);
    // gemm1b: remaining 21 tiles (W1hi, W3hi)
    gemm_f16<<<dim3(TILES_B, Tn / GBM), 512, SMEM_TOTAL>>>(
        xs, w13s, base13, NEXT, Hn, 1, TILES_A);
    cudaEventRecord(evGb, 0);

    // s1: fuse_lo concurrent with gemm1b; fuse_hi after gemm1b
    cudaStreamWaitEvent(s1, evGa, 0);
    fuse_grouped<<<Tn * Kn / CHF + En, 256, 0, s1>>>(
        b1h, b3h, 0, FLO, C_W1LO, C_W3LO);
    cudaStreamWaitEvent(s1, evGb, 0);
    fuse_grouped<<<Tn * Kn / CHF + En, 256, 0, s1>>>(
        b1h, b3h, FLO, Fn, C_W1HI - FLO, C_W3HI - FLO);
    cudaEventRecord(evFH, s1);

    // main joins fuse, then combine + down GEMM
    cudaStreamWaitEvent(0, evFH, 0);

    // fork: a2 + final on s2
    cudaEventRecord(ev2, 0);
    cudaStreamWaitEvent(s2, ev2, 0);
    a2_grouped<<<Tn * Kn / CH2 + En, 256, 0, s2>>>(A2);
    final_grouped<<<Tn * Kn / CHL + En, 256, 0, s2>>>(B2);
    cudaEventRecord(ev3, s2);

    combine_x2<<<Tn, 256>>>();
    cudaStreamWaitEvent(0, ev4, 0);
    gemm_f16<<<dim3(Hn / GBN, Tn / GBM), 512, SMEM_TOTAL>>>(
        x2s, w2s, out, Hn, Fn, 0, 0);

    cudaStreamWaitEvent(0, ev3, 0);
    add_out<<<Tn * Hn / 1024, 256>>>(out);
}